// round 11
// baseline (speedup 1.0000x reference)
#include <cuda_runtime.h>
#include <math.h>

// ---------------- constants ----------------
#define NBATCH 4
#define TTOP   65536
#define OFF_XHAT 0
#define OFF_LOSS 262144
#define OFF_IDS  262145
#define OFF_SIM  294913
#define NEMB 512

#define ALIGN4(n) (((n) + 3) & ~3)

// ---------------- scratch ----------------
__device__ float g_A[16777216];
__device__ float g_B[16777216];
__device__ float g_ne[NEMB];
__device__ float g_rsne[NEMB];
__device__ float g_loss;

__global__ void zero_loss_kernel() { g_loss = 0.f; }

__global__ void ne_kernel(const float* __restrict__ cb) {
    int e = blockIdx.x * blockDim.x + threadIdx.x;
    if (e < NEMB) {
        float s = 0.f;
        #pragma unroll 8
        for (int ci = 0; ci < 64; ci++) { float v = cb[e * 64 + ci]; s += v * v; }
        g_ne[e] = s;
        g_rsne[e] = rsqrtf(s);
    }
}

__global__ void loss_fin_kernel(float* __restrict__ out) {
    out[OFF_LOSS] = 1.25f * g_loss / 32768.0f;
}

// ---------------- first conv: Cin=1 -> 64, K=4, stride 2, ReLU ----------------
__global__ void __launch_bounds__(256) down0_kernel(
    const float* __restrict__ x, const float* __restrict__ w,
    const float* __restrict__ bias, float* __restrict__ y)
{
    __shared__ float ws[256];
    __shared__ float bs[64];
    int tid = threadIdx.x;
    ws[tid] = w[tid];
    if (tid < 64) bs[tid] = bias[tid];
    __syncthreads();

    int g = blockIdx.x * 256 + tid;
    int q = g & 3;
    int rest = g >> 2;
    int ot = rest & 32767;
    int b = rest >> 15;

    float acc[16];
    #pragma unroll
    for (int c = 0; c < 16; c++) acc[c] = bs[q * 16 + c];
    #pragma unroll
    for (int k = 0; k < 4; k++) {
        int t = 2 * ot - 1 + k;
        float xv = (t >= 0 && t < TTOP) ? x[(size_t)b * TTOP + t] : 0.f;
        #pragma unroll
        for (int c = 0; c < 16; c++) acc[c] += xv * ws[k * 64 + q * 16 + c];
    }
    float* op = y + ((size_t)(b * 32768 + ot)) * 64 + q * 16;
    #pragma unroll
    for (int c4 = 0; c4 < 4; c4++) {
        float4 o;
        o.x = fmaxf(acc[c4 * 4 + 0], 0.f);
        o.y = fmaxf(acc[c4 * 4 + 1], 0.f);
        o.z = fmaxf(acc[c4 * 4 + 2], 0.f);
        o.w = fmaxf(acc[c4 * 4 + 3], 0.f);
        *(float4*)(op + c4 * 4) = o;
    }
}

// ---------------- residual conv, 128-t tile (proven R6 kernel) --------------
// 256 threads, 8t x 4co per thread, x transposed in smem [64][164],
// weights via __ldg, 3 CTAs/SM. Best in-wave efficiency; used at T=32768.
#define XS128 164

template<int DIL, bool RES>
__global__ void __launch_bounds__(256, 3) conv_res128_kernel(
    const float* __restrict__ x, const float* __restrict__ w,
    const float* __restrict__ bias, const float* __restrict__ res,
    float* __restrict__ y, int T)
{
    constexpr int ROWS = 128 + 2 * DIL;
    constexpr int NQ = (ROWS + 3) >> 2;
    constexpr int W = 8 + 2 * DIL;
    constexpr int NV = (W + 3) >> 2;

    extern __shared__ float smem[];
    float* xsT = smem;   // [64][XS128]

    const int tid = threadIdx.x;
    const int tilesPerB = T >> 7;
    const int b = blockIdx.x / tilesPerB;
    const int t0 = (blockIdx.x - b * tilesPerB) << 7;
    const float* xb = x + (size_t)b * T * 64;

    for (int idx = tid; idx < 64 * NQ; idx += 256) {
        int ci = idx & 63;
        int rb = (idx >> 6) << 2;
        int gt = t0 - DIL + rb;
        float4 v;
        v.x = (gt + 0 >= 0 && gt + 0 < T) ? xb[(size_t)(gt + 0) * 64 + ci] : 0.f;
        v.y = (gt + 1 >= 0 && gt + 1 < T) ? xb[(size_t)(gt + 1) * 64 + ci] : 0.f;
        v.z = (gt + 2 >= 0 && gt + 2 < T) ? xb[(size_t)(gt + 2) * 64 + ci] : 0.f;
        v.w = (gt + 3 >= 0 && gt + 3 < T) ? xb[(size_t)(gt + 3) * 64 + ci] : 0.f;
        *(float4*)&xsT[ci * XS128 + rb] = v;
    }
    __syncthreads();

    const int tg = tid >> 4;
    const int cg = tid & 15;
    const int tb = tg << 3;
    const int co0 = cg << 2;

    float acc[8][4];
    #pragma unroll
    for (int i = 0; i < 8; i++)
        #pragma unroll
        for (int j = 0; j < 4; j++) acc[i][j] = 0.f;

    #pragma unroll 2
    for (int ci = 0; ci < 64; ci++) {
        const float4* xr = (const float4*)&xsT[ci * XS128 + tb];
        float xw[NV * 4];
        #pragma unroll
        for (int v = 0; v < NV; v++) {
            float4 c = xr[v];
            xw[v * 4 + 0] = c.x; xw[v * 4 + 1] = c.y;
            xw[v * 4 + 2] = c.z; xw[v * 4 + 3] = c.w;
        }

        #pragma unroll
        for (int k = 0; k < 3; k++) {
            float4 wa = __ldg((const float4*)(w + k * 4096 + ci * 64 + co0));
            #pragma unroll
            for (int i = 0; i < 8; i++) {
                float xv = xw[i + k * DIL];
                acc[i][0] += xv * wa.x; acc[i][1] += xv * wa.y;
                acc[i][2] += xv * wa.z; acc[i][3] += xv * wa.w;
            }
        }
    }

    float4 bv = *(const float4*)(bias + co0);
    #pragma unroll
    for (int i = 0; i < 8; i++) {
        int gt = t0 + tb + i;
        float* op = y + ((size_t)b * T + gt) * 64 + co0;
        float4 o;
        o.x = fmaxf(acc[i][0] + bv.x, 0.f);
        o.y = fmaxf(acc[i][1] + bv.y, 0.f);
        o.z = fmaxf(acc[i][2] + bv.z, 0.f);
        o.w = fmaxf(acc[i][3] + bv.w, 0.f);
        if (RES) {
            float4 r0 = *(const float4*)(res + ((size_t)b * T + gt) * 64 + co0);
            o.x += r0.x; o.y += r0.y; o.z += r0.z; o.w += r0.w;
        }
        *(float4*)op = o;
    }
}

// ---------------- residual conv, 64-t tile (proven R10 kernel) --------------
// 256 threads, 4t x 4co per thread, x transposed in smem [64][76],
// 4 CTAs/SM. Better wave geometry; used at T<=16384.
#define XS64 76

template<int DIL, bool RES>
__global__ void __launch_bounds__(256, 4) conv_res64_kernel(
    const float* __restrict__ x, const float* __restrict__ w,
    const float* __restrict__ bias, const float* __restrict__ res,
    float* __restrict__ y, int T)
{
    constexpr int ROWS = 64 + 2 * DIL;
    constexpr int NQ = (ROWS + 3) >> 2;
    constexpr int W = 4 + 2 * DIL;
    constexpr int NV = (W + 3) >> 2;

    extern __shared__ float smem[];
    float* xsT = smem;   // [64][XS64]

    const int tid = threadIdx.x;
    const int tilesPerB = T >> 6;
    const int b = blockIdx.x / tilesPerB;
    const int t0 = (blockIdx.x - b * tilesPerB) << 6;
    const float* xb = x + (size_t)b * T * 64;

    for (int idx = tid; idx < 64 * NQ; idx += 256) {
        int ci = idx & 63;
        int rb = (idx >> 6) << 2;
        int gt = t0 - DIL + rb;
        float4 v;
        v.x = (gt + 0 >= 0 && gt + 0 < T) ? xb[(size_t)(gt + 0) * 64 + ci] : 0.f;
        v.y = (gt + 1 >= 0 && gt + 1 < T) ? xb[(size_t)(gt + 1) * 64 + ci] : 0.f;
        v.z = (gt + 2 >= 0 && gt + 2 < T) ? xb[(size_t)(gt + 2) * 64 + ci] : 0.f;
        v.w = (gt + 3 >= 0 && gt + 3 < T) ? xb[(size_t)(gt + 3) * 64 + ci] : 0.f;
        *(float4*)&xsT[ci * XS64 + rb] = v;
    }
    __syncthreads();

    const int tg = tid >> 4;
    const int cg = tid & 15;
    const int tb = tg << 2;
    const int co0 = cg << 2;

    float acc[4][4];
    #pragma unroll
    for (int i = 0; i < 4; i++)
        #pragma unroll
        for (int j = 0; j < 4; j++) acc[i][j] = 0.f;

    #pragma unroll 2
    for (int ci = 0; ci < 64; ci++) {
        const float4* xr = (const float4*)&xsT[ci * XS64 + tb];
        float xw[NV * 4];
        #pragma unroll
        for (int v = 0; v < NV; v++) {
            float4 c = xr[v];
            xw[v * 4 + 0] = c.x; xw[v * 4 + 1] = c.y;
            xw[v * 4 + 2] = c.z; xw[v * 4 + 3] = c.w;
        }

        #pragma unroll
        for (int k = 0; k < 3; k++) {
            float4 wa = __ldg((const float4*)(w + k * 4096 + ci * 64 + co0));
            #pragma unroll
            for (int i = 0; i < 4; i++) {
                float xv = xw[i + k * DIL];
                acc[i][0] += xv * wa.x; acc[i][1] += xv * wa.y;
                acc[i][2] += xv * wa.z; acc[i][3] += xv * wa.w;
            }
        }
    }

    float4 bv = *(const float4*)(bias + co0);
    #pragma unroll
    for (int i = 0; i < 4; i++) {
        int gt = t0 + tb + i;
        float* op = y + ((size_t)b * T + gt) * 64 + co0;
        float4 o;
        o.x = fmaxf(acc[i][0] + bv.x, 0.f);
        o.y = fmaxf(acc[i][1] + bv.y, 0.f);
        o.z = fmaxf(acc[i][2] + bv.z, 0.f);
        o.w = fmaxf(acc[i][3] + bv.w, 0.f);
        if (RES) {
            float4 r0 = *(const float4*)(res + ((size_t)b * T + gt) * 64 + co0);
            o.x += r0.x; o.y += r0.y; o.z += r0.z; o.w += r0.w;
        }
        *(float4*)op = o;
    }
}

// ---------------- strided down conv: K=4, stride 2, 64->64, ReLU ----------------
__global__ void __launch_bounds__(256, 2) conv_s2_kernel(
    const float* __restrict__ x, const float* __restrict__ w,
    const float* __restrict__ bias, float* __restrict__ y, int Tout)
{
    extern __shared__ float smem[];
    float* xs = smem;                           // [258][65]
    float* wsm = smem + ALIGN4(258 * 65);       // [64][64]
    const int Tin = Tout << 1;
    const int tid = threadIdx.x;
    const int tilesPerB = Tout >> 7;
    const int b = blockIdx.x / tilesPerB;
    const int t0 = (blockIdx.x - b * tilesPerB) << 7;
    const float* xb = x + (size_t)b * Tin * 64;

    for (int idx = tid; idx < 258 * 16; idx += 256) {
        int r = idx >> 4, c4 = idx & 15;
        int gt = 2 * t0 - 1 + r;
        float4 v = make_float4(0.f, 0.f, 0.f, 0.f);
        if (gt >= 0 && gt < Tin) v = *(const float4*)(xb + (size_t)gt * 64 + c4 * 4);
        float* d = &xs[r * 65 + c4 * 4];
        d[0] = v.x; d[1] = v.y; d[2] = v.z; d[3] = v.w;
    }

    const int tg = tid >> 3;
    const int cg = tid & 7;
    float acc[4][8];
    #pragma unroll
    for (int i = 0; i < 4; i++)
        #pragma unroll
        for (int j = 0; j < 8; j++) acc[i][j] = 0.f;

    for (int k = 0; k < 4; k++) {
        __syncthreads();
        {
            const float4* wg = (const float4*)(w + k * 4096);
            float4* wd = (float4*)wsm;
            for (int idx = tid; idx < 1024; idx += 256) wd[idx] = wg[idx];
        }
        __syncthreads();
        const float4* ws4 = (const float4*)wsm;
        #pragma unroll 2
        for (int ci = 0; ci < 64; ci++) {
            float4 wa = ws4[ci * 16 + cg * 2];
            float4 wb = ws4[ci * 16 + cg * 2 + 1];
            #pragma unroll
            for (int i = 0; i < 4; i++) {
                float xv = xs[(2 * (tg * 4 + i) + k) * 65 + ci];
                acc[i][0] += xv * wa.x; acc[i][1] += xv * wa.y;
                acc[i][2] += xv * wa.z; acc[i][3] += xv * wa.w;
                acc[i][4] += xv * wb.x; acc[i][5] += xv * wb.y;
                acc[i][6] += xv * wb.z; acc[i][7] += xv * wb.w;
            }
        }
    }

    const int co0 = cg * 8;
    float4 bv0 = *(const float4*)(bias + co0);
    float4 bv1 = *(const float4*)(bias + co0 + 4);
    #pragma unroll
    for (int i = 0; i < 4; i++) {
        int gt = t0 + tg * 4 + i;
        float* op = y + ((size_t)b * Tout + gt) * 64 + co0;
        float4 o0, o1;
        o0.x = fmaxf(acc[i][0] + bv0.x, 0.f);
        o0.y = fmaxf(acc[i][1] + bv0.y, 0.f);
        o0.z = fmaxf(acc[i][2] + bv0.z, 0.f);
        o0.w = fmaxf(acc[i][3] + bv0.w, 0.f);
        o1.x = fmaxf(acc[i][4] + bv1.x, 0.f);
        o1.y = fmaxf(acc[i][5] + bv1.y, 0.f);
        o1.z = fmaxf(acc[i][6] + bv1.z, 0.f);
        o1.w = fmaxf(acc[i][7] + bv1.w, 0.f);
        *(float4*)op = o0;
        *(float4*)(op + 4) = o1;
    }
}

// ---------------- transposed conv: K=4, stride 2, 64->64, ReLU ----------------
__global__ void __launch_bounds__(256, 2) conv_tr_kernel(
    const float* __restrict__ x, const float* __restrict__ w,
    const float* __restrict__ bias, float* __restrict__ y, int Tout)
{
    extern __shared__ float smem[];
    float* xs = smem;                           // [130][65]
    float* wsm = smem + ALIGN4(130 * 65);       // [4][64][64]
    const int Tin = Tout >> 1;
    const int tid = threadIdx.x;
    const int tilesPerB = Tout >> 8;
    const int b = blockIdx.x / tilesPerB;
    const int t0 = (blockIdx.x - b * tilesPerB) << 8;
    const float* xb = x + (size_t)b * Tin * 64;
    const int in0 = (t0 >> 1) - 1;

    for (int idx = tid; idx < 130 * 16; idx += 256) {
        int r = idx >> 4, c4 = idx & 15;
        int gt = in0 + r;
        float4 v = make_float4(0.f, 0.f, 0.f, 0.f);
        if (gt >= 0 && gt < Tin) v = *(const float4*)(xb + (size_t)gt * 64 + c4 * 4);
        float* d = &xs[r * 65 + c4 * 4];
        d[0] = v.x; d[1] = v.y; d[2] = v.z; d[3] = v.w;
    }
    {
        const float4* wg = (const float4*)w;
        float4* wd = (float4*)wsm;
        for (int idx = tid; idx < 4096; idx += 256) wd[idx] = wg[idx];
    }
    __syncthreads();

    const int tg = tid >> 3;
    const int cg = tid & 7;
    float acc[8][8];
    #pragma unroll
    for (int i = 0; i < 8; i++)
        #pragma unroll
        for (int j = 0; j < 8; j++) acc[i][j] = 0.f;

    const float4* ws4 = (const float4*)wsm;
    #pragma unroll 2
    for (int ci = 0; ci < 64; ci++) {
        float xv[6];
        #pragma unroll
        for (int m = 0; m < 6; m++) xv[m] = xs[(tg * 4 + m) * 65 + ci];
        {
            float4 wa0 = ws4[ci * 16 + cg * 2];
            float4 wb0 = ws4[ci * 16 + cg * 2 + 1];
            float4 wa2 = ws4[2 * 1024 + ci * 16 + cg * 2];
            float4 wb2 = ws4[2 * 1024 + ci * 16 + cg * 2 + 1];
            #pragma unroll
            for (int ii = 0; ii < 4; ii++) {
                const int i = 2 * ii;
                float xa = xv[ii], xbv = xv[ii + 1];
                acc[i][0] += xa * wa0.x + xbv * wa2.x;
                acc[i][1] += xa * wa0.y + xbv * wa2.y;
                acc[i][2] += xa * wa0.z + xbv * wa2.z;
                acc[i][3] += xa * wa0.w + xbv * wa2.w;
                acc[i][4] += xa * wb0.x + xbv * wb2.x;
                acc[i][5] += xa * wb0.y + xbv * wb2.y;
                acc[i][6] += xa * wb0.z + xbv * wb2.z;
                acc[i][7] += xa * wb0.w + xbv * wb2.w;
            }
        }
        {
            float4 wa1 = ws4[1024 + ci * 16 + cg * 2];
            float4 wb1 = ws4[1024 + ci * 16 + cg * 2 + 1];
            float4 wa3 = ws4[3 * 1024 + ci * 16 + cg * 2];
            float4 wb3 = ws4[3 * 1024 + ci * 16 + cg * 2 + 1];
            #pragma unroll
            for (int ii = 0; ii < 4; ii++) {
                const int i = 2 * ii + 1;
                float xa = xv[ii + 1], xbv = xv[ii + 2];
                acc[i][0] += xa * wa1.x + xbv * wa3.x;
                acc[i][1] += xa * wa1.y + xbv * wa3.y;
                acc[i][2] += xa * wa1.z + xbv * wa3.z;
                acc[i][3] += xa * wa1.w + xbv * wa3.w;
                acc[i][4] += xa * wb1.x + xbv * wb3.x;
                acc[i][5] += xa * wb1.y + xbv * wb3.y;
                acc[i][6] += xa * wb1.z + xbv * wb3.z;
                acc[i][7] += xa * wb1.w + xbv * wb3.w;
            }
        }
    }

    const int co0 = cg * 8;
    float4 bv0 = *(const float4*)(bias + co0);
    float4 bv1 = *(const float4*)(bias + co0 + 4);
    #pragma unroll
    for (int i = 0; i < 8; i++) {
        int gt = t0 + tg * 8 + i;
        float* op = y + ((size_t)b * Tout + gt) * 64 + co0;
        float4 o0, o1;
        o0.x = fmaxf(acc[i][0] + bv0.x, 0.f);
        o0.y = fmaxf(acc[i][1] + bv0.y, 0.f);
        o0.z = fmaxf(acc[i][2] + bv0.z, 0.f);
        o0.w = fmaxf(acc[i][3] + bv0.w, 0.f);
        o1.x = fmaxf(acc[i][4] + bv1.x, 0.f);
        o1.y = fmaxf(acc[i][5] + bv1.y, 0.f);
        o1.z = fmaxf(acc[i][6] + bv1.z, 0.f);
        o1.w = fmaxf(acc[i][7] + bv1.w, 0.f);
        *(float4*)op = o0;
        *(float4*)(op + 4) = o1;
    }
}

// ---------------- final projection: K=3, dil 1, 64->1, linear ----------------
__global__ void __launch_bounds__(256) proj_kernel(
    const float* __restrict__ x, const float* __restrict__ w,
    const float* __restrict__ bias, float* __restrict__ out, int T)
{
    extern __shared__ float smem[];
    float* xs = smem;                           // [258][65]
    float* ws = smem + ALIGN4(258 * 65);        // [192]
    const int tid = threadIdx.x;
    const int tilesPerB = T >> 8;
    const int b = blockIdx.x / tilesPerB;
    const int t0 = (blockIdx.x - b * tilesPerB) << 8;
    const float* xb = x + (size_t)b * T * 64;

    for (int idx = tid; idx < 258 * 16; idx += 256) {
        int r = idx >> 4, c4 = idx & 15;
        int gt = t0 - 1 + r;
        float4 v = make_float4(0.f, 0.f, 0.f, 0.f);
        if (gt >= 0 && gt < T) v = *(const float4*)(xb + (size_t)gt * 64 + c4 * 4);
        float* d = &xs[r * 65 + c4 * 4];
        d[0] = v.x; d[1] = v.y; d[2] = v.z; d[3] = v.w;
    }
    if (tid < 192) ws[tid] = w[tid];
    __syncthreads();

    float acc = 0.f;
    #pragma unroll
    for (int k = 0; k < 3; k++) {
        #pragma unroll 8
        for (int ci = 0; ci < 64; ci++)
            acc += xs[(tid + k) * 65 + ci] * ws[k * 64 + ci];
    }
    out[OFF_XHAT + (size_t)b * T + t0 + tid] = acc + bias[0];
}

// ---------------- VQ ----------------
__global__ void __launch_bounds__(256) vq_kernel(
    const float* __restrict__ ze, const float* __restrict__ cb,
    float* __restrict__ zq, float* __restrict__ dout)
{
    __shared__ float zs[32 * 65];
    __shared__ float cbs[128 * 65];
    __shared__ float nzs[32], rsnzs[32];

    const int tid = threadIdx.x;
    const int rg = tid >> 5;
    const int eg = tid & 31;
    const int row0 = blockIdx.x * 32;

    for (int idx = tid; idx < 32 * 16; idx += 256) {
        int r = idx >> 4, c4 = idx & 15;
        float4 v = *(const float4*)(ze + (size_t)(row0 + r) * 64 + c4 * 4);
        float* d = &zs[r * 65 + c4 * 4];
        d[0] = v.x; d[1] = v.y; d[2] = v.z; d[3] = v.w;
    }
    __syncthreads();
    if (tid < 32) {
        float s = 0.f;
        #pragma unroll 8
        for (int ci = 0; ci < 64; ci++) { float v = zs[tid * 65 + ci]; s += v * v; }
        nzs[tid] = s;
        rsnzs[tid] = rsqrtf(s);
    }

    float bv[4] = {3.4e38f, 3.4e38f, 3.4e38f, 3.4e38f};
    int bi[4] = {0, 0, 0, 0};

    for (int c = 0; c < 4; c++) {
        __syncthreads();
        for (int idx = tid; idx < 128 * 16; idx += 256) {
            int e = idx >> 4, c4 = idx & 15;
            float4 v = *(const float4*)(cb + (size_t)(c * 128 + e) * 64 + c4 * 4);
            float* d = &cbs[e * 65 + c4 * 4];
            d[0] = v.x; d[1] = v.y; d[2] = v.z; d[3] = v.w;
        }
        __syncthreads();

        float acc[4][4];
        #pragma unroll
        for (int i = 0; i < 4; i++)
            #pragma unroll
            for (int j = 0; j < 4; j++) acc[i][j] = 0.f;

        #pragma unroll 4
        for (int ci = 0; ci < 64; ci++) {
            float zv[4], cv[4];
            #pragma unroll
            for (int i = 0; i < 4; i++) zv[i] = zs[(rg * 4 + i) * 65 + ci];
            #pragma unroll
            for (int j = 0; j < 4; j++) cv[j] = cbs[(j * 32 + eg) * 65 + ci];
            #pragma unroll
            for (int i = 0; i < 4; i++)
                #pragma unroll
                for (int j = 0; j < 4; j++) acc[i][j] += zv[i] * cv[j];
        }

        #pragma unroll
        for (int j = 0; j < 4; j++) {
            int e = c * 128 + j * 32 + eg;
            float nev = __ldg(&g_ne[e]);
            float rse = __ldg(&g_rsne[e]);
            #pragma unroll
            for (int i = 0; i < 4; i++) {
                int r = rg * 4 + i;
                float dot = acc[i][j];
                float dist = -2.0f * dot + nzs[r] + nev;
                float sim = dot * rsnzs[r] * rse;
                dout[OFF_SIM + (size_t)(row0 + r) * NEMB + e] = sim;
                if (dist < bv[i]) { bv[i] = dist; bi[i] = e; }
            }
        }
    }

    #pragma unroll
    for (int i = 0; i < 4; i++) {
        float v = bv[i];
        int idx = bi[i];
        #pragma unroll
        for (int off = 16; off > 0; off >>= 1) {
            float ov = __shfl_down_sync(0xffffffffu, v, off);
            int oi = __shfl_down_sync(0xffffffffu, idx, off);
            if (ov < v || (ov == v && oi < idx)) { v = ov; idx = oi; }
        }
        if (eg == 0) {
            int r = rg * 4 + i;
            int gr = row0 + r;
            dout[OFF_IDS + gr] = (float)idx;
            float s = 0.f;
            const float* cp = cb + (size_t)idx * 64;
            float* qp = zq + (size_t)gr * 64;
            #pragma unroll 8
            for (int ci = 0; ci < 64; ci++) {
                float cvv = __ldg(cp + ci);
                qp[ci] = cvv;
                float d = zs[r * 65 + ci] - cvv;
                s += d * d;
            }
            atomicAdd(&g_loss, sqrtf(s));
        }
    }
}

// ---------------- host orchestration ----------------
#define SMEM_RES128 (64 * XS128 * 4)
#define SMEM_RES64  (64 * XS64 * 4)
#define SMEM_S2   ((ALIGN4(258 * 65) + 4096) * 4)
#define SMEM_TR   ((ALIGN4(130 * 65) + 16384) * 4)
#define SMEM_PROJ ((ALIGN4(258 * 65) + 192) * 4)

static inline void launch_res_pair(bool enc, int T,
    const float* w1, const float* b1, const float* w2, const float* b2,
    float* h, float* t)
{
    if (T >= 32768) {
        const int grid = NBATCH * (T >> 7);
        if (enc) {
            conv_res128_kernel<3, false><<<grid, 256, SMEM_RES128>>>(h, w1, b1, nullptr, t, T);
            conv_res128_kernel<1, true ><<<grid, 256, SMEM_RES128>>>(t, w2, b2, h, h, T);
        } else {
            conv_res128_kernel<1, false><<<grid, 256, SMEM_RES128>>>(h, w1, b1, nullptr, t, T);
            conv_res128_kernel<3, true ><<<grid, 256, SMEM_RES128>>>(t, w2, b2, h, h, T);
        }
    } else {
        const int grid = NBATCH * (T >> 6);
        if (enc) {
            conv_res64_kernel<3, false><<<grid, 256, SMEM_RES64>>>(h, w1, b1, nullptr, t, T);
            conv_res64_kernel<1, true ><<<grid, 256, SMEM_RES64>>>(t, w2, b2, h, h, T);
        } else {
            conv_res64_kernel<1, false><<<grid, 256, SMEM_RES64>>>(h, w1, b1, nullptr, t, T);
            conv_res64_kernel<3, true ><<<grid, 256, SMEM_RES64>>>(t, w2, b2, h, h, T);
        }
    }
}

extern "C" void kernel_launch(void* const* d_in, const int* in_sizes, int n_in,
                              void* d_out, int out_size)
{
    const float* x        = (const float*)d_in[0];
    const float* w_down0  = (const float*)d_in[1];
    const float* b_down0  = (const float*)d_in[2];
    const float* w_down   = (const float*)d_in[3];
    const float* b_down   = (const float*)d_in[4];
    const float* w_res_e  = (const float*)d_in[5];
    const float* b_res_e  = (const float*)d_in[6];
    const float* codebook = (const float*)d_in[7];
    const float* w_res_d  = (const float*)d_in[8];
    const float* b_res_d  = (const float*)d_in[9];
    const float* w_up     = (const float*)d_in[10];
    const float* b_up     = (const float*)d_in[11];
    const float* w_proj   = (const float*)d_in[12];
    const float* b_proj   = (const float*)d_in[13];
    float* out = (float*)d_out;

    float *A, *Bb;
    cudaGetSymbolAddress((void**)&A, g_A);
    cudaGetSymbolAddress((void**)&Bb, g_B);

    cudaFuncSetAttribute(conv_res128_kernel<3, false>, cudaFuncAttributeMaxDynamicSharedMemorySize, SMEM_RES128);
    cudaFuncSetAttribute(conv_res128_kernel<3, true >, cudaFuncAttributeMaxDynamicSharedMemorySize, SMEM_RES128);
    cudaFuncSetAttribute(conv_res128_kernel<1, false>, cudaFuncAttributeMaxDynamicSharedMemorySize, SMEM_RES128);
    cudaFuncSetAttribute(conv_res128_kernel<1, true >, cudaFuncAttributeMaxDynamicSharedMemorySize, SMEM_RES128);
    cudaFuncSetAttribute(conv_res64_kernel<3, false>, cudaFuncAttributeMaxDynamicSharedMemorySize, SMEM_RES64);
    cudaFuncSetAttribute(conv_res64_kernel<3, true >, cudaFuncAttributeMaxDynamicSharedMemorySize, SMEM_RES64);
    cudaFuncSetAttribute(conv_res64_kernel<1, false>, cudaFuncAttributeMaxDynamicSharedMemorySize, SMEM_RES64);
    cudaFuncSetAttribute(conv_res64_kernel<1, true >, cudaFuncAttributeMaxDynamicSharedMemorySize, SMEM_RES64);
    cudaFuncSetAttribute(conv_s2_kernel, cudaFuncAttributeMaxDynamicSharedMemorySize, SMEM_S2);
    cudaFuncSetAttribute(conv_tr_kernel, cudaFuncAttributeMaxDynamicSharedMemorySize, SMEM_TR);
    cudaFuncSetAttribute(proj_kernel,    cudaFuncAttributeMaxDynamicSharedMemorySize, SMEM_PROJ);

    zero_loss_kernel<<<1, 1>>>();
    ne_kernel<<<2, 256>>>(codebook);

    float* h = A;
    float* t = Bb;

    // ---------- encoder ----------
    down0_kernel<<<2048, 256>>>(x, w_down0, b_down0, h);
    int T = 32768;
    for (int blk = 0; blk < 3; blk++) {
        if (blk > 0) {
            int Tout = T >> 1;
            conv_s2_kernel<<<NBATCH * (Tout >> 7), 256, SMEM_S2>>>(
                h, w_down + (size_t)(blk - 1) * 16384, b_down + (blk - 1) * 64, t, Tout);
            T = Tout;
            float* tmp = h; h = t; t = tmp;
        }
        for (int r = 0; r < 4; r++) {
            const float* w1 = w_res_e + (size_t)((blk * 4 + r) * 2 + 0) * 12288;
            const float* w2 = w_res_e + (size_t)((blk * 4 + r) * 2 + 1) * 12288;
            const float* bb1 = b_res_e + ((blk * 4 + r) * 2 + 0) * 64;
            const float* bb2 = b_res_e + ((blk * 4 + r) * 2 + 1) * 64;
            launch_res_pair(true, T, w1, bb1, w2, bb2, h, t);
        }
    }

    // ---------- VQ (T = 8192) ----------
    vq_kernel<<<1024, 256>>>(h, codebook, t, out);
    loss_fin_kernel<<<1, 1>>>(out);
    { float* tmp = h; h = t; t = tmp; }   // h = z_q

    // ---------- decoder ----------
    for (int blk = 0; blk < 3; blk++) {
        for (int r = 0; r < 4; r++) {
            const float* w1 = w_res_d + (size_t)((blk * 4 + r) * 2 + 0) * 12288;
            const float* w2 = w_res_d + (size_t)((blk * 4 + r) * 2 + 1) * 12288;
            const float* bb1 = b_res_d + ((blk * 4 + r) * 2 + 0) * 64;
            const float* bb2 = b_res_d + ((blk * 4 + r) * 2 + 1) * 64;
            launch_res_pair(false, T, w1, bb1, w2, bb2, h, t);
        }
        int Tout = T << 1;
        conv_tr_kernel<<<NBATCH * (Tout >> 8), 256, SMEM_TR>>>(
            h, w_up + (size_t)blk * 16384, b_up + blk * 64, t, Tout);
        T = Tout;
        float* tmp = h; h = t; t = tmp;
    }

    // ---------- projection (T = 65536) ----------
    proj_kernel<<<NBATCH * (T >> 8), 256, SMEM_PROJ>>>(h, w_proj, b_proj, out, T);
}

// round 12
// speedup vs baseline: 1.5632x; 1.5632x over previous
#include <cuda_runtime.h>
#include <math.h>

// ---------------- constants ----------------
#define NBATCH 4
#define TTOP   65536
#define OFF_XHAT 0
#define OFF_LOSS 262144
#define OFF_IDS  262145
#define OFF_SIM  294913
#define NEMB 512

#define ALIGN4(n) (((n) + 3) & ~3)

// ---------------- scratch ----------------
__device__ float g_A[16777216];
__device__ float g_B[16777216];
__device__ float g_ne[NEMB];
__device__ float g_rsne[NEMB];
__device__ float g_loss;

__global__ void zero_loss_kernel() { g_loss = 0.f; }

__global__ void ne_kernel(const float* __restrict__ cb) {
    int e = blockIdx.x * blockDim.x + threadIdx.x;
    if (e < NEMB) {
        float s = 0.f;
        #pragma unroll 8
        for (int ci = 0; ci < 64; ci++) { float v = cb[e * 64 + ci]; s += v * v; }
        g_ne[e] = s;
        g_rsne[e] = rsqrtf(s);
    }
}

__global__ void loss_fin_kernel(float* __restrict__ out) {
    out[OFF_LOSS] = 1.25f * g_loss / 32768.0f;
}

// ---------------- first conv: Cin=1 -> 64, K=4, stride 2, ReLU ----------------
__global__ void __launch_bounds__(256) down0_kernel(
    const float* __restrict__ x, const float* __restrict__ w,
    const float* __restrict__ bias, float* __restrict__ y)
{
    __shared__ float ws[256];
    __shared__ float bs[64];
    int tid = threadIdx.x;
    ws[tid] = w[tid];
    if (tid < 64) bs[tid] = bias[tid];
    __syncthreads();

    int g = blockIdx.x * 256 + tid;
    int q = g & 3;
    int rest = g >> 2;
    int ot = rest & 32767;
    int b = rest >> 15;

    float acc[16];
    #pragma unroll
    for (int c = 0; c < 16; c++) acc[c] = bs[q * 16 + c];
    #pragma unroll
    for (int k = 0; k < 4; k++) {
        int t = 2 * ot - 1 + k;
        float xv = (t >= 0 && t < TTOP) ? x[(size_t)b * TTOP + t] : 0.f;
        #pragma unroll
        for (int c = 0; c < 16; c++) acc[c] += xv * ws[k * 64 + q * 16 + c];
    }
    float* op = y + ((size_t)(b * 32768 + ot)) * 64 + q * 16;
    #pragma unroll
    for (int c4 = 0; c4 < 4; c4++) {
        float4 o;
        o.x = fmaxf(acc[c4 * 4 + 0], 0.f);
        o.y = fmaxf(acc[c4 * 4 + 1], 0.f);
        o.z = fmaxf(acc[c4 * 4 + 2], 0.f);
        o.w = fmaxf(acc[c4 * 4 + 3], 0.f);
        *(float4*)(op + c4 * 4) = o;
    }
}

// ---------------- residual conv, 128-t tile (proven R6 kernel) --------------
// 256 threads, 8t x 4co per thread, x transposed in smem [64][164],
// weights via __ldg, 3 CTAs/SM. Best in-wave efficiency; used at T=32768.
#define XS128 164

template<int DIL, bool RES>
__global__ void __launch_bounds__(256, 3) conv_res128_kernel(
    const float* __restrict__ x, const float* __restrict__ w,
    const float* __restrict__ bias, const float* __restrict__ res,
    float* __restrict__ y, int T)
{
    constexpr int ROWS = 128 + 2 * DIL;
    constexpr int NQ = (ROWS + 3) >> 2;
    constexpr int W = 8 + 2 * DIL;
    constexpr int NV = (W + 3) >> 2;

    extern __shared__ float smem[];
    float* xsT = smem;   // [64][XS128]

    const int tid = threadIdx.x;
    const int tilesPerB = T >> 7;
    const int b = blockIdx.x / tilesPerB;
    const int t0 = (blockIdx.x - b * tilesPerB) << 7;
    const float* xb = x + (size_t)b * T * 64;

    for (int idx = tid; idx < 64 * NQ; idx += 256) {
        int ci = idx & 63;
        int rb = (idx >> 6) << 2;
        int gt = t0 - DIL + rb;
        float4 v;
        v.x = (gt + 0 >= 0 && gt + 0 < T) ? xb[(size_t)(gt + 0) * 64 + ci] : 0.f;
        v.y = (gt + 1 >= 0 && gt + 1 < T) ? xb[(size_t)(gt + 1) * 64 + ci] : 0.f;
        v.z = (gt + 2 >= 0 && gt + 2 < T) ? xb[(size_t)(gt + 2) * 64 + ci] : 0.f;
        v.w = (gt + 3 >= 0 && gt + 3 < T) ? xb[(size_t)(gt + 3) * 64 + ci] : 0.f;
        *(float4*)&xsT[ci * XS128 + rb] = v;
    }
    __syncthreads();

    const int tg = tid >> 4;
    const int cg = tid & 15;
    const int tb = tg << 3;
    const int co0 = cg << 2;

    float acc[8][4];
    #pragma unroll
    for (int i = 0; i < 8; i++)
        #pragma unroll
        for (int j = 0; j < 4; j++) acc[i][j] = 0.f;

    #pragma unroll 2
    for (int ci = 0; ci < 64; ci++) {
        const float4* xr = (const float4*)&xsT[ci * XS128 + tb];
        float xw[NV * 4];
        #pragma unroll
        for (int v = 0; v < NV; v++) {
            float4 c = xr[v];
            xw[v * 4 + 0] = c.x; xw[v * 4 + 1] = c.y;
            xw[v * 4 + 2] = c.z; xw[v * 4 + 3] = c.w;
        }

        #pragma unroll
        for (int k = 0; k < 3; k++) {
            float4 wa = __ldg((const float4*)(w + k * 4096 + ci * 64 + co0));
            #pragma unroll
            for (int i = 0; i < 8; i++) {
                float xv = xw[i + k * DIL];
                acc[i][0] += xv * wa.x; acc[i][1] += xv * wa.y;
                acc[i][2] += xv * wa.z; acc[i][3] += xv * wa.w;
            }
        }
    }

    float4 bv = *(const float4*)(bias + co0);
    #pragma unroll
    for (int i = 0; i < 8; i++) {
        int gt = t0 + tb + i;
        float* op = y + ((size_t)b * T + gt) * 64 + co0;
        float4 o;
        o.x = fmaxf(acc[i][0] + bv.x, 0.f);
        o.y = fmaxf(acc[i][1] + bv.y, 0.f);
        o.z = fmaxf(acc[i][2] + bv.z, 0.f);
        o.w = fmaxf(acc[i][3] + bv.w, 0.f);
        if (RES) {
            float4 r0 = *(const float4*)(res + ((size_t)b * T + gt) * 64 + co0);
            o.x += r0.x; o.y += r0.y; o.z += r0.z; o.w += r0.w;
        }
        *(float4*)op = o;
    }
}

// ---------------- residual conv, 64-t tile (proven R10 kernel) --------------
// 256 threads, 4t x 4co per thread, x transposed in smem [64][76],
// 4 CTAs/SM. Better wave geometry; used at T<=16384.
#define XS64 76

template<int DIL, bool RES>
__global__ void __launch_bounds__(256, 4) conv_res64_kernel(
    const float* __restrict__ x, const float* __restrict__ w,
    const float* __restrict__ bias, const float* __restrict__ res,
    float* __restrict__ y, int T)
{
    constexpr int ROWS = 64 + 2 * DIL;
    constexpr int NQ = (ROWS + 3) >> 2;
    constexpr int W = 4 + 2 * DIL;
    constexpr int NV = (W + 3) >> 2;

    extern __shared__ float smem[];
    float* xsT = smem;   // [64][XS64]

    const int tid = threadIdx.x;
    const int tilesPerB = T >> 6;
    const int b = blockIdx.x / tilesPerB;
    const int t0 = (blockIdx.x - b * tilesPerB) << 6;
    const float* xb = x + (size_t)b * T * 64;

    for (int idx = tid; idx < 64 * NQ; idx += 256) {
        int ci = idx & 63;
        int rb = (idx >> 6) << 2;
        int gt = t0 - DIL + rb;
        float4 v;
        v.x = (gt + 0 >= 0 && gt + 0 < T) ? xb[(size_t)(gt + 0) * 64 + ci] : 0.f;
        v.y = (gt + 1 >= 0 && gt + 1 < T) ? xb[(size_t)(gt + 1) * 64 + ci] : 0.f;
        v.z = (gt + 2 >= 0 && gt + 2 < T) ? xb[(size_t)(gt + 2) * 64 + ci] : 0.f;
        v.w = (gt + 3 >= 0 && gt + 3 < T) ? xb[(size_t)(gt + 3) * 64 + ci] : 0.f;
        *(float4*)&xsT[ci * XS64 + rb] = v;
    }
    __syncthreads();

    const int tg = tid >> 4;
    const int cg = tid & 15;
    const int tb = tg << 2;
    const int co0 = cg << 2;

    float acc[4][4];
    #pragma unroll
    for (int i = 0; i < 4; i++)
        #pragma unroll
        for (int j = 0; j < 4; j++) acc[i][j] = 0.f;

    #pragma unroll 2
    for (int ci = 0; ci < 64; ci++) {
        const float4* xr = (const float4*)&xsT[ci * XS64 + tb];
        float xw[NV * 4];
        #pragma unroll
        for (int v = 0; v < NV; v++) {
            float4 c = xr[v];
            xw[v * 4 + 0] = c.x; xw[v * 4 + 1] = c.y;
            xw[v * 4 + 2] = c.z; xw[v * 4 + 3] = c.w;
        }

        #pragma unroll
        for (int k = 0; k < 3; k++) {
            float4 wa = __ldg((const float4*)(w + k * 4096 + ci * 64 + co0));
            #pragma unroll
            for (int i = 0; i < 4; i++) {
                float xv = xw[i + k * DIL];
                acc[i][0] += xv * wa.x; acc[i][1] += xv * wa.y;
                acc[i][2] += xv * wa.z; acc[i][3] += xv * wa.w;
            }
        }
    }

    float4 bv = *(const float4*)(bias + co0);
    #pragma unroll
    for (int i = 0; i < 4; i++) {
        int gt = t0 + tb + i;
        float* op = y + ((size_t)b * T + gt) * 64 + co0;
        float4 o;
        o.x = fmaxf(acc[i][0] + bv.x, 0.f);
        o.y = fmaxf(acc[i][1] + bv.y, 0.f);
        o.z = fmaxf(acc[i][2] + bv.z, 0.f);
        o.w = fmaxf(acc[i][3] + bv.w, 0.f);
        if (RES) {
            float4 r0 = *(const float4*)(res + ((size_t)b * T + gt) * 64 + co0);
            o.x += r0.x; o.y += r0.y; o.z += r0.z; o.w += r0.w;
        }
        *(float4*)op = o;
    }
}

// ---------------- strided down conv: K=4, stride 2, 64->64, ReLU ----------------
__global__ void __launch_bounds__(256, 2) conv_s2_kernel(
    const float* __restrict__ x, const float* __restrict__ w,
    const float* __restrict__ bias, float* __restrict__ y, int Tout)
{
    extern __shared__ float smem[];
    float* xs = smem;                           // [258][65]
    float* wsm = smem + ALIGN4(258 * 65);       // [64][64]
    const int Tin = Tout << 1;
    const int tid = threadIdx.x;
    const int tilesPerB = Tout >> 7;
    const int b = blockIdx.x / tilesPerB;
    const int t0 = (blockIdx.x - b * tilesPerB) << 7;
    const float* xb = x + (size_t)b * Tin * 64;

    for (int idx = tid; idx < 258 * 16; idx += 256) {
        int r = idx >> 4, c4 = idx & 15;
        int gt = 2 * t0 - 1 + r;
        float4 v = make_float4(0.f, 0.f, 0.f, 0.f);
        if (gt >= 0 && gt < Tin) v = *(const float4*)(xb + (size_t)gt * 64 + c4 * 4);
        float* d = &xs[r * 65 + c4 * 4];
        d[0] = v.x; d[1] = v.y; d[2] = v.z; d[3] = v.w;
    }

    const int tg = tid >> 3;
    const int cg = tid & 7;
    float acc[4][8];
    #pragma unroll
    for (int i = 0; i < 4; i++)
        #pragma unroll
        for (int j = 0; j < 8; j++) acc[i][j] = 0.f;

    for (int k = 0; k < 4; k++) {
        __syncthreads();
        {
            const float4* wg = (const float4*)(w + k * 4096);
            float4* wd = (float4*)wsm;
            for (int idx = tid; idx < 1024; idx += 256) wd[idx] = wg[idx];
        }
        __syncthreads();
        const float4* ws4 = (const float4*)wsm;
        #pragma unroll 2
        for (int ci = 0; ci < 64; ci++) {
            float4 wa = ws4[ci * 16 + cg * 2];
            float4 wb = ws4[ci * 16 + cg * 2 + 1];
            #pragma unroll
            for (int i = 0; i < 4; i++) {
                float xv = xs[(2 * (tg * 4 + i) + k) * 65 + ci];
                acc[i][0] += xv * wa.x; acc[i][1] += xv * wa.y;
                acc[i][2] += xv * wa.z; acc[i][3] += xv * wa.w;
                acc[i][4] += xv * wb.x; acc[i][5] += xv * wb.y;
                acc[i][6] += xv * wb.z; acc[i][7] += xv * wb.w;
            }
        }
    }

    const int co0 = cg * 8;
    float4 bv0 = *(const float4*)(bias + co0);
    float4 bv1 = *(const float4*)(bias + co0 + 4);
    #pragma unroll
    for (int i = 0; i < 4; i++) {
        int gt = t0 + tg * 4 + i;
        float* op = y + ((size_t)b * Tout + gt) * 64 + co0;
        float4 o0, o1;
        o0.x = fmaxf(acc[i][0] + bv0.x, 0.f);
        o0.y = fmaxf(acc[i][1] + bv0.y, 0.f);
        o0.z = fmaxf(acc[i][2] + bv0.z, 0.f);
        o0.w = fmaxf(acc[i][3] + bv0.w, 0.f);
        o1.x = fmaxf(acc[i][4] + bv1.x, 0.f);
        o1.y = fmaxf(acc[i][5] + bv1.y, 0.f);
        o1.z = fmaxf(acc[i][6] + bv1.z, 0.f);
        o1.w = fmaxf(acc[i][7] + bv1.w, 0.f);
        *(float4*)op = o0;
        *(float4*)(op + 4) = o1;
    }
}

// ---------------- transposed conv: K=4, stride 2, 64->64, ReLU ----------------
__global__ void __launch_bounds__(256, 2) conv_tr_kernel(
    const float* __restrict__ x, const float* __restrict__ w,
    const float* __restrict__ bias, float* __restrict__ y, int Tout)
{
    extern __shared__ float smem[];
    float* xs = smem;                           // [130][65]
    float* wsm = smem + ALIGN4(130 * 65);       // [4][64][64]
    const int Tin = Tout >> 1;
    const int tid = threadIdx.x;
    const int tilesPerB = Tout >> 8;
    const int b = blockIdx.x / tilesPerB;
    const int t0 = (blockIdx.x - b * tilesPerB) << 8;
    const float* xb = x + (size_t)b * Tin * 64;
    const int in0 = (t0 >> 1) - 1;

    for (int idx = tid; idx < 130 * 16; idx += 256) {
        int r = idx >> 4, c4 = idx & 15;
        int gt = in0 + r;
        float4 v = make_float4(0.f, 0.f, 0.f, 0.f);
        if (gt >= 0 && gt < Tin) v = *(const float4*)(xb + (size_t)gt * 64 + c4 * 4);
        float* d = &xs[r * 65 + c4 * 4];
        d[0] = v.x; d[1] = v.y; d[2] = v.z; d[3] = v.w;
    }
    {
        const float4* wg = (const float4*)w;
        float4* wd = (float4*)wsm;
        for (int idx = tid; idx < 4096; idx += 256) wd[idx] = wg[idx];
    }
    __syncthreads();

    const int tg = tid >> 3;
    const int cg = tid & 7;
    float acc[8][8];
    #pragma unroll
    for (int i = 0; i < 8; i++)
        #pragma unroll
        for (int j = 0; j < 8; j++) acc[i][j] = 0.f;

    const float4* ws4 = (const float4*)wsm;
    #pragma unroll 2
    for (int ci = 0; ci < 64; ci++) {
        float xv[6];
        #pragma unroll
        for (int m = 0; m < 6; m++) xv[m] = xs[(tg * 4 + m) * 65 + ci];
        {
            float4 wa0 = ws4[ci * 16 + cg * 2];
            float4 wb0 = ws4[ci * 16 + cg * 2 + 1];
            float4 wa2 = ws4[2 * 1024 + ci * 16 + cg * 2];
            float4 wb2 = ws4[2 * 1024 + ci * 16 + cg * 2 + 1];
            #pragma unroll
            for (int ii = 0; ii < 4; ii++) {
                const int i = 2 * ii;
                float xa = xv[ii], xbv = xv[ii + 1];
                acc[i][0] += xa * wa0.x + xbv * wa2.x;
                acc[i][1] += xa * wa0.y + xbv * wa2.y;
                acc[i][2] += xa * wa0.z + xbv * wa2.z;
                acc[i][3] += xa * wa0.w + xbv * wa2.w;
                acc[i][4] += xa * wb0.x + xbv * wb2.x;
                acc[i][5] += xa * wb0.y + xbv * wb2.y;
                acc[i][6] += xa * wb0.z + xbv * wb2.z;
                acc[i][7] += xa * wb0.w + xbv * wb2.w;
            }
        }
        {
            float4 wa1 = ws4[1024 + ci * 16 + cg * 2];
            float4 wb1 = ws4[1024 + ci * 16 + cg * 2 + 1];
            float4 wa3 = ws4[3 * 1024 + ci * 16 + cg * 2];
            float4 wb3 = ws4[3 * 1024 + ci * 16 + cg * 2 + 1];
            #pragma unroll
            for (int ii = 0; ii < 4; ii++) {
                const int i = 2 * ii + 1;
                float xa = xv[ii + 1], xbv = xv[ii + 2];
                acc[i][0] += xa * wa1.x + xbv * wa3.x;
                acc[i][1] += xa * wa1.y + xbv * wa3.y;
                acc[i][2] += xa * wa1.z + xbv * wa3.z;
                acc[i][3] += xa * wa1.w + xbv * wa3.w;
                acc[i][4] += xa * wb1.x + xbv * wb3.x;
                acc[i][5] += xa * wb1.y + xbv * wb3.y;
                acc[i][6] += xa * wb1.z + xbv * wb3.z;
                acc[i][7] += xa * wb1.w + xbv * wb3.w;
            }
        }
    }

    const int co0 = cg * 8;
    float4 bv0 = *(const float4*)(bias + co0);
    float4 bv1 = *(const float4*)(bias + co0 + 4);
    #pragma unroll
    for (int i = 0; i < 8; i++) {
        int gt = t0 + tg * 8 + i;
        float* op = y + ((size_t)b * Tout + gt) * 64 + co0;
        float4 o0, o1;
        o0.x = fmaxf(acc[i][0] + bv0.x, 0.f);
        o0.y = fmaxf(acc[i][1] + bv0.y, 0.f);
        o0.z = fmaxf(acc[i][2] + bv0.z, 0.f);
        o0.w = fmaxf(acc[i][3] + bv0.w, 0.f);
        o1.x = fmaxf(acc[i][4] + bv1.x, 0.f);
        o1.y = fmaxf(acc[i][5] + bv1.y, 0.f);
        o1.z = fmaxf(acc[i][6] + bv1.z, 0.f);
        o1.w = fmaxf(acc[i][7] + bv1.w, 0.f);
        *(float4*)op = o0;
        *(float4*)(op + 4) = o1;
    }
}

// ---------------- final projection: K=3, dil 1, 64->1, linear ----------------
__global__ void __launch_bounds__(256) proj_kernel(
    const float* __restrict__ x, const float* __restrict__ w,
    const float* __restrict__ bias, float* __restrict__ out, int T)
{
    extern __shared__ float smem[];
    float* xs = smem;                           // [258][65]
    float* ws = smem + ALIGN4(258 * 65);        // [192]
    const int tid = threadIdx.x;
    const int tilesPerB = T >> 8;
    const int b = blockIdx.x / tilesPerB;
    const int t0 = (blockIdx.x - b * tilesPerB) << 8;
    const float* xb = x + (size_t)b * T * 64;

    for (int idx = tid; idx < 258 * 16; idx += 256) {
        int r = idx >> 4, c4 = idx & 15;
        int gt = t0 - 1 + r;
        float4 v = make_float4(0.f, 0.f, 0.f, 0.f);
        if (gt >= 0 && gt < T) v = *(const float4*)(xb + (size_t)gt * 64 + c4 * 4);
        float* d = &xs[r * 65 + c4 * 4];
        d[0] = v.x; d[1] = v.y; d[2] = v.z; d[3] = v.w;
    }
    if (tid < 192) ws[tid] = w[tid];
    __syncthreads();

    float acc = 0.f;
    #pragma unroll
    for (int k = 0; k < 3; k++) {
        #pragma unroll 8
        for (int ci = 0; ci < 64; ci++)
            acc += xs[(tid + k) * 65 + ci] * ws[k * 64 + ci];
    }
    out[OFF_XHAT + (size_t)b * T + t0 + tid] = acc + bias[0];
}

// ---------------- VQ ----------------
__global__ void __launch_bounds__(256) vq_kernel(
    const float* __restrict__ ze, const float* __restrict__ cb,
    float* __restrict__ zq, float* __restrict__ dout)
{
    __shared__ float zs[32 * 65];
    __shared__ float cbs[128 * 65];
    __shared__ float nzs[32], rsnzs[32];

    const int tid = threadIdx.x;
    const int rg = tid >> 5;
    const int eg = tid & 31;
    const int row0 = blockIdx.x * 32;

    for (int idx = tid; idx < 32 * 16; idx += 256) {
        int r = idx >> 4, c4 = idx & 15;
        float4 v = *(const float4*)(ze + (size_t)(row0 + r) * 64 + c4 * 4);
        float* d = &zs[r * 65 + c4 * 4];
        d[0] = v.x; d[1] = v.y; d[2] = v.z; d[3] = v.w;
    }
    __syncthreads();
    if (tid < 32) {
        float s = 0.f;
        #pragma unroll 8
        for (int ci = 0; ci < 64; ci++) { float v = zs[tid * 65 + ci]; s += v * v; }
        nzs[tid] = s;
        rsnzs[tid] = rsqrtf(s);
    }

    float bv[4] = {3.4e38f, 3.4e38f, 3.4e38f, 3.4e38f};
    int bi[4] = {0, 0, 0, 0};

    for (int c = 0; c < 4; c++) {
        __syncthreads();
        for (int idx = tid; idx < 128 * 16; idx += 256) {
            int e = idx >> 4, c4 = idx & 15;
            float4 v = *(const float4*)(cb + (size_t)(c * 128 + e) * 64 + c4 * 4);
            float* d = &cbs[e * 65 + c4 * 4];
            d[0] = v.x; d[1] = v.y; d[2] = v.z; d[3] = v.w;
        }
        __syncthreads();

        float acc[4][4];
        #pragma unroll
        for (int i = 0; i < 4; i++)
            #pragma unroll
            for (int j = 0; j < 4; j++) acc[i][j] = 0.f;

        #pragma unroll 4
        for (int ci = 0; ci < 64; ci++) {
            float zv[4], cv[4];
            #pragma unroll
            for (int i = 0; i < 4; i++) zv[i] = zs[(rg * 4 + i) * 65 + ci];
            #pragma unroll
            for (int j = 0; j < 4; j++) cv[j] = cbs[(j * 32 + eg) * 65 + ci];
            #pragma unroll
            for (int i = 0; i < 4; i++)
                #pragma unroll
                for (int j = 0; j < 4; j++) acc[i][j] += zv[i] * cv[j];
        }

        #pragma unroll
        for (int j = 0; j < 4; j++) {
            int e = c * 128 + j * 32 + eg;
            float nev = __ldg(&g_ne[e]);
            float rse = __ldg(&g_rsne[e]);
            #pragma unroll
            for (int i = 0; i < 4; i++) {
                int r = rg * 4 + i;
                float dot = acc[i][j];
                float dist = -2.0f * dot + nzs[r] + nev;
                float sim = dot * rsnzs[r] * rse;
                dout[OFF_SIM + (size_t)(row0 + r) * NEMB + e] = sim;
                if (dist < bv[i]) { bv[i] = dist; bi[i] = e; }
            }
        }
    }

    #pragma unroll
    for (int i = 0; i < 4; i++) {
        float v = bv[i];
        int idx = bi[i];
        #pragma unroll
        for (int off = 16; off > 0; off >>= 1) {
            float ov = __shfl_down_sync(0xffffffffu, v, off);
            int oi = __shfl_down_sync(0xffffffffu, idx, off);
            if (ov < v || (ov == v && oi < idx)) { v = ov; idx = oi; }
        }
        if (eg == 0) {
            int r = rg * 4 + i;
            int gr = row0 + r;
            dout[OFF_IDS + gr] = (float)idx;
            float s = 0.f;
            const float* cp = cb + (size_t)idx * 64;
            float* qp = zq + (size_t)gr * 64;
            #pragma unroll 8
            for (int ci = 0; ci < 64; ci++) {
                float cvv = __ldg(cp + ci);
                qp[ci] = cvv;
                float d = zs[r * 65 + ci] - cvv;
                s += d * d;
            }
            atomicAdd(&g_loss, sqrtf(s));
        }
    }
}

// ---------------- host orchestration ----------------
#define SMEM_RES128 (64 * XS128 * 4)
#define SMEM_RES64  (64 * XS64 * 4)
#define SMEM_S2   ((ALIGN4(258 * 65) + 4096) * 4)
#define SMEM_TR   ((ALIGN4(130 * 65) + 16384) * 4)
#define SMEM_PROJ ((ALIGN4(258 * 65) + 192) * 4)

static inline void launch_res_pair(bool enc, int T,
    const float* w1, const float* b1, const float* w2, const float* b2,
    float* h, float* t)
{
    if (T >= 32768) {
        const int grid = NBATCH * (T >> 7);
        if (enc) {
            conv_res128_kernel<3, false><<<grid, 256, SMEM_RES128>>>(h, w1, b1, nullptr, t, T);
            conv_res128_kernel<1, true ><<<grid, 256, SMEM_RES128>>>(t, w2, b2, h, h, T);
        } else {
            conv_res128_kernel<1, false><<<grid, 256, SMEM_RES128>>>(h, w1, b1, nullptr, t, T);
            conv_res128_kernel<3, true ><<<grid, 256, SMEM_RES128>>>(t, w2, b2, h, h, T);
        }
    } else {
        const int grid = NBATCH * (T >> 6);
        if (enc) {
            conv_res64_kernel<3, false><<<grid, 256, SMEM_RES64>>>(h, w1, b1, nullptr, t, T);
            conv_res64_kernel<1, true ><<<grid, 256, SMEM_RES64>>>(t, w2, b2, h, h, T);
        } else {
            conv_res64_kernel<1, false><<<grid, 256, SMEM_RES64>>>(h, w1, b1, nullptr, t, T);
            conv_res64_kernel<3, true ><<<grid, 256, SMEM_RES64>>>(t, w2, b2, h, h, T);
        }
    }
}

extern "C" void kernel_launch(void* const* d_in, const int* in_sizes, int n_in,
                              void* d_out, int out_size)
{
    const float* x        = (const float*)d_in[0];
    const float* w_down0  = (const float*)d_in[1];
    const float* b_down0  = (const float*)d_in[2];
    const float* w_down   = (const float*)d_in[3];
    const float* b_down   = (const float*)d_in[4];
    const float* w_res_e  = (const float*)d_in[5];
    const float* b_res_e  = (const float*)d_in[6];
    const float* codebook = (const float*)d_in[7];
    const float* w_res_d  = (const float*)d_in[8];
    const float* b_res_d  = (const float*)d_in[9];
    const float* w_up     = (const float*)d_in[10];
    const float* b_up     = (const float*)d_in[11];
    const float* w_proj   = (const float*)d_in[12];
    const float* b_proj   = (const float*)d_in[13];
    float* out = (float*)d_out;

    float *A, *Bb;
    cudaGetSymbolAddress((void**)&A, g_A);
    cudaGetSymbolAddress((void**)&Bb, g_B);

    cudaFuncSetAttribute(conv_res128_kernel<3, false>, cudaFuncAttributeMaxDynamicSharedMemorySize, SMEM_RES128);
    cudaFuncSetAttribute(conv_res128_kernel<3, true >, cudaFuncAttributeMaxDynamicSharedMemorySize, SMEM_RES128);
    cudaFuncSetAttribute(conv_res128_kernel<1, false>, cudaFuncAttributeMaxDynamicSharedMemorySize, SMEM_RES128);
    cudaFuncSetAttribute(conv_res128_kernel<1, true >, cudaFuncAttributeMaxDynamicSharedMemorySize, SMEM_RES128);
    cudaFuncSetAttribute(conv_res64_kernel<3, false>, cudaFuncAttributeMaxDynamicSharedMemorySize, SMEM_RES64);
    cudaFuncSetAttribute(conv_res64_kernel<3, true >, cudaFuncAttributeMaxDynamicSharedMemorySize, SMEM_RES64);
    cudaFuncSetAttribute(conv_res64_kernel<1, false>, cudaFuncAttributeMaxDynamicSharedMemorySize, SMEM_RES64);
    cudaFuncSetAttribute(conv_res64_kernel<1, true >, cudaFuncAttributeMaxDynamicSharedMemorySize, SMEM_RES64);
    cudaFuncSetAttribute(conv_s2_kernel, cudaFuncAttributeMaxDynamicSharedMemorySize, SMEM_S2);
    cudaFuncSetAttribute(conv_tr_kernel, cudaFuncAttributeMaxDynamicSharedMemorySize, SMEM_TR);
    cudaFuncSetAttribute(proj_kernel,    cudaFuncAttributeMaxDynamicSharedMemorySize, SMEM_PROJ);

    zero_loss_kernel<<<1, 1>>>();
    ne_kernel<<<2, 256>>>(codebook);

    float* h = A;
    float* t = Bb;

    // ---------- encoder ----------
    down0_kernel<<<2048, 256>>>(x, w_down0, b_down0, h);
    int T = 32768;
    for (int blk = 0; blk < 3; blk++) {
        if (blk > 0) {
            int Tout = T >> 1;
            conv_s2_kernel<<<NBATCH * (Tout >> 7), 256, SMEM_S2>>>(
                h, w_down + (size_t)(blk - 1) * 16384, b_down + (blk - 1) * 64, t, Tout);
            T = Tout;
            float* tmp = h; h = t; t = tmp;
        }
        for (int r = 0; r < 4; r++) {
            const float* w1 = w_res_e + (size_t)((blk * 4 + r) * 2 + 0) * 12288;
            const float* w2 = w_res_e + (size_t)((blk * 4 + r) * 2 + 1) * 12288;
            const float* bb1 = b_res_e + ((blk * 4 + r) * 2 + 0) * 64;
            const float* bb2 = b_res_e + ((blk * 4 + r) * 2 + 1) * 64;
            launch_res_pair(true, T, w1, bb1, w2, bb2, h, t);
        }
    }

    // ---------- VQ (T = 8192) ----------
    vq_kernel<<<1024, 256>>>(h, codebook, t, out);
    loss_fin_kernel<<<1, 1>>>(out);
    { float* tmp = h; h = t; t = tmp; }   // h = z_q

    // ---------- decoder ----------
    for (int blk = 0; blk < 3; blk++) {
        for (int r = 0; r < 4; r++) {
            const float* w1 = w_res_d + (size_t)((blk * 4 + r) * 2 + 0) * 12288;
            const float* w2 = w_res_d + (size_t)((blk * 4 + r) * 2 + 1) * 12288;
            const float* bb1 = b_res_d + ((blk * 4 + r) * 2 + 0) * 64;
            const float* bb2 = b_res_d + ((blk * 4 + r) * 2 + 1) * 64;
            launch_res_pair(false, T, w1, bb1, w2, bb2, h, t);
        }
        int Tout = T << 1;
        conv_tr_kernel<<<NBATCH * (Tout >> 8), 256, SMEM_TR>>>(
            h, w_up + (size_t)blk * 16384, b_up + blk * 64, t, Tout);
        T = Tout;
        float* tmp = h; h = t; t = tmp;
    }

    // ---------- projection (T = 65536) ----------
    proj_kernel<<<NBATCH * (T >> 8), 256, SMEM_PROJ>>>(h, w_proj, b_proj, out, T);
}

// round 14
// speedup vs baseline: 1.5735x; 1.0066x over previous
#include <cuda_runtime.h>
#include <math.h>

// ---------------- constants ----------------
#define NBATCH 4
#define TTOP   65536
#define OFF_XHAT 0
#define OFF_LOSS 262144
#define OFF_IDS  262145
#define OFF_SIM  294913
#define NEMB 512

#define ALIGN4(n) (((n) + 3) & ~3)

// ---------------- scratch ----------------
__device__ float g_A[16777216];
__device__ float g_B[16777216];
__device__ float g_ne[NEMB];
__device__ float g_rsne[NEMB];
__device__ float g_loss;

__global__ void zero_loss_kernel() { g_loss = 0.f; }

__global__ void ne_kernel(const float* __restrict__ cb) {
    int e = blockIdx.x * blockDim.x + threadIdx.x;
    if (e < NEMB) {
        float s = 0.f;
        #pragma unroll 8
        for (int ci = 0; ci < 64; ci++) { float v = cb[e * 64 + ci]; s += v * v; }
        g_ne[e] = s;
        g_rsne[e] = rsqrtf(s);
    }
}

__global__ void loss_fin_kernel(float* __restrict__ out) {
    out[OFF_LOSS] = 1.25f * g_loss / 32768.0f;
}

// ---------------- first conv: Cin=1 -> 64, K=4, stride 2, ReLU ----------------
__global__ void __launch_bounds__(256) down0_kernel(
    const float* __restrict__ x, const float* __restrict__ w,
    const float* __restrict__ bias, float* __restrict__ y)
{
    __shared__ float ws[256];
    __shared__ float bs[64];
    int tid = threadIdx.x;
    ws[tid] = w[tid];
    if (tid < 64) bs[tid] = bias[tid];
    __syncthreads();

    int g = blockIdx.x * 256 + tid;
    int q = g & 3;
    int rest = g >> 2;
    int ot = rest & 32767;
    int b = rest >> 15;

    float acc[16];
    #pragma unroll
    for (int c = 0; c < 16; c++) acc[c] = bs[q * 16 + c];
    #pragma unroll
    for (int k = 0; k < 4; k++) {
        int t = 2 * ot - 1 + k;
        float xv = (t >= 0 && t < TTOP) ? x[(size_t)b * TTOP + t] : 0.f;
        #pragma unroll
        for (int c = 0; c < 16; c++) acc[c] += xv * ws[k * 64 + q * 16 + c];
    }
    float* op = y + ((size_t)(b * 32768 + ot)) * 64 + q * 16;
    #pragma unroll
    for (int c4 = 0; c4 < 4; c4++) {
        float4 o;
        o.x = fmaxf(acc[c4 * 4 + 0], 0.f);
        o.y = fmaxf(acc[c4 * 4 + 1], 0.f);
        o.z = fmaxf(acc[c4 * 4 + 2], 0.f);
        o.w = fmaxf(acc[c4 * 4 + 3], 0.f);
        *(float4*)(op + c4 * 4) = o;
    }
}

// ---------------- residual conv, 128-t tile (proven) -------------------------
#define XS128 164

template<int DIL, bool RES>
__global__ void __launch_bounds__(256, 3) conv_res128_kernel(
    const float* __restrict__ x, const float* __restrict__ w,
    const float* __restrict__ bias, const float* __restrict__ res,
    float* __restrict__ y, int T)
{
    constexpr int ROWS = 128 + 2 * DIL;
    constexpr int NQ = (ROWS + 3) >> 2;
    constexpr int W = 8 + 2 * DIL;
    constexpr int NV = (W + 3) >> 2;

    extern __shared__ float smem[];
    float* xsT = smem;   // [64][XS128]

    const int tid = threadIdx.x;
    const int tilesPerB = T >> 7;
    const int b = blockIdx.x / tilesPerB;
    const int t0 = (blockIdx.x - b * tilesPerB) << 7;
    const float* xb = x + (size_t)b * T * 64;

    for (int idx = tid; idx < 64 * NQ; idx += 256) {
        int ci = idx & 63;
        int rb = (idx >> 6) << 2;
        int gt = t0 - DIL + rb;
        float4 v;
        v.x = (gt + 0 >= 0 && gt + 0 < T) ? xb[(size_t)(gt + 0) * 64 + ci] : 0.f;
        v.y = (gt + 1 >= 0 && gt + 1 < T) ? xb[(size_t)(gt + 1) * 64 + ci] : 0.f;
        v.z = (gt + 2 >= 0 && gt + 2 < T) ? xb[(size_t)(gt + 2) * 64 + ci] : 0.f;
        v.w = (gt + 3 >= 0 && gt + 3 < T) ? xb[(size_t)(gt + 3) * 64 + ci] : 0.f;
        *(float4*)&xsT[ci * XS128 + rb] = v;
    }
    __syncthreads();

    const int tg = tid >> 4;
    const int cg = tid & 15;
    const int tb = tg << 3;
    const int co0 = cg << 2;

    float acc[8][4];
    #pragma unroll
    for (int i = 0; i < 8; i++)
        #pragma unroll
        for (int j = 0; j < 4; j++) acc[i][j] = 0.f;

    const float4* wp0 = (const float4*)(w + co0);
    const float4* wp1 = (const float4*)(w + 4096 + co0);
    const float4* wp2 = (const float4*)(w + 8192 + co0);
    const float* xrp = &xsT[tb];

    #pragma unroll 2
    for (int ci = 0; ci < 64; ci++) {
        const float4* xr = (const float4*)xrp;
        float xw[NV * 4];
        #pragma unroll
        for (int v = 0; v < NV; v++) {
            float4 c = xr[v];
            xw[v * 4 + 0] = c.x; xw[v * 4 + 1] = c.y;
            xw[v * 4 + 2] = c.z; xw[v * 4 + 3] = c.w;
        }

        float4 wa0 = __ldg(wp0);
        float4 wa1 = __ldg(wp1);
        float4 wa2 = __ldg(wp2);
        #pragma unroll
        for (int i = 0; i < 8; i++) {
            float x0 = xw[i];
            acc[i][0] += x0 * wa0.x; acc[i][1] += x0 * wa0.y;
            acc[i][2] += x0 * wa0.z; acc[i][3] += x0 * wa0.w;
            float x1 = xw[i + DIL];
            acc[i][0] += x1 * wa1.x; acc[i][1] += x1 * wa1.y;
            acc[i][2] += x1 * wa1.z; acc[i][3] += x1 * wa1.w;
            float x2 = xw[i + 2 * DIL];
            acc[i][0] += x2 * wa2.x; acc[i][1] += x2 * wa2.y;
            acc[i][2] += x2 * wa2.z; acc[i][3] += x2 * wa2.w;
        }
        wp0 += 16; wp1 += 16; wp2 += 16;
        xrp += XS128;
    }

    float4 bv = *(const float4*)(bias + co0);
    #pragma unroll
    for (int i = 0; i < 8; i++) {
        int gt = t0 + tb + i;
        float* op = y + ((size_t)b * T + gt) * 64 + co0;
        float4 o;
        o.x = fmaxf(acc[i][0] + bv.x, 0.f);
        o.y = fmaxf(acc[i][1] + bv.y, 0.f);
        o.z = fmaxf(acc[i][2] + bv.z, 0.f);
        o.w = fmaxf(acc[i][3] + bv.w, 0.f);
        if (RES) {
            float4 r0 = *(const float4*)(res + ((size_t)b * T + gt) * 64 + co0);
            o.x += r0.x; o.y += r0.y; o.z += r0.z; o.w += r0.w;
        }
        *(float4*)op = o;
    }
}

// ---------------- residual conv, 64-t tile (proven) --------------------------
#define XS64 76

template<int DIL, bool RES>
__global__ void __launch_bounds__(256, 4) conv_res64_kernel(
    const float* __restrict__ x, const float* __restrict__ w,
    const float* __restrict__ bias, const float* __restrict__ res,
    float* __restrict__ y, int T)
{
    constexpr int ROWS = 64 + 2 * DIL;
    constexpr int NQ = (ROWS + 3) >> 2;
    constexpr int W = 4 + 2 * DIL;
    constexpr int NV = (W + 3) >> 2;

    extern __shared__ float smem[];
    float* xsT = smem;   // [64][XS64]

    const int tid = threadIdx.x;
    const int tilesPerB = T >> 6;
    const int b = blockIdx.x / tilesPerB;
    const int t0 = (blockIdx.x - b * tilesPerB) << 6;
    const float* xb = x + (size_t)b * T * 64;

    for (int idx = tid; idx < 64 * NQ; idx += 256) {
        int ci = idx & 63;
        int rb = (idx >> 6) << 2;
        int gt = t0 - DIL + rb;
        float4 v;
        v.x = (gt + 0 >= 0 && gt + 0 < T) ? xb[(size_t)(gt + 0) * 64 + ci] : 0.f;
        v.y = (gt + 1 >= 0 && gt + 1 < T) ? xb[(size_t)(gt + 1) * 64 + ci] : 0.f;
        v.z = (gt + 2 >= 0 && gt + 2 < T) ? xb[(size_t)(gt + 2) * 64 + ci] : 0.f;
        v.w = (gt + 3 >= 0 && gt + 3 < T) ? xb[(size_t)(gt + 3) * 64 + ci] : 0.f;
        *(float4*)&xsT[ci * XS64 + rb] = v;
    }
    __syncthreads();

    const int tg = tid >> 4;
    const int cg = tid & 15;
    const int tb = tg << 2;
    const int co0 = cg << 2;

    float acc[4][4];
    #pragma unroll
    for (int i = 0; i < 4; i++)
        #pragma unroll
        for (int j = 0; j < 4; j++) acc[i][j] = 0.f;

    const float4* wp0 = (const float4*)(w + co0);
    const float4* wp1 = (const float4*)(w + 4096 + co0);
    const float4* wp2 = (const float4*)(w + 8192 + co0);
    const float* xrp = &xsT[tb];

    #pragma unroll 2
    for (int ci = 0; ci < 64; ci++) {
        const float4* xr = (const float4*)xrp;
        float xw[NV * 4];
        #pragma unroll
        for (int v = 0; v < NV; v++) {
            float4 c = xr[v];
            xw[v * 4 + 0] = c.x; xw[v * 4 + 1] = c.y;
            xw[v * 4 + 2] = c.z; xw[v * 4 + 3] = c.w;
        }

        float4 wa0 = __ldg(wp0);
        float4 wa1 = __ldg(wp1);
        float4 wa2 = __ldg(wp2);
        #pragma unroll
        for (int i = 0; i < 4; i++) {
            float x0 = xw[i];
            acc[i][0] += x0 * wa0.x; acc[i][1] += x0 * wa0.y;
            acc[i][2] += x0 * wa0.z; acc[i][3] += x0 * wa0.w;
            float x1 = xw[i + DIL];
            acc[i][0] += x1 * wa1.x; acc[i][1] += x1 * wa1.y;
            acc[i][2] += x1 * wa1.z; acc[i][3] += x1 * wa1.w;
            float x2 = xw[i + 2 * DIL];
            acc[i][0] += x2 * wa2.x; acc[i][1] += x2 * wa2.y;
            acc[i][2] += x2 * wa2.z; acc[i][3] += x2 * wa2.w;
        }
        wp0 += 16; wp1 += 16; wp2 += 16;
        xrp += XS64;
    }

    float4 bv = *(const float4*)(bias + co0);
    #pragma unroll
    for (int i = 0; i < 4; i++) {
        int gt = t0 + tb + i;
        float* op = y + ((size_t)b * T + gt) * 64 + co0;
        float4 o;
        o.x = fmaxf(acc[i][0] + bv.x, 0.f);
        o.y = fmaxf(acc[i][1] + bv.y, 0.f);
        o.z = fmaxf(acc[i][2] + bv.z, 0.f);
        o.w = fmaxf(acc[i][3] + bv.w, 0.f);
        if (RES) {
            float4 r0 = *(const float4*)(res + ((size_t)b * T + gt) * 64 + co0);
            o.x += r0.x; o.y += r0.y; o.z += r0.z; o.w += r0.w;
        }
        *(float4*)op = o;
    }
}

// ---------------- strided down conv: K=4, stride 2, 64->64, ReLU ----------------
__global__ void __launch_bounds__(256, 2) conv_s2_kernel(
    const float* __restrict__ x, const float* __restrict__ w,
    const float* __restrict__ bias, float* __restrict__ y, int Tout)
{
    extern __shared__ float smem[];
    float* xs = smem;                           // [258][65]
    float* wsm = smem + ALIGN4(258 * 65);       // [64][64]
    const int Tin = Tout << 1;
    const int tid = threadIdx.x;
    const int tilesPerB = Tout >> 7;
    const int b = blockIdx.x / tilesPerB;
    const int t0 = (blockIdx.x - b * tilesPerB) << 7;
    const float* xb = x + (size_t)b * Tin * 64;

    for (int idx = tid; idx < 258 * 16; idx += 256) {
        int r = idx >> 4, c4 = idx & 15;
        int gt = 2 * t0 - 1 + r;
        float4 v = make_float4(0.f, 0.f, 0.f, 0.f);
        if (gt >= 0 && gt < Tin) v = *(const float4*)(xb + (size_t)gt * 64 + c4 * 4);
        float* d = &xs[r * 65 + c4 * 4];
        d[0] = v.x; d[1] = v.y; d[2] = v.z; d[3] = v.w;
    }

    const int tg = tid >> 3;
    const int cg = tid & 7;
    float acc[4][8];
    #pragma unroll
    for (int i = 0; i < 4; i++)
        #pragma unroll
        for (int j = 0; j < 8; j++) acc[i][j] = 0.f;

    for (int k = 0; k < 4; k++) {
        __syncthreads();
        {
            const float4* wg = (const float4*)(w + k * 4096);
            float4* wd = (float4*)wsm;
            for (int idx = tid; idx < 1024; idx += 256) wd[idx] = wg[idx];
        }
        __syncthreads();
        const float4* ws4 = (const float4*)wsm;
        #pragma unroll 2
        for (int ci = 0; ci < 64; ci++) {
            float4 wa = ws4[ci * 16 + cg * 2];
            float4 wb = ws4[ci * 16 + cg * 2 + 1];
            #pragma unroll
            for (int i = 0; i < 4; i++) {
                float xv = xs[(2 * (tg * 4 + i) + k) * 65 + ci];
                acc[i][0] += xv * wa.x; acc[i][1] += xv * wa.y;
                acc[i][2] += xv * wa.z; acc[i][3] += xv * wa.w;
                acc[i][4] += xv * wb.x; acc[i][5] += xv * wb.y;
                acc[i][6] += xv * wb.z; acc[i][7] += xv * wb.w;
            }
        }
    }

    const int co0 = cg * 8;
    float4 bv0 = *(const float4*)(bias + co0);
    float4 bv1 = *(const float4*)(bias + co0 + 4);
    #pragma unroll
    for (int i = 0; i < 4; i++) {
        int gt = t0 + tg * 4 + i;
        float* op = y + ((size_t)b * Tout + gt) * 64 + co0;
        float4 o0, o1;
        o0.x = fmaxf(acc[i][0] + bv0.x, 0.f);
        o0.y = fmaxf(acc[i][1] + bv0.y, 0.f);
        o0.z = fmaxf(acc[i][2] + bv0.z, 0.f);
        o0.w = fmaxf(acc[i][3] + bv0.w, 0.f);
        o1.x = fmaxf(acc[i][4] + bv1.x, 0.f);
        o1.y = fmaxf(acc[i][5] + bv1.y, 0.f);
        o1.z = fmaxf(acc[i][6] + bv1.z, 0.f);
        o1.w = fmaxf(acc[i][7] + bv1.w, 0.f);
        *(float4*)op = o0;
        *(float4*)(op + 4) = o1;
    }
}

// ---------------- transposed conv, 128-out tile (Tout=65536) ----------------
// even o: w0*x[o/2-1] + w2*x[o/2] ; odd o: w1*x[(o-1)/2] + w3*x[(o+1)/2]
#define XT_S 68

__global__ void __launch_bounds__(256, 3) conv_tr128_kernel(
    const float* __restrict__ x, const float* __restrict__ w,
    const float* __restrict__ bias, float* __restrict__ y, int Tout)
{
    extern __shared__ float smem[];
    float* xsT = smem;   // [64][XT_S], rows 0..67 staged (17 quads)

    const int Tin = Tout >> 1;
    const int tid = threadIdx.x;
    const int tilesPerB = Tout >> 7;
    const int b = blockIdx.x / tilesPerB;
    const int t0 = (blockIdx.x - b * tilesPerB) << 7;
    const float* xb = x + (size_t)b * Tin * 64;
    const int in0 = (t0 >> 1) - 1;

    for (int idx = tid; idx < 64 * 17; idx += 256) {
        int ci = idx & 63;
        int rb = (idx >> 6) << 2;
        int gt = in0 + rb;
        float4 v;
        v.x = (gt + 0 >= 0 && gt + 0 < Tin) ? xb[(size_t)(gt + 0) * 64 + ci] : 0.f;
        v.y = (gt + 1 >= 0 && gt + 1 < Tin) ? xb[(size_t)(gt + 1) * 64 + ci] : 0.f;
        v.z = (gt + 2 >= 0 && gt + 2 < Tin) ? xb[(size_t)(gt + 2) * 64 + ci] : 0.f;
        v.w = (gt + 3 >= 0 && gt + 3 < Tin) ? xb[(size_t)(gt + 3) * 64 + ci] : 0.f;
        *(float4*)&xsT[ci * XT_S + rb] = v;
    }
    __syncthreads();

    const int tg = tid >> 4;        // 16 groups of 8 outputs
    const int cg = tid & 15;        // 16 co groups of 4
    const int tb = tg << 3;         // output base in tile
    const int ib = tg << 2;         // input window base (local), 16B-aligned
    const int co0 = cg << 2;

    float acc[8][4];
    #pragma unroll
    for (int i = 0; i < 8; i++)
        #pragma unroll
        for (int j = 0; j < 4; j++) acc[i][j] = 0.f;

    const float4* wp0 = (const float4*)(w + co0);
    const float4* wp1 = (const float4*)(w + 4096 + co0);
    const float4* wp2 = (const float4*)(w + 8192 + co0);
    const float4* wp3 = (const float4*)(w + 12288 + co0);
    const float* xrp = &xsT[ib];

    #pragma unroll 2
    for (int ci = 0; ci < 64; ci++) {
        const float4* xr = (const float4*)xrp;
        float4 c0 = xr[0];
        float4 c1 = xr[1];
        float xw[8];
        xw[0] = c0.x; xw[1] = c0.y; xw[2] = c0.z; xw[3] = c0.w;
        xw[4] = c1.x; xw[5] = c1.y; xw[6] = c1.z; xw[7] = c1.w;

        float4 w0 = __ldg(wp0);
        float4 w1 = __ldg(wp1);
        float4 w2 = __ldg(wp2);
        float4 w3 = __ldg(wp3);
        #pragma unroll
        for (int ii = 0; ii < 4; ii++) {
            const int e = 2 * ii, o = 2 * ii + 1;
            // even output gt=t0+tb+2ii: x[gt/2-1]=xw[ii], x[gt/2]=xw[ii+1]
            float xe0 = xw[ii], xe1 = xw[ii + 1];
            acc[e][0] += xe0 * w0.x + xe1 * w2.x;
            acc[e][1] += xe0 * w0.y + xe1 * w2.y;
            acc[e][2] += xe0 * w0.z + xe1 * w2.z;
            acc[e][3] += xe0 * w0.w + xe1 * w2.w;
            // odd output: x[(o-1)/2]=xw[ii+1], x[(o+1)/2]=xw[ii+2]
            float xo0 = xw[ii + 1], xo1 = xw[ii + 2];
            acc[o][0] += xo0 * w1.x + xo1 * w3.x;
            acc[o][1] += xo0 * w1.y + xo1 * w3.y;
            acc[o][2] += xo0 * w1.z + xo1 * w3.z;
            acc[o][3] += xo0 * w1.w + xo1 * w3.w;
        }
        wp0 += 16; wp1 += 16; wp2 += 16; wp3 += 16;
        xrp += XT_S;
    }

    float4 bv = *(const float4*)(bias + co0);
    #pragma unroll
    for (int i = 0; i < 8; i++) {
        int gt = t0 + tb + i;
        float* op = y + ((size_t)b * Tout + gt) * 64 + co0;
        float4 o;
        o.x = fmaxf(acc[i][0] + bv.x, 0.f);
        o.y = fmaxf(acc[i][1] + bv.y, 0.f);
        o.z = fmaxf(acc[i][2] + bv.z, 0.f);
        o.w = fmaxf(acc[i][3] + bv.w, 0.f);
        *(float4*)op = o;
    }
}

// ---------------- transposed conv (old, Tout<=32768) ------------------------
__global__ void __launch_bounds__(256, 2) conv_tr_kernel(
    const float* __restrict__ x, const float* __restrict__ w,
    const float* __restrict__ bias, float* __restrict__ y, int Tout)
{
    extern __shared__ float smem[];
    float* xs = smem;                           // [130][65]
    float* wsm = smem + ALIGN4(130 * 65);       // [4][64][64]
    const int Tin = Tout >> 1;
    const int tid = threadIdx.x;
    const int tilesPerB = Tout >> 8;
    const int b = blockIdx.x / tilesPerB;
    const int t0 = (blockIdx.x - b * tilesPerB) << 8;
    const float* xb = x + (size_t)b * Tin * 64;
    const int in0 = (t0 >> 1) - 1;

    for (int idx = tid; idx < 130 * 16; idx += 256) {
        int r = idx >> 4, c4 = idx & 15;
        int gt = in0 + r;
        float4 v = make_float4(0.f, 0.f, 0.f, 0.f);
        if (gt >= 0 && gt < Tin) v = *(const float4*)(xb + (size_t)gt * 64 + c4 * 4);
        float* d = &xs[r * 65 + c4 * 4];
        d[0] = v.x; d[1] = v.y; d[2] = v.z; d[3] = v.w;
    }
    {
        const float4* wg = (const float4*)w;
        float4* wd = (float4*)wsm;
        for (int idx = tid; idx < 4096; idx += 256) wd[idx] = wg[idx];
    }
    __syncthreads();

    const int tg = tid >> 3;
    const int cg = tid & 7;
    float acc[8][8];
    #pragma unroll
    for (int i = 0; i < 8; i++)
        #pragma unroll
        for (int j = 0; j < 8; j++) acc[i][j] = 0.f;

    const float4* ws4 = (const float4*)wsm;
    #pragma unroll 2
    for (int ci = 0; ci < 64; ci++) {
        float xv[6];
        #pragma unroll
        for (int m = 0; m < 6; m++) xv[m] = xs[(tg * 4 + m) * 65 + ci];
        {
            float4 wa0 = ws4[ci * 16 + cg * 2];
            float4 wb0 = ws4[ci * 16 + cg * 2 + 1];
            float4 wa2 = ws4[2 * 1024 + ci * 16 + cg * 2];
            float4 wb2 = ws4[2 * 1024 + ci * 16 + cg * 2 + 1];
            #pragma unroll
            for (int ii = 0; ii < 4; ii++) {
                const int i = 2 * ii;
                float xa = xv[ii], xbv = xv[ii + 1];
                acc[i][0] += xa * wa0.x + xbv * wa2.x;
                acc[i][1] += xa * wa0.y + xbv * wa2.y;
                acc[i][2] += xa * wa0.z + xbv * wa2.z;
                acc[i][3] += xa * wa0.w + xbv * wa2.w;
                acc[i][4] += xa * wb0.x + xbv * wb2.x;
                acc[i][5] += xa * wb0.y + xbv * wb2.y;
                acc[i][6] += xa * wb0.z + xbv * wb2.z;
                acc[i][7] += xa * wb0.w + xbv * wb2.w;
            }
        }
        {
            float4 wa1 = ws4[1024 + ci * 16 + cg * 2];
            float4 wb1 = ws4[1024 + ci * 16 + cg * 2 + 1];
            float4 wa3 = ws4[3 * 1024 + ci * 16 + cg * 2];
            float4 wb3 = ws4[3 * 1024 + ci * 16 + cg * 2 + 1];
            #pragma unroll
            for (int ii = 0; ii < 4; ii++) {
                const int i = 2 * ii + 1;
                float xa = xv[ii + 1], xbv = xv[ii + 2];
                acc[i][0] += xa * wa1.x + xbv * wa3.x;
                acc[i][1] += xa * wa1.y + xbv * wa3.y;
                acc[i][2] += xa * wa1.z + xbv * wa3.z;
                acc[i][3] += xa * wa1.w + xbv * wa3.w;
                acc[i][4] += xa * wb1.x + xbv * wb3.x;
                acc[i][5] += xa * wb1.y + xbv * wb3.y;
                acc[i][6] += xa * wb1.z + xbv * wb3.z;
                acc[i][7] += xa * wb1.w + xbv * wb3.w;
            }
        }
    }

    const int co0 = cg * 8;
    float4 bv0 = *(const float4*)(bias + co0);
    float4 bv1 = *(const float4*)(bias + co0 + 4);
    #pragma unroll
    for (int i = 0; i < 8; i++) {
        int gt = t0 + tg * 8 + i;
        float* op = y + ((size_t)b * Tout + gt) * 64 + co0;
        float4 o0, o1;
        o0.x = fmaxf(acc[i][0] + bv0.x, 0.f);
        o0.y = fmaxf(acc[i][1] + bv0.y, 0.f);
        o0.z = fmaxf(acc[i][2] + bv0.z, 0.f);
        o0.w = fmaxf(acc[i][3] + bv0.w, 0.f);
        o1.x = fmaxf(acc[i][4] + bv1.x, 0.f);
        o1.y = fmaxf(acc[i][5] + bv1.y, 0.f);
        o1.z = fmaxf(acc[i][6] + bv1.z, 0.f);
        o1.w = fmaxf(acc[i][7] + bv1.w, 0.f);
        *(float4*)op = o0;
        *(float4*)(op + 4) = o1;
    }
}

// ---------------- final projection: K=3, dil 1, 64->1, linear ----------------
__global__ void __launch_bounds__(256) proj_kernel(
    const float* __restrict__ x, const float* __restrict__ w,
    const float* __restrict__ bias, float* __restrict__ out, int T)
{
    extern __shared__ float smem[];
    float* xs = smem;                           // [258][65]
    float* ws = smem + ALIGN4(258 * 65);        // [192]
    const int tid = threadIdx.x;
    const int tilesPerB = T >> 8;
    const int b = blockIdx.x / tilesPerB;
    const int t0 = (blockIdx.x - b * tilesPerB) << 8;
    const float* xb = x + (size_t)b * T * 64;

    for (int idx = tid; idx < 258 * 16; idx += 256) {
        int r = idx >> 4, c4 = idx & 15;
        int gt = t0 - 1 + r;
        float4 v = make_float4(0.f, 0.f, 0.f, 0.f);
        if (gt >= 0 && gt < T) v = *(const float4*)(xb + (size_t)gt * 64 + c4 * 4);
        float* d = &xs[r * 65 + c4 * 4];
        d[0] = v.x; d[1] = v.y; d[2] = v.z; d[3] = v.w;
    }
    if (tid < 192) ws[tid] = w[tid];
    __syncthreads();

    float acc = 0.f;
    #pragma unroll
    for (int k = 0; k < 3; k++) {
        #pragma unroll 8
        for (int ci = 0; ci < 64; ci++)
            acc += xs[(tid + k) * 65 + ci] * ws[k * 64 + ci];
    }
    out[OFF_XHAT + (size_t)b * T + t0 + tid] = acc + bias[0];
}

// ---------------- VQ ----------------
__global__ void __launch_bounds__(256) vq_kernel(
    const float* __restrict__ ze, const float* __restrict__ cb,
    float* __restrict__ zq, float* __restrict__ dout)
{
    __shared__ float zs[32 * 65];
    __shared__ float cbs[128 * 65];
    __shared__ float nzs[32], rsnzs[32];

    const int tid = threadIdx.x;
    const int rg = tid >> 5;
    const int eg = tid & 31;
    const int row0 = blockIdx.x * 32;

    for (int idx = tid; idx < 32 * 16; idx += 256) {
        int r = idx >> 4, c4 = idx & 15;
        float4 v = *(const float4*)(ze + (size_t)(row0 + r) * 64 + c4 * 4);
        float* d = &zs[r * 65 + c4 * 4];
        d[0] = v.x; d[1] = v.y; d[2] = v.z; d[3] = v.w;
    }
    __syncthreads();
    if (tid < 32) {
        float s = 0.f;
        #pragma unroll 8
        for (int ci = 0; ci < 64; ci++) { float v = zs[tid * 65 + ci]; s += v * v; }
        nzs[tid] = s;
        rsnzs[tid] = rsqrtf(s);
    }

    float bv[4] = {3.4e38f, 3.4e38f, 3.4e38f, 3.4e38f};
    int bi[4] = {0, 0, 0, 0};

    for (int c = 0; c < 4; c++) {
        __syncthreads();
        for (int idx = tid; idx < 128 * 16; idx += 256) {
            int e = idx >> 4, c4 = idx & 15;
            float4 v = *(const float4*)(cb + (size_t)(c * 128 + e) * 64 + c4 * 4);
            float* d = &cbs[e * 65 + c4 * 4];
            d[0] = v.x; d[1] = v.y; d[2] = v.z; d[3] = v.w;
        }
        __syncthreads();

        float acc[4][4];
        #pragma unroll
        for (int i = 0; i < 4; i++)
            #pragma unroll
            for (int j = 0; j < 4; j++) acc[i][j] = 0.f;

        #pragma unroll 4
        for (int ci = 0; ci < 64; ci++) {
            float zv[4], cv[4];
            #pragma unroll
            for (int i = 0; i < 4; i++) zv[i] = zs[(rg * 4 + i) * 65 + ci];
            #pragma unroll
            for (int j = 0; j < 4; j++) cv[j] = cbs[(j * 32 + eg) * 65 + ci];
            #pragma unroll
            for (int i = 0; i < 4; i++)
                #pragma unroll
                for (int j = 0; j < 4; j++) acc[i][j] += zv[i] * cv[j];
        }

        #pragma unroll
        for (int j = 0; j < 4; j++) {
            int e = c * 128 + j * 32 + eg;
            float nev = __ldg(&g_ne[e]);
            float rse = __ldg(&g_rsne[e]);
            #pragma unroll
            for (int i = 0; i < 4; i++) {
                int r = rg * 4 + i;
                float dot = acc[i][j];
                float dist = -2.0f * dot + nzs[r] + nev;
                float sim = dot * rsnzs[r] * rse;
                dout[OFF_SIM + (size_t)(row0 + r) * NEMB + e] = sim;
                if (dist < bv[i]) { bv[i] = dist; bi[i] = e; }
            }
        }
    }

    #pragma unroll
    for (int i = 0; i < 4; i++) {
        float v = bv[i];
        int idx = bi[i];
        #pragma unroll
        for (int off = 16; off > 0; off >>= 1) {
            float ov = __shfl_down_sync(0xffffffffu, v, off);
            int oi = __shfl_down_sync(0xffffffffu, idx, off);
            if (ov < v || (ov == v && oi < idx)) { v = ov; idx = oi; }
        }
        if (eg == 0) {
            int r = rg * 4 + i;
            int gr = row0 + r;
            dout[OFF_IDS + gr] = (float)idx;
            float s = 0.f;
            const float* cp = cb + (size_t)idx * 64;
            float* qp = zq + (size_t)gr * 64;
            #pragma unroll 8
            for (int ci = 0; ci < 64; ci++) {
                float cvv = __ldg(cp + ci);
                qp[ci] = cvv;
                float d = zs[r * 65 + ci] - cvv;
                s += d * d;
            }
            atomicAdd(&g_loss, sqrtf(s));
        }
    }
}

// ---------------- host orchestration ----------------
#define SMEM_RES128 (64 * XS128 * 4)
#define SMEM_RES64  (64 * XS64 * 4)
#define SMEM_TR128  (64 * XT_S * 4)
#define SMEM_S2   ((ALIGN4(258 * 65) + 4096) * 4)
#define SMEM_TR   ((ALIGN4(130 * 65) + 16384) * 4)
#define SMEM_PROJ ((ALIGN4(258 * 65) + 192) * 4)

static inline void launch_res_pair(bool enc, int T,
    const float* w1, const float* b1, const float* w2, const float* b2,
    float* h, float* t)
{
    if (T >= 32768) {
        const int grid = NBATCH * (T >> 7);
        if (enc) {
            conv_res128_kernel<3, false><<<grid, 256, SMEM_RES128>>>(h, w1, b1, nullptr, t, T);
            conv_res128_kernel<1, true ><<<grid, 256, SMEM_RES128>>>(t, w2, b2, h, h, T);
        } else {
            conv_res128_kernel<1, false><<<grid, 256, SMEM_RES128>>>(h, w1, b1, nullptr, t, T);
            conv_res128_kernel<3, true ><<<grid, 256, SMEM_RES128>>>(t, w2, b2, h, h, T);
        }
    } else {
        const int grid = NBATCH * (T >> 6);
        if (enc) {
            conv_res64_kernel<3, false><<<grid, 256, SMEM_RES64>>>(h, w1, b1, nullptr, t, T);
            conv_res64_kernel<1, true ><<<grid, 256, SMEM_RES64>>>(t, w2, b2, h, h, T);
        } else {
            conv_res64_kernel<1, false><<<grid, 256, SMEM_RES64>>>(h, w1, b1, nullptr, t, T);
            conv_res64_kernel<3, true ><<<grid, 256, SMEM_RES64>>>(t, w2, b2, h, h, T);
        }
    }
}

extern "C" void kernel_launch(void* const* d_in, const int* in_sizes, int n_in,
                              void* d_out, int out_size)
{
    const float* x        = (const float*)d_in[0];
    const float* w_down0  = (const float*)d_in[1];
    const float* b_down0  = (const float*)d_in[2];
    const float* w_down   = (const float*)d_in[3];
    const float* b_down   = (const float*)d_in[4];
    const float* w_res_e  = (const float*)d_in[5];
    const float* b_res_e  = (const float*)d_in[6];
    const float* codebook = (const float*)d_in[7];
    const float* w_res_d  = (const float*)d_in[8];
    const float* b_res_d  = (const float*)d_in[9];
    const float* w_up     = (const float*)d_in[10];
    const float* b_up     = (const float*)d_in[11];
    const float* w_proj   = (const float*)d_in[12];
    const float* b_proj   = (const float*)d_in[13];
    float* out = (float*)d_out;

    float *A, *Bb;
    cudaGetSymbolAddress((void**)&A, g_A);
    cudaGetSymbolAddress((void**)&Bb, g_B);

    cudaFuncSetAttribute(conv_res128_kernel<3, false>, cudaFuncAttributeMaxDynamicSharedMemorySize, SMEM_RES128);
    cudaFuncSetAttribute(conv_res128_kernel<3, true >, cudaFuncAttributeMaxDynamicSharedMemorySize, SMEM_RES128);
    cudaFuncSetAttribute(conv_res128_kernel<1, false>, cudaFuncAttributeMaxDynamicSharedMemorySize, SMEM_RES128);
    cudaFuncSetAttribute(conv_res128_kernel<1, true >, cudaFuncAttributeMaxDynamicSharedMemorySize, SMEM_RES128);
    cudaFuncSetAttribute(conv_res64_kernel<3, false>, cudaFuncAttributeMaxDynamicSharedMemorySize, SMEM_RES64);
    cudaFuncSetAttribute(conv_res64_kernel<3, true >, cudaFuncAttributeMaxDynamicSharedMemorySize, SMEM_RES64);
    cudaFuncSetAttribute(conv_res64_kernel<1, false>, cudaFuncAttributeMaxDynamicSharedMemorySize, SMEM_RES64);
    cudaFuncSetAttribute(conv_res64_kernel<1, true >, cudaFuncAttributeMaxDynamicSharedMemorySize, SMEM_RES64);
    cudaFuncSetAttribute(conv_tr128_kernel, cudaFuncAttributeMaxDynamicSharedMemorySize, SMEM_TR128);
    cudaFuncSetAttribute(conv_s2_kernel, cudaFuncAttributeMaxDynamicSharedMemorySize, SMEM_S2);
    cudaFuncSetAttribute(conv_tr_kernel, cudaFuncAttributeMaxDynamicSharedMemorySize, SMEM_TR);
    cudaFuncSetAttribute(proj_kernel,    cudaFuncAttributeMaxDynamicSharedMemorySize, SMEM_PROJ);

    zero_loss_kernel<<<1, 1>>>();
    ne_kernel<<<2, 256>>>(codebook);

    float* h = A;
    float* t = Bb;

    // ---------- encoder ----------
    down0_kernel<<<2048, 256>>>(x, w_down0, b_down0, h);
    int T = 32768;
    for (int blk = 0; blk < 3; blk++) {
        if (blk > 0) {
            int Tout = T >> 1;
            conv_s2_kernel<<<NBATCH * (Tout >> 7), 256, SMEM_S2>>>(
                h, w_down + (size_t)(blk - 1) * 16384, b_down + (blk - 1) * 64, t, Tout);
            T = Tout;
            float* tmp = h; h = t; t = tmp;
        }
        for (int r = 0; r < 4; r++) {
            const float* w1 = w_res_e + (size_t)((blk * 4 + r) * 2 + 0) * 12288;
            const float* w2 = w_res_e + (size_t)((blk * 4 + r) * 2 + 1) * 12288;
            const float* bb1 = b_res_e + ((blk * 4 + r) * 2 + 0) * 64;
            const float* bb2 = b_res_e + ((blk * 4 + r) * 2 + 1) * 64;
            launch_res_pair(true, T, w1, bb1, w2, bb2, h, t);
        }
    }

    // ---------- VQ (T = 8192) ----------
    vq_kernel<<<1024, 256>>>(h, codebook, t, out);
    loss_fin_kernel<<<1, 1>>>(out);
    { float* tmp = h; h = t; t = tmp; }   // h = z_q

    // ---------- decoder ----------
    for (int blk = 0; blk < 3; blk++) {
        for (int r = 0; r < 4; r++) {
            const float* w1 = w_res_d + (size_t)((blk * 4 + r) * 2 + 0) * 12288;
            const float* w2 = w_res_d + (size_t)((blk * 4 + r) * 2 + 1) * 12288;
            const float* bb1 = b_res_d + ((blk * 4 + r) * 2 + 0) * 64;
            const float* bb2 = b_res_d + ((blk * 4 + r) * 2 + 1) * 64;
            launch_res_pair(false, T, w1, bb1, w2, bb2, h, t);
        }
        int Tout = T << 1;
        if (Tout >= 65536) {
            conv_tr128_kernel<<<NBATCH * (Tout >> 7), 256, SMEM_TR128>>>(
                h, w_up + (size_t)blk * 16384, b_up + blk * 64, t, Tout);
        } else {
            conv_tr_kernel<<<NBATCH * (Tout >> 8), 256, SMEM_TR>>>(
                h, w_up + (size_t)blk * 16384, b_up + blk * 64, t, Tout);
        }
        T = Tout;
        float* tmp = h; h = t; t = tmp;
    }

    // ---------- projection (T = 65536) ----------
    proj_kernel<<<NBATCH * (T >> 8), 256, SMEM_PROJ>>>(h, w_proj, b_proj, out, T);
}

// round 15
// speedup vs baseline: 1.5796x; 1.0039x over previous
#include <cuda_runtime.h>
#include <math.h>

// ---------------- constants ----------------
#define NBATCH 4
#define TTOP   65536
#define OFF_XHAT 0
#define OFF_LOSS 262144
#define OFF_IDS  262145
#define OFF_SIM  294913
#define NEMB 512

#define ALIGN4(n) (((n) + 3) & ~3)

// ---------------- scratch ----------------
__device__ float g_A[16777216];
__device__ float g_B[16777216];
__device__ float g_ne[NEMB];
__device__ float g_rsne[NEMB];
__device__ float g_loss;

__global__ void zero_loss_kernel() { g_loss = 0.f; }

__global__ void ne_kernel(const float* __restrict__ cb) {
    int e = blockIdx.x * blockDim.x + threadIdx.x;
    if (e < NEMB) {
        float s = 0.f;
        #pragma unroll 8
        for (int ci = 0; ci < 64; ci++) { float v = cb[e * 64 + ci]; s += v * v; }
        g_ne[e] = s;
        g_rsne[e] = rsqrtf(s);
    }
}

__global__ void loss_fin_kernel(float* __restrict__ out) {
    out[OFF_LOSS] = 1.25f * g_loss / 32768.0f;
}

// ---------------- first conv: Cin=1 -> 64, K=4, stride 2, ReLU ----------------
__global__ void __launch_bounds__(256) down0_kernel(
    const float* __restrict__ x, const float* __restrict__ w,
    const float* __restrict__ bias, float* __restrict__ y)
{
    __shared__ float ws[256];
    __shared__ float bs[64];
    int tid = threadIdx.x;
    ws[tid] = w[tid];
    if (tid < 64) bs[tid] = bias[tid];
    __syncthreads();

    int g = blockIdx.x * 256 + tid;
    int q = g & 3;
    int rest = g >> 2;
    int ot = rest & 32767;
    int b = rest >> 15;

    float acc[16];
    #pragma unroll
    for (int c = 0; c < 16; c++) acc[c] = bs[q * 16 + c];
    #pragma unroll
    for (int k = 0; k < 4; k++) {
        int t = 2 * ot - 1 + k;
        float xv = (t >= 0 && t < TTOP) ? x[(size_t)b * TTOP + t] : 0.f;
        #pragma unroll
        for (int c = 0; c < 16; c++) acc[c] += xv * ws[k * 64 + q * 16 + c];
    }
    float* op = y + ((size_t)(b * 32768 + ot)) * 64 + q * 16;
    #pragma unroll
    for (int c4 = 0; c4 < 4; c4++) {
        float4 o;
        o.x = fmaxf(acc[c4 * 4 + 0], 0.f);
        o.y = fmaxf(acc[c4 * 4 + 1], 0.f);
        o.z = fmaxf(acc[c4 * 4 + 2], 0.f);
        o.w = fmaxf(acc[c4 * 4 + 3], 0.f);
        *(float4*)(op + c4 * 4) = o;
    }
}

// ---------------- residual conv, 128-t tile (proven) -------------------------
#define XS128 164

template<int DIL, bool RES>
__global__ void __launch_bounds__(256, 3) conv_res128_kernel(
    const float* __restrict__ x, const float* __restrict__ w,
    const float* __restrict__ bias, const float* __restrict__ res,
    float* __restrict__ y, int T)
{
    constexpr int ROWS = 128 + 2 * DIL;
    constexpr int NQ = (ROWS + 3) >> 2;
    constexpr int W = 8 + 2 * DIL;
    constexpr int NV = (W + 3) >> 2;

    extern __shared__ float smem[];
    float* xsT = smem;   // [64][XS128]

    const int tid = threadIdx.x;
    const int tilesPerB = T >> 7;
    const int b = blockIdx.x / tilesPerB;
    const int t0 = (blockIdx.x - b * tilesPerB) << 7;
    const float* xb = x + (size_t)b * T * 64;

    for (int idx = tid; idx < 64 * NQ; idx += 256) {
        int ci = idx & 63;
        int rb = (idx >> 6) << 2;
        int gt = t0 - DIL + rb;
        float4 v;
        v.x = (gt + 0 >= 0 && gt + 0 < T) ? xb[(size_t)(gt + 0) * 64 + ci] : 0.f;
        v.y = (gt + 1 >= 0 && gt + 1 < T) ? xb[(size_t)(gt + 1) * 64 + ci] : 0.f;
        v.z = (gt + 2 >= 0 && gt + 2 < T) ? xb[(size_t)(gt + 2) * 64 + ci] : 0.f;
        v.w = (gt + 3 >= 0 && gt + 3 < T) ? xb[(size_t)(gt + 3) * 64 + ci] : 0.f;
        *(float4*)&xsT[ci * XS128 + rb] = v;
    }
    __syncthreads();

    const int tg = tid >> 4;
    const int cg = tid & 15;
    const int tb = tg << 3;
    const int co0 = cg << 2;

    float acc[8][4];
    #pragma unroll
    for (int i = 0; i < 8; i++)
        #pragma unroll
        for (int j = 0; j < 4; j++) acc[i][j] = 0.f;

    const float4* wp = (const float4*)(w + co0);   // taps at +0, +1024, +2048 (float4)
    const float* xrp = &xsT[tb];

    #pragma unroll 2
    for (int ci = 0; ci < 64; ci++) {
        const float4* xr = (const float4*)xrp;
        float xw[NV * 4];
        #pragma unroll
        for (int v = 0; v < NV; v++) {
            float4 c = xr[v];
            xw[v * 4 + 0] = c.x; xw[v * 4 + 1] = c.y;
            xw[v * 4 + 2] = c.z; xw[v * 4 + 3] = c.w;
        }

        float4 wa0 = __ldg(wp);
        float4 wa1 = __ldg(wp + 1024);
        float4 wa2 = __ldg(wp + 2048);
        #pragma unroll
        for (int i = 0; i < 8; i++) {
            float x0 = xw[i];
            acc[i][0] += x0 * wa0.x; acc[i][1] += x0 * wa0.y;
            acc[i][2] += x0 * wa0.z; acc[i][3] += x0 * wa0.w;
            float x1 = xw[i + DIL];
            acc[i][0] += x1 * wa1.x; acc[i][1] += x1 * wa1.y;
            acc[i][2] += x1 * wa1.z; acc[i][3] += x1 * wa1.w;
            float x2 = xw[i + 2 * DIL];
            acc[i][0] += x2 * wa2.x; acc[i][1] += x2 * wa2.y;
            acc[i][2] += x2 * wa2.z; acc[i][3] += x2 * wa2.w;
        }
        wp += 16;
        xrp += XS128;
    }

    float4 bv = *(const float4*)(bias + co0);
    #pragma unroll
    for (int i = 0; i < 8; i++) {
        int gt = t0 + tb + i;
        float* op = y + ((size_t)b * T + gt) * 64 + co0;
        float4 o;
        o.x = fmaxf(acc[i][0] + bv.x, 0.f);
        o.y = fmaxf(acc[i][1] + bv.y, 0.f);
        o.z = fmaxf(acc[i][2] + bv.z, 0.f);
        o.w = fmaxf(acc[i][3] + bv.w, 0.f);
        if (RES) {
            float4 r0 = *(const float4*)(res + ((size_t)b * T + gt) * 64 + co0);
            o.x += r0.x; o.y += r0.y; o.z += r0.z; o.w += r0.w;
        }
        *(float4*)op = o;
    }
}

// ---------------- residual conv, 64-t tile (proven) --------------------------
#define XS64 76

template<int DIL, bool RES>
__global__ void __launch_bounds__(256, 4) conv_res64_kernel(
    const float* __restrict__ x, const float* __restrict__ w,
    const float* __restrict__ bias, const float* __restrict__ res,
    float* __restrict__ y, int T)
{
    constexpr int ROWS = 64 + 2 * DIL;
    constexpr int NQ = (ROWS + 3) >> 2;
    constexpr int W = 4 + 2 * DIL;
    constexpr int NV = (W + 3) >> 2;

    extern __shared__ float smem[];
    float* xsT = smem;   // [64][XS64]

    const int tid = threadIdx.x;
    const int tilesPerB = T >> 6;
    const int b = blockIdx.x / tilesPerB;
    const int t0 = (blockIdx.x - b * tilesPerB) << 6;
    const float* xb = x + (size_t)b * T * 64;

    for (int idx = tid; idx < 64 * NQ; idx += 256) {
        int ci = idx & 63;
        int rb = (idx >> 6) << 2;
        int gt = t0 - DIL + rb;
        float4 v;
        v.x = (gt + 0 >= 0 && gt + 0 < T) ? xb[(size_t)(gt + 0) * 64 + ci] : 0.f;
        v.y = (gt + 1 >= 0 && gt + 1 < T) ? xb[(size_t)(gt + 1) * 64 + ci] : 0.f;
        v.z = (gt + 2 >= 0 && gt + 2 < T) ? xb[(size_t)(gt + 2) * 64 + ci] : 0.f;
        v.w = (gt + 3 >= 0 && gt + 3 < T) ? xb[(size_t)(gt + 3) * 64 + ci] : 0.f;
        *(float4*)&xsT[ci * XS64 + rb] = v;
    }
    __syncthreads();

    const int tg = tid >> 4;
    const int cg = tid & 15;
    const int tb = tg << 2;
    const int co0 = cg << 2;

    float acc[4][4];
    #pragma unroll
    for (int i = 0; i < 4; i++)
        #pragma unroll
        for (int j = 0; j < 4; j++) acc[i][j] = 0.f;

    const float4* wp = (const float4*)(w + co0);
    const float* xrp = &xsT[tb];

    #pragma unroll 2
    for (int ci = 0; ci < 64; ci++) {
        const float4* xr = (const float4*)xrp;
        float xw[NV * 4];
        #pragma unroll
        for (int v = 0; v < NV; v++) {
            float4 c = xr[v];
            xw[v * 4 + 0] = c.x; xw[v * 4 + 1] = c.y;
            xw[v * 4 + 2] = c.z; xw[v * 4 + 3] = c.w;
        }

        float4 wa0 = __ldg(wp);
        float4 wa1 = __ldg(wp + 1024);
        float4 wa2 = __ldg(wp + 2048);
        #pragma unroll
        for (int i = 0; i < 4; i++) {
            float x0 = xw[i];
            acc[i][0] += x0 * wa0.x; acc[i][1] += x0 * wa0.y;
            acc[i][2] += x0 * wa0.z; acc[i][3] += x0 * wa0.w;
            float x1 = xw[i + DIL];
            acc[i][0] += x1 * wa1.x; acc[i][1] += x1 * wa1.y;
            acc[i][2] += x1 * wa1.z; acc[i][3] += x1 * wa1.w;
            float x2 = xw[i + 2 * DIL];
            acc[i][0] += x2 * wa2.x; acc[i][1] += x2 * wa2.y;
            acc[i][2] += x2 * wa2.z; acc[i][3] += x2 * wa2.w;
        }
        wp += 16;
        xrp += XS64;
    }

    float4 bv = *(const float4*)(bias + co0);
    #pragma unroll
    for (int i = 0; i < 4; i++) {
        int gt = t0 + tb + i;
        float* op = y + ((size_t)b * T + gt) * 64 + co0;
        float4 o;
        o.x = fmaxf(acc[i][0] + bv.x, 0.f);
        o.y = fmaxf(acc[i][1] + bv.y, 0.f);
        o.z = fmaxf(acc[i][2] + bv.z, 0.f);
        o.w = fmaxf(acc[i][3] + bv.w, 0.f);
        if (RES) {
            float4 r0 = *(const float4*)(res + ((size_t)b * T + gt) * 64 + co0);
            o.x += r0.x; o.y += r0.y; o.z += r0.z; o.w += r0.w;
        }
        *(float4*)op = o;
    }
}

// ---------------- strided down conv: K=4, stride 2, 64->64, ReLU ----------------
__global__ void __launch_bounds__(256, 2) conv_s2_kernel(
    const float* __restrict__ x, const float* __restrict__ w,
    const float* __restrict__ bias, float* __restrict__ y, int Tout)
{
    extern __shared__ float smem[];
    float* xs = smem;                           // [258][65]
    float* wsm = smem + ALIGN4(258 * 65);       // [64][64]
    const int Tin = Tout << 1;
    const int tid = threadIdx.x;
    const int tilesPerB = Tout >> 7;
    const int b = blockIdx.x / tilesPerB;
    const int t0 = (blockIdx.x - b * tilesPerB) << 7;
    const float* xb = x + (size_t)b * Tin * 64;

    for (int idx = tid; idx < 258 * 16; idx += 256) {
        int r = idx >> 4, c4 = idx & 15;
        int gt = 2 * t0 - 1 + r;
        float4 v = make_float4(0.f, 0.f, 0.f, 0.f);
        if (gt >= 0 && gt < Tin) v = *(const float4*)(xb + (size_t)gt * 64 + c4 * 4);
        float* d = &xs[r * 65 + c4 * 4];
        d[0] = v.x; d[1] = v.y; d[2] = v.z; d[3] = v.w;
    }

    const int tg = tid >> 3;
    const int cg = tid & 7;
    float acc[4][8];
    #pragma unroll
    for (int i = 0; i < 4; i++)
        #pragma unroll
        for (int j = 0; j < 8; j++) acc[i][j] = 0.f;

    for (int k = 0; k < 4; k++) {
        __syncthreads();
        {
            const float4* wg = (const float4*)(w + k * 4096);
            float4* wd = (float4*)wsm;
            for (int idx = tid; idx < 1024; idx += 256) wd[idx] = wg[idx];
        }
        __syncthreads();
        const float4* ws4 = (const float4*)wsm;
        #pragma unroll 2
        for (int ci = 0; ci < 64; ci++) {
            float4 wa = ws4[ci * 16 + cg * 2];
            float4 wb = ws4[ci * 16 + cg * 2 + 1];
            #pragma unroll
            for (int i = 0; i < 4; i++) {
                float xv = xs[(2 * (tg * 4 + i) + k) * 65 + ci];
                acc[i][0] += xv * wa.x; acc[i][1] += xv * wa.y;
                acc[i][2] += xv * wa.z; acc[i][3] += xv * wa.w;
                acc[i][4] += xv * wb.x; acc[i][5] += xv * wb.y;
                acc[i][6] += xv * wb.z; acc[i][7] += xv * wb.w;
            }
        }
    }

    const int co0 = cg * 8;
    float4 bv0 = *(const float4*)(bias + co0);
    float4 bv1 = *(const float4*)(bias + co0 + 4);
    #pragma unroll
    for (int i = 0; i < 4; i++) {
        int gt = t0 + tg * 4 + i;
        float* op = y + ((size_t)b * Tout + gt) * 64 + co0;
        float4 o0, o1;
        o0.x = fmaxf(acc[i][0] + bv0.x, 0.f);
        o0.y = fmaxf(acc[i][1] + bv0.y, 0.f);
        o0.z = fmaxf(acc[i][2] + bv0.z, 0.f);
        o0.w = fmaxf(acc[i][3] + bv0.w, 0.f);
        o1.x = fmaxf(acc[i][4] + bv1.x, 0.f);
        o1.y = fmaxf(acc[i][5] + bv1.y, 0.f);
        o1.z = fmaxf(acc[i][6] + bv1.z, 0.f);
        o1.w = fmaxf(acc[i][7] + bv1.w, 0.f);
        *(float4*)op = o0;
        *(float4*)(op + 4) = o1;
    }
}

// ---------------- fused transposed conv + projection (Tout=65536) -----------
// tr: even o: w0*x[o/2-1] + w2*x[o/2] ; odd o: w1*x[(o-1)/2] + w3*x[(o+1)/2]
// then proj K=3 over the ReLU'd tr output, straight to out[x_hat].
#define XT_S 68
#define HS_S 68

__global__ void __launch_bounds__(256, 3) conv_tr_proj_kernel(
    const float* __restrict__ x, const float* __restrict__ w,
    const float* __restrict__ bias,
    const float* __restrict__ wproj, const float* __restrict__ bproj,
    float* __restrict__ out, int Tout)
{
    extern __shared__ float smem[];
    float* xsT = smem;                         // [64][XT_S]
    float* hs  = smem + 64 * XT_S;             // [130][HS_S] rows = t0-1 .. t0+128
    float* wps = smem + 64 * XT_S + 130 * HS_S; // [192]

    const int Tin = Tout >> 1;
    const int tid = threadIdx.x;
    const int tilesPerB = Tout >> 7;
    const int b = blockIdx.x / tilesPerB;
    const int t0 = (blockIdx.x - b * tilesPerB) << 7;
    const float* xb = x + (size_t)b * Tin * 64;
    const int in0 = (t0 >> 1) - 1;

    for (int idx = tid; idx < 64 * 17; idx += 256) {
        int ci = idx & 63;
        int rb = (idx >> 6) << 2;
        int gt = in0 + rb;
        float4 v;
        v.x = (gt + 0 >= 0 && gt + 0 < Tin) ? xb[(size_t)(gt + 0) * 64 + ci] : 0.f;
        v.y = (gt + 1 >= 0 && gt + 1 < Tin) ? xb[(size_t)(gt + 1) * 64 + ci] : 0.f;
        v.z = (gt + 2 >= 0 && gt + 2 < Tin) ? xb[(size_t)(gt + 2) * 64 + ci] : 0.f;
        v.w = (gt + 3 >= 0 && gt + 3 < Tin) ? xb[(size_t)(gt + 3) * 64 + ci] : 0.f;
        *(float4*)&xsT[ci * XT_S + rb] = v;
    }
    if (tid < 192) wps[tid] = wproj[tid];
    __syncthreads();

    const int tg = tid >> 4;        // 16 groups of 8 outputs
    const int cg = tid & 15;        // 16 co groups of 4
    const int tb = tg << 3;
    const int ib = tg << 2;
    const int co0 = cg << 2;

    float acc[8][4];
    #pragma unroll
    for (int i = 0; i < 8; i++)
        #pragma unroll
        for (int j = 0; j < 4; j++) acc[i][j] = 0.f;
    float accE[4] = {0.f, 0.f, 0.f, 0.f};   // tg0: odd out @ t0-1; tg15: even out @ t0+128

    const float4* wp = (const float4*)(w + co0);   // taps at +0,+1024,+2048,+3072
    const float* xrp = &xsT[ib];

    #pragma unroll 2
    for (int ci = 0; ci < 64; ci++) {
        const float4* xr = (const float4*)xrp;
        float4 c0 = xr[0];
        float4 c1 = xr[1];
        float xw[8];
        xw[0] = c0.x; xw[1] = c0.y; xw[2] = c0.z; xw[3] = c0.w;
        xw[4] = c1.x; xw[5] = c1.y; xw[6] = c1.z; xw[7] = c1.w;

        float4 w0 = __ldg(wp);
        float4 w1 = __ldg(wp + 1024);
        float4 w2 = __ldg(wp + 2048);
        float4 w3 = __ldg(wp + 3072);
        #pragma unroll
        for (int ii = 0; ii < 4; ii++) {
            const int e = 2 * ii, o = 2 * ii + 1;
            float xe0 = xw[ii], xe1 = xw[ii + 1];
            acc[e][0] += xe0 * w0.x + xe1 * w2.x;
            acc[e][1] += xe0 * w0.y + xe1 * w2.y;
            acc[e][2] += xe0 * w0.z + xe1 * w2.z;
            acc[e][3] += xe0 * w0.w + xe1 * w2.w;
            float xo0 = xw[ii + 1], xo1 = xw[ii + 2];
            acc[o][0] += xo0 * w1.x + xo1 * w3.x;
            acc[o][1] += xo0 * w1.y + xo1 * w3.y;
            acc[o][2] += xo0 * w1.z + xo1 * w3.z;
            acc[o][3] += xo0 * w1.w + xo1 * w3.w;
        }
        if (tg == 0) {
            // odd output gt=t0-1: x[(gt-1)/2]=local0=xw[0], x[(gt+1)/2]=local1=xw[1]
            accE[0] += xw[0] * w1.x + xw[1] * w3.x;
            accE[1] += xw[0] * w1.y + xw[1] * w3.y;
            accE[2] += xw[0] * w1.z + xw[1] * w3.z;
            accE[3] += xw[0] * w1.w + xw[1] * w3.w;
        } else if (tg == 15) {
            // even output gt=t0+128: x[gt/2-1]=local64=xw[4], x[gt/2]=local65=xw[5]
            accE[0] += xw[4] * w0.x + xw[5] * w2.x;
            accE[1] += xw[4] * w0.y + xw[5] * w2.y;
            accE[2] += xw[4] * w0.z + xw[5] * w2.z;
            accE[3] += xw[4] * w0.w + xw[5] * w2.w;
        }
        wp += 16;
        xrp += XT_S;
    }

    // ReLU'd tr outputs -> smem rows (row r == global t0-1+r)
    float4 bv = *(const float4*)(bias + co0);
    #pragma unroll
    for (int i = 0; i < 8; i++) {
        float4 o;
        o.x = fmaxf(acc[i][0] + bv.x, 0.f);
        o.y = fmaxf(acc[i][1] + bv.y, 0.f);
        o.z = fmaxf(acc[i][2] + bv.z, 0.f);
        o.w = fmaxf(acc[i][3] + bv.w, 0.f);
        *(float4*)&hs[(tb + 1 + i) * HS_S + co0] = o;
    }
    if (tg == 0) {
        float4 o = make_float4(0.f, 0.f, 0.f, 0.f);
        if (t0 > 0) {
            o.x = fmaxf(accE[0] + bv.x, 0.f);
            o.y = fmaxf(accE[1] + bv.y, 0.f);
            o.z = fmaxf(accE[2] + bv.z, 0.f);
            o.w = fmaxf(accE[3] + bv.w, 0.f);
        }
        *(float4*)&hs[0 * HS_S + co0] = o;
    } else if (tg == 15) {
        float4 o = make_float4(0.f, 0.f, 0.f, 0.f);
        if (t0 + 128 < Tout) {
            o.x = fmaxf(accE[0] + bv.x, 0.f);
            o.y = fmaxf(accE[1] + bv.y, 0.f);
            o.z = fmaxf(accE[2] + bv.z, 0.f);
            o.w = fmaxf(accE[3] + bv.w, 0.f);
        }
        *(float4*)&hs[129 * HS_S + co0] = o;
    }
    __syncthreads();

    // projection: out[t0+tid] = b + sum_k sum_ci hs[tid+k][ci] * wproj[k*64+ci]
    if (tid < 128) {
        float a = __ldg(bproj);
        #pragma unroll
        for (int k = 0; k < 3; k++) {
            const float* hrow = &hs[(tid + k) * HS_S];
            const float* wrow = &wps[k * 64];
            #pragma unroll 8
            for (int ci = 0; ci < 64; ci++)
                a += hrow[ci] * wrow[ci];
        }
        out[OFF_XHAT + (size_t)b * Tout + t0 + tid] = a;
    }
}

// ---------------- transposed conv (Tout<=32768) ------------------------------
__global__ void __launch_bounds__(256, 2) conv_tr_kernel(
    const float* __restrict__ x, const float* __restrict__ w,
    const float* __restrict__ bias, float* __restrict__ y, int Tout)
{
    extern __shared__ float smem[];
    float* xs = smem;                           // [130][65]
    float* wsm = smem + ALIGN4(130 * 65);       // [4][64][64]
    const int Tin = Tout >> 1;
    const int tid = threadIdx.x;
    const int tilesPerB = Tout >> 8;
    const int b = blockIdx.x / tilesPerB;
    const int t0 = (blockIdx.x - b * tilesPerB) << 8;
    const float* xb = x + (size_t)b * Tin * 64;
    const int in0 = (t0 >> 1) - 1;

    for (int idx = tid; idx < 130 * 16; idx += 256) {
        int r = idx >> 4, c4 = idx & 15;
        int gt = in0 + r;
        float4 v = make_float4(0.f, 0.f, 0.f, 0.f);
        if (gt >= 0 && gt < Tin) v = *(const float4*)(xb + (size_t)gt * 64 + c4 * 4);
        float* d = &xs[r * 65 + c4 * 4];
        d[0] = v.x; d[1] = v.y; d[2] = v.z; d[3] = v.w;
    }
    {
        const float4* wg = (const float4*)w;
        float4* wd = (float4*)wsm;
        for (int idx = tid; idx < 4096; idx += 256) wd[idx] = wg[idx];
    }
    __syncthreads();

    const int tg = tid >> 3;
    const int cg = tid & 7;
    float acc[8][8];
    #pragma unroll
    for (int i = 0; i < 8; i++)
        #pragma unroll
        for (int j = 0; j < 8; j++) acc[i][j] = 0.f;

    const float4* ws4 = (const float4*)wsm;
    #pragma unroll 2
    for (int ci = 0; ci < 64; ci++) {
        float xv[6];
        #pragma unroll
        for (int m = 0; m < 6; m++) xv[m] = xs[(tg * 4 + m) * 65 + ci];
        {
            float4 wa0 = ws4[ci * 16 + cg * 2];
            float4 wb0 = ws4[ci * 16 + cg * 2 + 1];
            float4 wa2 = ws4[2 * 1024 + ci * 16 + cg * 2];
            float4 wb2 = ws4[2 * 1024 + ci * 16 + cg * 2 + 1];
            #pragma unroll
            for (int ii = 0; ii < 4; ii++) {
                const int i = 2 * ii;
                float xa = xv[ii], xbv = xv[ii + 1];
                acc[i][0] += xa * wa0.x + xbv * wa2.x;
                acc[i][1] += xa * wa0.y + xbv * wa2.y;
                acc[i][2] += xa * wa0.z + xbv * wa2.z;
                acc[i][3] += xa * wa0.w + xbv * wa2.w;
                acc[i][4] += xa * wb0.x + xbv * wb2.x;
                acc[i][5] += xa * wb0.y + xbv * wb2.y;
                acc[i][6] += xa * wb0.z + xbv * wb2.z;
                acc[i][7] += xa * wb0.w + xbv * wb2.w;
            }
        }
        {
            float4 wa1 = ws4[1024 + ci * 16 + cg * 2];
            float4 wb1 = ws4[1024 + ci * 16 + cg * 2 + 1];
            float4 wa3 = ws4[3 * 1024 + ci * 16 + cg * 2];
            float4 wb3 = ws4[3 * 1024 + ci * 16 + cg * 2 + 1];
            #pragma unroll
            for (int ii = 0; ii < 4; ii++) {
                const int i = 2 * ii + 1;
                float xa = xv[ii + 1], xbv = xv[ii + 2];
                acc[i][0] += xa * wa1.x + xbv * wa3.x;
                acc[i][1] += xa * wa1.y + xbv * wa3.y;
                acc[i][2] += xa * wa1.z + xbv * wa3.z;
                acc[i][3] += xa * wa1.w + xbv * wa3.w;
                acc[i][4] += xa * wb1.x + xbv * wb3.x;
                acc[i][5] += xa * wb1.y + xbv * wb3.y;
                acc[i][6] += xa * wb1.z + xbv * wb3.z;
                acc[i][7] += xa * wb1.w + xbv * wb3.w;
            }
        }
    }

    const int co0 = cg * 8;
    float4 bv0 = *(const float4*)(bias + co0);
    float4 bv1 = *(const float4*)(bias + co0 + 4);
    #pragma unroll
    for (int i = 0; i < 8; i++) {
        int gt = t0 + tg * 8 + i;
        float* op = y + ((size_t)b * Tout + gt) * 64 + co0;
        float4 o0, o1;
        o0.x = fmaxf(acc[i][0] + bv0.x, 0.f);
        o0.y = fmaxf(acc[i][1] + bv0.y, 0.f);
        o0.z = fmaxf(acc[i][2] + bv0.z, 0.f);
        o0.w = fmaxf(acc[i][3] + bv0.w, 0.f);
        o1.x = fmaxf(acc[i][4] + bv1.x, 0.f);
        o1.y = fmaxf(acc[i][5] + bv1.y, 0.f);
        o1.z = fmaxf(acc[i][6] + bv1.z, 0.f);
        o1.w = fmaxf(acc[i][7] + bv1.w, 0.f);
        *(float4*)op = o0;
        *(float4*)(op + 4) = o1;
    }
}

// ---------------- VQ ----------------
__global__ void __launch_bounds__(256) vq_kernel(
    const float* __restrict__ ze, const float* __restrict__ cb,
    float* __restrict__ zq, float* __restrict__ dout)
{
    __shared__ float zs[32 * 65];
    __shared__ float cbs[128 * 65];
    __shared__ float nzs[32], rsnzs[32];

    const int tid = threadIdx.x;
    const int rg = tid >> 5;
    const int eg = tid & 31;
    const int row0 = blockIdx.x * 32;

    for (int idx = tid; idx < 32 * 16; idx += 256) {
        int r = idx >> 4, c4 = idx & 15;
        float4 v = *(const float4*)(ze + (size_t)(row0 + r) * 64 + c4 * 4);
        float* d = &zs[r * 65 + c4 * 4];
        d[0] = v.x; d[1] = v.y; d[2] = v.z; d[3] = v.w;
    }
    __syncthreads();
    if (tid < 32) {
        float s = 0.f;
        #pragma unroll 8
        for (int ci = 0; ci < 64; ci++) { float v = zs[tid * 65 + ci]; s += v * v; }
        nzs[tid] = s;
        rsnzs[tid] = rsqrtf(s);
    }

    float bv[4] = {3.4e38f, 3.4e38f, 3.4e38f, 3.4e38f};
    int bi[4] = {0, 0, 0, 0};

    for (int c = 0; c < 4; c++) {
        __syncthreads();
        for (int idx = tid; idx < 128 * 16; idx += 256) {
            int e = idx >> 4, c4 = idx & 15;
            float4 v = *(const float4*)(cb + (size_t)(c * 128 + e) * 64 + c4 * 4);
            float* d = &cbs[e * 65 + c4 * 4];
            d[0] = v.x; d[1] = v.y; d[2] = v.z; d[3] = v.w;
        }
        __syncthreads();

        float acc[4][4];
        #pragma unroll
        for (int i = 0; i < 4; i++)
            #pragma unroll
            for (int j = 0; j < 4; j++) acc[i][j] = 0.f;

        #pragma unroll 4
        for (int ci = 0; ci < 64; ci++) {
            float zv[4], cv[4];
            #pragma unroll
            for (int i = 0; i < 4; i++) zv[i] = zs[(rg * 4 + i) * 65 + ci];
            #pragma unroll
            for (int j = 0; j < 4; j++) cv[j] = cbs[(j * 32 + eg) * 65 + ci];
            #pragma unroll
            for (int i = 0; i < 4; i++)
                #pragma unroll
                for (int j = 0; j < 4; j++) acc[i][j] += zv[i] * cv[j];
        }

        #pragma unroll
        for (int j = 0; j < 4; j++) {
            int e = c * 128 + j * 32 + eg;
            float nev = __ldg(&g_ne[e]);
            float rse = __ldg(&g_rsne[e]);
            #pragma unroll
            for (int i = 0; i < 4; i++) {
                int r = rg * 4 + i;
                float dot = acc[i][j];
                float dist = -2.0f * dot + nzs[r] + nev;
                float sim = dot * rsnzs[r] * rse;
                dout[OFF_SIM + (size_t)(row0 + r) * NEMB + e] = sim;
                if (dist < bv[i]) { bv[i] = dist; bi[i] = e; }
            }
        }
    }

    #pragma unroll
    for (int i = 0; i < 4; i++) {
        float v = bv[i];
        int idx = bi[i];
        #pragma unroll
        for (int off = 16; off > 0; off >>= 1) {
            float ov = __shfl_down_sync(0xffffffffu, v, off);
            int oi = __shfl_down_sync(0xffffffffu, idx, off);
            if (ov < v || (ov == v && oi < idx)) { v = ov; idx = oi; }
        }
        if (eg == 0) {
            int r = rg * 4 + i;
            int gr = row0 + r;
            dout[OFF_IDS + gr] = (float)idx;
            float s = 0.f;
            const float* cp = cb + (size_t)idx * 64;
            float* qp = zq + (size_t)gr * 64;
            #pragma unroll 8
            for (int ci = 0; ci < 64; ci++) {
                float cvv = __ldg(cp + ci);
                qp[ci] = cvv;
                float d = zs[r * 65 + ci] - cvv;
                s += d * d;
            }
            atomicAdd(&g_loss, sqrtf(s));
        }
    }
}

// ---------------- host orchestration ----------------
#define SMEM_RES128 (64 * XS128 * 4)
#define SMEM_RES64  (64 * XS64 * 4)
#define SMEM_TRPJ   ((64 * XT_S + 130 * HS_S + 192) * 4)
#define SMEM_S2   ((ALIGN4(258 * 65) + 4096) * 4)
#define SMEM_TR   ((ALIGN4(130 * 65) + 16384) * 4)

static inline void launch_res_pair(bool enc, int T,
    const float* w1, const float* b1, const float* w2, const float* b2,
    float* h, float* t)
{
    if (T >= 32768) {
        const int grid = NBATCH * (T >> 7);
        if (enc) {
            conv_res128_kernel<3, false><<<grid, 256, SMEM_RES128>>>(h, w1, b1, nullptr, t, T);
            conv_res128_kernel<1, true ><<<grid, 256, SMEM_RES128>>>(t, w2, b2, h, h, T);
        } else {
            conv_res128_kernel<1, false><<<grid, 256, SMEM_RES128>>>(h, w1, b1, nullptr, t, T);
            conv_res128_kernel<3, true ><<<grid, 256, SMEM_RES128>>>(t, w2, b2, h, h, T);
        }
    } else {
        const int grid = NBATCH * (T >> 6);
        if (enc) {
            conv_res64_kernel<3, false><<<grid, 256, SMEM_RES64>>>(h, w1, b1, nullptr, t, T);
            conv_res64_kernel<1, true ><<<grid, 256, SMEM_RES64>>>(t, w2, b2, h, h, T);
        } else {
            conv_res64_kernel<1, false><<<grid, 256, SMEM_RES64>>>(h, w1, b1, nullptr, t, T);
            conv_res64_kernel<3, true ><<<grid, 256, SMEM_RES64>>>(t, w2, b2, h, h, T);
        }
    }
}

extern "C" void kernel_launch(void* const* d_in, const int* in_sizes, int n_in,
                              void* d_out, int out_size)
{
    const float* x        = (const float*)d_in[0];
    const float* w_down0  = (const float*)d_in[1];
    const float* b_down0  = (const float*)d_in[2];
    const float* w_down   = (const float*)d_in[3];
    const float* b_down   = (const float*)d_in[4];
    const float* w_res_e  = (const float*)d_in[5];
    const float* b_res_e  = (const float*)d_in[6];
    const float* codebook = (const float*)d_in[7];
    const float* w_res_d  = (const float*)d_in[8];
    const float* b_res_d  = (const float*)d_in[9];
    const float* w_up     = (const float*)d_in[10];
    const float* b_up     = (const float*)d_in[11];
    const float* w_proj   = (const float*)d_in[12];
    const float* b_proj   = (const float*)d_in[13];
    float* out = (float*)d_out;

    float *A, *Bb;
    cudaGetSymbolAddress((void**)&A, g_A);
    cudaGetSymbolAddress((void**)&Bb, g_B);

    cudaFuncSetAttribute(conv_res128_kernel<3, false>, cudaFuncAttributeMaxDynamicSharedMemorySize, SMEM_RES128);
    cudaFuncSetAttribute(conv_res128_kernel<3, true >, cudaFuncAttributeMaxDynamicSharedMemorySize, SMEM_RES128);
    cudaFuncSetAttribute(conv_res128_kernel<1, false>, cudaFuncAttributeMaxDynamicSharedMemorySize, SMEM_RES128);
    cudaFuncSetAttribute(conv_res128_kernel<1, true >, cudaFuncAttributeMaxDynamicSharedMemorySize, SMEM_RES128);
    cudaFuncSetAttribute(conv_res64_kernel<3, false>, cudaFuncAttributeMaxDynamicSharedMemorySize, SMEM_RES64);
    cudaFuncSetAttribute(conv_res64_kernel<3, true >, cudaFuncAttributeMaxDynamicSharedMemorySize, SMEM_RES64);
    cudaFuncSetAttribute(conv_res64_kernel<1, false>, cudaFuncAttributeMaxDynamicSharedMemorySize, SMEM_RES64);
    cudaFuncSetAttribute(conv_res64_kernel<1, true >, cudaFuncAttributeMaxDynamicSharedMemorySize, SMEM_RES64);
    cudaFuncSetAttribute(conv_tr_proj_kernel, cudaFuncAttributeMaxDynamicSharedMemorySize, SMEM_TRPJ);
    cudaFuncSetAttribute(conv_s2_kernel, cudaFuncAttributeMaxDynamicSharedMemorySize, SMEM_S2);
    cudaFuncSetAttribute(conv_tr_kernel, cudaFuncAttributeMaxDynamicSharedMemorySize, SMEM_TR);

    zero_loss_kernel<<<1, 1>>>();
    ne_kernel<<<2, 256>>>(codebook);

    float* h = A;
    float* t = Bb;

    // ---------- encoder ----------
    down0_kernel<<<2048, 256>>>(x, w_down0, b_down0, h);
    int T = 32768;
    for (int blk = 0; blk < 3; blk++) {
        if (blk > 0) {
            int Tout = T >> 1;
            conv_s2_kernel<<<NBATCH * (Tout >> 7), 256, SMEM_S2>>>(
                h, w_down + (size_t)(blk - 1) * 16384, b_down + (blk - 1) * 64, t, Tout);
            T = Tout;
            float* tmp = h; h = t; t = tmp;
        }
        for (int r = 0; r < 4; r++) {
            const float* w1 = w_res_e + (size_t)((blk * 4 + r) * 2 + 0) * 12288;
            const float* w2 = w_res_e + (size_t)((blk * 4 + r) * 2 + 1) * 12288;
            const float* bb1 = b_res_e + ((blk * 4 + r) * 2 + 0) * 64;
            const float* bb2 = b_res_e + ((blk * 4 + r) * 2 + 1) * 64;
            launch_res_pair(true, T, w1, bb1, w2, bb2, h, t);
        }
    }

    // ---------- VQ (T = 8192) ----------
    vq_kernel<<<1024, 256>>>(h, codebook, t, out);
    loss_fin_kernel<<<1, 1>>>(out);
    { float* tmp = h; h = t; t = tmp; }   // h = z_q

    // ---------- decoder ----------
    for (int blk = 0; blk < 3; blk++) {
        for (int r = 0; r < 4; r++) {
            const float* w1 = w_res_d + (size_t)((blk * 4 + r) * 2 + 0) * 12288;
            const float* w2 = w_res_d + (size_t)((blk * 4 + r) * 2 + 1) * 12288;
            const float* bb1 = b_res_d + ((blk * 4 + r) * 2 + 0) * 64;
            const float* bb2 = b_res_d + ((blk * 4 + r) * 2 + 1) * 64;
            launch_res_pair(false, T, w1, bb1, w2, bb2, h, t);
        }
        int Tout = T << 1;
        if (Tout >= 65536) {
            // fused final upsample + projection, writes x_hat directly
            conv_tr_proj_kernel<<<NBATCH * (Tout >> 7), 256, SMEM_TRPJ>>>(
                h, w_up + (size_t)blk * 16384, b_up + blk * 64,
                w_proj, b_proj, out, Tout);
        } else {
            conv_tr_kernel<<<NBATCH * (Tout >> 8), 256, SMEM_TR>>>(
                h, w_up + (size_t)blk * 16384, b_up + blk * 64, t, Tout);
            float* tmp = h; h = t; t = tmp;
        }
        T = Tout;
    }
}

// round 16
// speedup vs baseline: 1.5984x; 1.0119x over previous
#include <cuda_runtime.h>
#include <math.h>
#include <stdint.h>

// ---------------- constants ----------------
#define NBATCH 4
#define TTOP   65536
#define OFF_XHAT 0
#define OFF_LOSS 262144
#define OFF_IDS  262145
#define OFF_SIM  294913
#define NEMB 512

#define ALIGN4(n) (((n) + 3) & ~3)

// ---------------- scratch ----------------
__device__ float g_A[16777216];
__device__ float g_B[16777216];
__device__ float g_ne[NEMB];
__device__ float g_rsne[NEMB];
__device__ float g_loss;

__global__ void ne_kernel(const float* __restrict__ cb) {
    if (blockIdx.x == 0 && threadIdx.x == 0) g_loss = 0.f;
    int e = blockIdx.x * blockDim.x + threadIdx.x;
    if (e < NEMB) {
        float s = 0.f;
        #pragma unroll 8
        for (int ci = 0; ci < 64; ci++) { float v = cb[e * 64 + ci]; s += v * v; }
        g_ne[e] = s;
        g_rsne[e] = rsqrtf(s);
    }
}

__global__ void loss_fin_kernel(float* __restrict__ out) {
    out[OFF_LOSS] = 1.25f * g_loss / 32768.0f;
}

// ---------------- first conv: Cin=1 -> 64, K=4, stride 2, ReLU ----------------
__global__ void __launch_bounds__(256) down0_kernel(
    const float* __restrict__ x, const float* __restrict__ w,
    const float* __restrict__ bias, float* __restrict__ y)
{
    __shared__ float ws[256];
    __shared__ float bs[64];
    int tid = threadIdx.x;
    ws[tid] = w[tid];
    if (tid < 64) bs[tid] = bias[tid];
    __syncthreads();

    int g = blockIdx.x * 256 + tid;
    int q = g & 3;
    int rest = g >> 2;
    int ot = rest & 32767;
    int b = rest >> 15;

    float acc[16];
    #pragma unroll
    for (int c = 0; c < 16; c++) acc[c] = bs[q * 16 + c];
    #pragma unroll
    for (int k = 0; k < 4; k++) {
        int t = 2 * ot - 1 + k;
        float xv = (t >= 0 && t < TTOP) ? x[(size_t)b * TTOP + t] : 0.f;
        #pragma unroll
        for (int c = 0; c < 16; c++) acc[c] += xv * ws[k * 64 + q * 16 + c];
    }
    float* op = y + ((size_t)(b * 32768 + ot)) * 64 + q * 16;
    #pragma unroll
    for (int c4 = 0; c4 < 4; c4++) {
        float4 o;
        o.x = fmaxf(acc[c4 * 4 + 0], 0.f);
        o.y = fmaxf(acc[c4 * 4 + 1], 0.f);
        o.z = fmaxf(acc[c4 * 4 + 2], 0.f);
        o.w = fmaxf(acc[c4 * 4 + 3], 0.f);
        *(float4*)(op + c4 * 4) = o;
    }
}

// ---------------- residual conv, 128-t tile (proven) -------------------------
#define XS128 164

template<int DIL, bool RES>
__global__ void __launch_bounds__(256, 3) conv_res128_kernel(
    const float* __restrict__ x, const float* __restrict__ w,
    const float* __restrict__ bias, const float* __restrict__ res,
    float* __restrict__ y, int T)
{
    constexpr int ROWS = 128 + 2 * DIL;
    constexpr int NQ = (ROWS + 3) >> 2;
    constexpr int W = 8 + 2 * DIL;
    constexpr int NV = (W + 3) >> 2;

    extern __shared__ float smem[];
    float* xsT = smem;   // [64][XS128]

    const int tid = threadIdx.x;
    const int tilesPerB = T >> 7;
    const int b = blockIdx.x / tilesPerB;
    const int t0 = (blockIdx.x - b * tilesPerB) << 7;
    const float* xb = x + (size_t)b * T * 64;

    for (int idx = tid; idx < 64 * NQ; idx += 256) {
        int ci = idx & 63;
        int rb = (idx >> 6) << 2;
        int gt = t0 - DIL + rb;
        float4 v;
        v.x = (gt + 0 >= 0 && gt + 0 < T) ? xb[(size_t)(gt + 0) * 64 + ci] : 0.f;
        v.y = (gt + 1 >= 0 && gt + 1 < T) ? xb[(size_t)(gt + 1) * 64 + ci] : 0.f;
        v.z = (gt + 2 >= 0 && gt + 2 < T) ? xb[(size_t)(gt + 2) * 64 + ci] : 0.f;
        v.w = (gt + 3 >= 0 && gt + 3 < T) ? xb[(size_t)(gt + 3) * 64 + ci] : 0.f;
        *(float4*)&xsT[ci * XS128 + rb] = v;
    }
    __syncthreads();

    const int tg = tid >> 4;
    const int cg = tid & 15;
    const int tb = tg << 3;
    const int co0 = cg << 2;

    float acc[8][4];
    #pragma unroll
    for (int i = 0; i < 8; i++)
        #pragma unroll
        for (int j = 0; j < 4; j++) acc[i][j] = 0.f;

    const float4* wp = (const float4*)(w + co0);
    const float* xrp = &xsT[tb];

    #pragma unroll 2
    for (int ci = 0; ci < 64; ci++) {
        const float4* xr = (const float4*)xrp;
        float xw[NV * 4];
        #pragma unroll
        for (int v = 0; v < NV; v++) {
            float4 c = xr[v];
            xw[v * 4 + 0] = c.x; xw[v * 4 + 1] = c.y;
            xw[v * 4 + 2] = c.z; xw[v * 4 + 3] = c.w;
        }

        float4 wa0 = __ldg(wp);
        float4 wa1 = __ldg(wp + 1024);
        float4 wa2 = __ldg(wp + 2048);
        #pragma unroll
        for (int i = 0; i < 8; i++) {
            float x0 = xw[i];
            acc[i][0] += x0 * wa0.x; acc[i][1] += x0 * wa0.y;
            acc[i][2] += x0 * wa0.z; acc[i][3] += x0 * wa0.w;
            float x1 = xw[i + DIL];
            acc[i][0] += x1 * wa1.x; acc[i][1] += x1 * wa1.y;
            acc[i][2] += x1 * wa1.z; acc[i][3] += x1 * wa1.w;
            float x2 = xw[i + 2 * DIL];
            acc[i][0] += x2 * wa2.x; acc[i][1] += x2 * wa2.y;
            acc[i][2] += x2 * wa2.z; acc[i][3] += x2 * wa2.w;
        }
        wp += 16;
        xrp += XS128;
    }

    float4 bv = *(const float4*)(bias + co0);
    #pragma unroll
    for (int i = 0; i < 8; i++) {
        int gt = t0 + tb + i;
        float* op = y + ((size_t)b * T + gt) * 64 + co0;
        float4 o;
        o.x = fmaxf(acc[i][0] + bv.x, 0.f);
        o.y = fmaxf(acc[i][1] + bv.y, 0.f);
        o.z = fmaxf(acc[i][2] + bv.z, 0.f);
        o.w = fmaxf(acc[i][3] + bv.w, 0.f);
        if (RES) {
            float4 r0 = *(const float4*)(res + ((size_t)b * T + gt) * 64 + co0);
            o.x += r0.x; o.y += r0.y; o.z += r0.z; o.w += r0.w;
        }
        *(float4*)op = o;
    }
}

// ---------------- residual conv, 64-t tile (proven) --------------------------
#define XS64 76

template<int DIL, bool RES>
__global__ void __launch_bounds__(256, 4) conv_res64_kernel(
    const float* __restrict__ x, const float* __restrict__ w,
    const float* __restrict__ bias, const float* __restrict__ res,
    float* __restrict__ y, int T)
{
    constexpr int ROWS = 64 + 2 * DIL;
    constexpr int NQ = (ROWS + 3) >> 2;
    constexpr int W = 4 + 2 * DIL;
    constexpr int NV = (W + 3) >> 2;

    extern __shared__ float smem[];
    float* xsT = smem;   // [64][XS64]

    const int tid = threadIdx.x;
    const int tilesPerB = T >> 6;
    const int b = blockIdx.x / tilesPerB;
    const int t0 = (blockIdx.x - b * tilesPerB) << 6;
    const float* xb = x + (size_t)b * T * 64;

    for (int idx = tid; idx < 64 * NQ; idx += 256) {
        int ci = idx & 63;
        int rb = (idx >> 6) << 2;
        int gt = t0 - DIL + rb;
        float4 v;
        v.x = (gt + 0 >= 0 && gt + 0 < T) ? xb[(size_t)(gt + 0) * 64 + ci] : 0.f;
        v.y = (gt + 1 >= 0 && gt + 1 < T) ? xb[(size_t)(gt + 1) * 64 + ci] : 0.f;
        v.z = (gt + 2 >= 0 && gt + 2 < T) ? xb[(size_t)(gt + 2) * 64 + ci] : 0.f;
        v.w = (gt + 3 >= 0 && gt + 3 < T) ? xb[(size_t)(gt + 3) * 64 + ci] : 0.f;
        *(float4*)&xsT[ci * XS64 + rb] = v;
    }
    __syncthreads();

    const int tg = tid >> 4;
    const int cg = tid & 15;
    const int tb = tg << 2;
    const int co0 = cg << 2;

    float acc[4][4];
    #pragma unroll
    for (int i = 0; i < 4; i++)
        #pragma unroll
        for (int j = 0; j < 4; j++) acc[i][j] = 0.f;

    const float4* wp = (const float4*)(w + co0);
    const float* xrp = &xsT[tb];

    #pragma unroll 2
    for (int ci = 0; ci < 64; ci++) {
        const float4* xr = (const float4*)xrp;
        float xw[NV * 4];
        #pragma unroll
        for (int v = 0; v < NV; v++) {
            float4 c = xr[v];
            xw[v * 4 + 0] = c.x; xw[v * 4 + 1] = c.y;
            xw[v * 4 + 2] = c.z; xw[v * 4 + 3] = c.w;
        }

        float4 wa0 = __ldg(wp);
        float4 wa1 = __ldg(wp + 1024);
        float4 wa2 = __ldg(wp + 2048);
        #pragma unroll
        for (int i = 0; i < 4; i++) {
            float x0 = xw[i];
            acc[i][0] += x0 * wa0.x; acc[i][1] += x0 * wa0.y;
            acc[i][2] += x0 * wa0.z; acc[i][3] += x0 * wa0.w;
            float x1 = xw[i + DIL];
            acc[i][0] += x1 * wa1.x; acc[i][1] += x1 * wa1.y;
            acc[i][2] += x1 * wa1.z; acc[i][3] += x1 * wa1.w;
            float x2 = xw[i + 2 * DIL];
            acc[i][0] += x2 * wa2.x; acc[i][1] += x2 * wa2.y;
            acc[i][2] += x2 * wa2.z; acc[i][3] += x2 * wa2.w;
        }
        wp += 16;
        xrp += XS64;
    }

    float4 bv = *(const float4*)(bias + co0);
    #pragma unroll
    for (int i = 0; i < 4; i++) {
        int gt = t0 + tb + i;
        float* op = y + ((size_t)b * T + gt) * 64 + co0;
        float4 o;
        o.x = fmaxf(acc[i][0] + bv.x, 0.f);
        o.y = fmaxf(acc[i][1] + bv.y, 0.f);
        o.z = fmaxf(acc[i][2] + bv.z, 0.f);
        o.w = fmaxf(acc[i][3] + bv.w, 0.f);
        if (RES) {
            float4 r0 = *(const float4*)(res + ((size_t)b * T + gt) * 64 + co0);
            o.x += r0.x; o.y += r0.y; o.z += r0.z; o.w += r0.w;
        }
        *(float4*)op = o;
    }
}

// ---------------- strided down conv: K=4, stride 2, 64->64, ReLU -------------
// Rewritten in res-kernel style: weights via __ldg (no smem tile, no in-loop
// syncs), 16 tg x 8 outputs x 4 co per thread, 3 CTAs/SM. Tile 128 outputs.
__global__ void __launch_bounds__(256, 3) conv_s2_kernel(
    const float* __restrict__ x, const float* __restrict__ w,
    const float* __restrict__ bias, float* __restrict__ y, int Tout)
{
    extern __shared__ float smem[];
    float* xs = smem;                           // [258][65]
    const int Tin = Tout << 1;
    const int tid = threadIdx.x;
    const int tilesPerB = Tout >> 7;
    const int b = blockIdx.x / tilesPerB;
    const int t0 = (blockIdx.x - b * tilesPerB) << 7;
    const float* xb = x + (size_t)b * Tin * 64;

    for (int idx = tid; idx < 258 * 16; idx += 256) {
        int r = idx >> 4, c4 = idx & 15;
        int gt = 2 * t0 - 1 + r;
        float4 v = make_float4(0.f, 0.f, 0.f, 0.f);
        if (gt >= 0 && gt < Tin) v = *(const float4*)(xb + (size_t)gt * 64 + c4 * 4);
        float* d = &xs[r * 65 + c4 * 4];
        d[0] = v.x; d[1] = v.y; d[2] = v.z; d[3] = v.w;
    }
    __syncthreads();

    const int tg = tid >> 4;        // 16 groups of 8 outputs
    const int cg = tid & 15;        // 16 co groups of 4
    const int tb = tg << 3;
    const int co0 = cg << 2;

    float acc[8][4];
    #pragma unroll
    for (int i = 0; i < 8; i++)
        #pragma unroll
        for (int j = 0; j < 4; j++) acc[i][j] = 0.f;

    const float4* wp = (const float4*)(w + co0);   // taps at +0,+1024,+2048,+3072
    const float* xrow = &xs[(16 * tg) * 65];       // local input row base (row 16tg .. 16tg+17)

    #pragma unroll 2
    for (int ci = 0; ci < 64; ci++) {
        float xw[18];
        #pragma unroll
        for (int m = 0; m < 18; m++) xw[m] = xrow[m * 65 + ci];

        float4 w0 = __ldg(wp);
        float4 w1 = __ldg(wp + 1024);
        float4 w2 = __ldg(wp + 2048);
        float4 w3 = __ldg(wp + 3072);
        #pragma unroll
        for (int i = 0; i < 8; i++) {
            // output t = t0+tb+i reads local rows 2i+k (k=0..3)
            float x0 = xw[2 * i + 0];
            acc[i][0] += x0 * w0.x; acc[i][1] += x0 * w0.y;
            acc[i][2] += x0 * w0.z; acc[i][3] += x0 * w0.w;
            float x1 = xw[2 * i + 1];
            acc[i][0] += x1 * w1.x; acc[i][1] += x1 * w1.y;
            acc[i][2] += x1 * w1.z; acc[i][3] += x1 * w1.w;
            float x2 = xw[2 * i + 2];
            acc[i][0] += x2 * w2.x; acc[i][1] += x2 * w2.y;
            acc[i][2] += x2 * w2.z; acc[i][3] += x2 * w2.w;
            float x3 = xw[2 * i + 3];
            acc[i][0] += x3 * w3.x; acc[i][1] += x3 * w3.y;
            acc[i][2] += x3 * w3.z; acc[i][3] += x3 * w3.w;
        }
        wp += 16;
    }

    float4 bv = *(const float4*)(bias + co0);
    #pragma unroll
    for (int i = 0; i < 8; i++) {
        int gt = t0 + tb + i;
        float* op = y + ((size_t)b * Tout + gt) * 64 + co0;
        float4 o;
        o.x = fmaxf(acc[i][0] + bv.x, 0.f);
        o.y = fmaxf(acc[i][1] + bv.y, 0.f);
        o.z = fmaxf(acc[i][2] + bv.z, 0.f);
        o.w = fmaxf(acc[i][3] + bv.w, 0.f);
        *(float4*)op = o;
    }
}

// ---------------- fused transposed conv + projection (Tout=65536) -----------
#define XT_S 68
#define HS_S 68

__global__ void __launch_bounds__(256, 3) conv_tr_proj_kernel(
    const float* __restrict__ x, const float* __restrict__ w,
    const float* __restrict__ bias,
    const float* __restrict__ wproj, const float* __restrict__ bproj,
    float* __restrict__ out, int Tout)
{
    extern __shared__ float smem[];
    float* xsT = smem;                          // [64][XT_S]
    float* hs  = smem + 64 * XT_S;              // [130][HS_S]
    float* wps = smem + 64 * XT_S + 130 * HS_S; // [192]

    const int Tin = Tout >> 1;
    const int tid = threadIdx.x;
    const int tilesPerB = Tout >> 7;
    const int b = blockIdx.x / tilesPerB;
    const int t0 = (blockIdx.x - b * tilesPerB) << 7;
    const float* xb = x + (size_t)b * Tin * 64;
    const int in0 = (t0 >> 1) - 1;

    for (int idx = tid; idx < 64 * 17; idx += 256) {
        int ci = idx & 63;
        int rb = (idx >> 6) << 2;
        int gt = in0 + rb;
        float4 v;
        v.x = (gt + 0 >= 0 && gt + 0 < Tin) ? xb[(size_t)(gt + 0) * 64 + ci] : 0.f;
        v.y = (gt + 1 >= 0 && gt + 1 < Tin) ? xb[(size_t)(gt + 1) * 64 + ci] : 0.f;
        v.z = (gt + 2 >= 0 && gt + 2 < Tin) ? xb[(size_t)(gt + 2) * 64 + ci] : 0.f;
        v.w = (gt + 3 >= 0 && gt + 3 < Tin) ? xb[(size_t)(gt + 3) * 64 + ci] : 0.f;
        *(float4*)&xsT[ci * XT_S + rb] = v;
    }
    if (tid < 192) wps[tid] = wproj[tid];
    __syncthreads();

    const int tg = tid >> 4;
    const int cg = tid & 15;
    const int tb = tg << 3;
    const int ib = tg << 2;
    const int co0 = cg << 2;

    float acc[8][4];
    #pragma unroll
    for (int i = 0; i < 8; i++)
        #pragma unroll
        for (int j = 0; j < 4; j++) acc[i][j] = 0.f;
    float accE[4] = {0.f, 0.f, 0.f, 0.f};

    const float4* wp = (const float4*)(w + co0);
    const float* xrp = &xsT[ib];

    #pragma unroll 2
    for (int ci = 0; ci < 64; ci++) {
        const float4* xr = (const float4*)xrp;
        float4 c0 = xr[0];
        float4 c1 = xr[1];
        float xw[8];
        xw[0] = c0.x; xw[1] = c0.y; xw[2] = c0.z; xw[3] = c0.w;
        xw[4] = c1.x; xw[5] = c1.y; xw[6] = c1.z; xw[7] = c1.w;

        float4 w0 = __ldg(wp);
        float4 w1 = __ldg(wp + 1024);
        float4 w2 = __ldg(wp + 2048);
        float4 w3 = __ldg(wp + 3072);
        #pragma unroll
        for (int ii = 0; ii < 4; ii++) {
            const int e = 2 * ii, o = 2 * ii + 1;
            float xe0 = xw[ii], xe1 = xw[ii + 1];
            acc[e][0] += xe0 * w0.x + xe1 * w2.x;
            acc[e][1] += xe0 * w0.y + xe1 * w2.y;
            acc[e][2] += xe0 * w0.z + xe1 * w2.z;
            acc[e][3] += xe0 * w0.w + xe1 * w2.w;
            float xo0 = xw[ii + 1], xo1 = xw[ii + 2];
            acc[o][0] += xo0 * w1.x + xo1 * w3.x;
            acc[o][1] += xo0 * w1.y + xo1 * w3.y;
            acc[o][2] += xo0 * w1.z + xo1 * w3.z;
            acc[o][3] += xo0 * w1.w + xo1 * w3.w;
        }
        if (tg == 0) {
            accE[0] += xw[0] * w1.x + xw[1] * w3.x;
            accE[1] += xw[0] * w1.y + xw[1] * w3.y;
            accE[2] += xw[0] * w1.z + xw[1] * w3.z;
            accE[3] += xw[0] * w1.w + xw[1] * w3.w;
        } else if (tg == 15) {
            accE[0] += xw[4] * w0.x + xw[5] * w2.x;
            accE[1] += xw[4] * w0.y + xw[5] * w2.y;
            accE[2] += xw[4] * w0.z + xw[5] * w2.z;
            accE[3] += xw[4] * w0.w + xw[5] * w2.w;
        }
        wp += 16;
        xrp += XT_S;
    }

    float4 bv = *(const float4*)(bias + co0);
    #pragma unroll
    for (int i = 0; i < 8; i++) {
        float4 o;
        o.x = fmaxf(acc[i][0] + bv.x, 0.f);
        o.y = fmaxf(acc[i][1] + bv.y, 0.f);
        o.z = fmaxf(acc[i][2] + bv.z, 0.f);
        o.w = fmaxf(acc[i][3] + bv.w, 0.f);
        *(float4*)&hs[(tb + 1 + i) * HS_S + co0] = o;
    }
    if (tg == 0) {
        float4 o = make_float4(0.f, 0.f, 0.f, 0.f);
        if (t0 > 0) {
            o.x = fmaxf(accE[0] + bv.x, 0.f);
            o.y = fmaxf(accE[1] + bv.y, 0.f);
            o.z = fmaxf(accE[2] + bv.z, 0.f);
            o.w = fmaxf(accE[3] + bv.w, 0.f);
        }
        *(float4*)&hs[0 * HS_S + co0] = o;
    } else if (tg == 15) {
        float4 o = make_float4(0.f, 0.f, 0.f, 0.f);
        if (t0 + 128 < Tout) {
            o.x = fmaxf(accE[0] + bv.x, 0.f);
            o.y = fmaxf(accE[1] + bv.y, 0.f);
            o.z = fmaxf(accE[2] + bv.z, 0.f);
            o.w = fmaxf(accE[3] + bv.w, 0.f);
        }
        *(float4*)&hs[129 * HS_S + co0] = o;
    }
    __syncthreads();

    if (tid < 128) {
        float a = __ldg(bproj);
        #pragma unroll
        for (int k = 0; k < 3; k++) {
            const float* hrow = &hs[(tid + k) * HS_S];
            const float* wrow = &wps[k * 64];
            #pragma unroll 8
            for (int ci = 0; ci < 64; ci++)
                a += hrow[ci] * wrow[ci];
        }
        out[OFF_XHAT + (size_t)b * Tout + t0 + tid] = a;
    }
}

// ---------------- transposed conv (Tout<=32768) ------------------------------
__global__ void __launch_bounds__(256, 2) conv_tr_kernel(
    const float* __restrict__ x, const float* __restrict__ w,
    const float* __restrict__ bias, float* __restrict__ y, int Tout)
{
    extern __shared__ float smem[];
    float* xs = smem;                           // [130][65]
    float* wsm = smem + ALIGN4(130 * 65);       // [4][64][64]
    const int Tin = Tout >> 1;
    const int tid = threadIdx.x;
    const int tilesPerB = Tout >> 8;
    const int b = blockIdx.x / tilesPerB;
    const int t0 = (blockIdx.x - b * tilesPerB) << 8;
    const float* xb = x + (size_t)b * Tin * 64;
    const int in0 = (t0 >> 1) - 1;

    for (int idx = tid; idx < 130 * 16; idx += 256) {
        int r = idx >> 4, c4 = idx & 15;
        int gt = in0 + r;
        float4 v = make_float4(0.f, 0.f, 0.f, 0.f);
        if (gt >= 0 && gt < Tin) v = *(const float4*)(xb + (size_t)gt * 64 + c4 * 4);
        float* d = &xs[r * 65 + c4 * 4];
        d[0] = v.x; d[1] = v.y; d[2] = v.z; d[3] = v.w;
    }
    {
        const float4* wg = (const float4*)w;
        float4* wd = (float4*)wsm;
        for (int idx = tid; idx < 4096; idx += 256) wd[idx] = wg[idx];
    }
    __syncthreads();

    const int tg = tid >> 3;
    const int cg = tid & 7;
    float acc[8][8];
    #pragma unroll
    for (int i = 0; i < 8; i++)
        #pragma unroll
        for (int j = 0; j < 8; j++) acc[i][j] = 0.f;

    const float4* ws4 = (const float4*)wsm;
    #pragma unroll 2
    for (int ci = 0; ci < 64; ci++) {
        float xv[6];
        #pragma unroll
        for (int m = 0; m < 6; m++) xv[m] = xs[(tg * 4 + m) * 65 + ci];
        {
            float4 wa0 = ws4[ci * 16 + cg * 2];
            float4 wb0 = ws4[ci * 16 + cg * 2 + 1];
            float4 wa2 = ws4[2 * 1024 + ci * 16 + cg * 2];
            float4 wb2 = ws4[2 * 1024 + ci * 16 + cg * 2 + 1];
            #pragma unroll
            for (int ii = 0; ii < 4; ii++) {
                const int i = 2 * ii;
                float xa = xv[ii], xbv = xv[ii + 1];
                acc[i][0] += xa * wa0.x + xbv * wa2.x;
                acc[i][1] += xa * wa0.y + xbv * wa2.y;
                acc[i][2] += xa * wa0.z + xbv * wa2.z;
                acc[i][3] += xa * wa0.w + xbv * wa2.w;
                acc[i][4] += xa * wb0.x + xbv * wb2.x;
                acc[i][5] += xa * wb0.y + xbv * wb2.y;
                acc[i][6] += xa * wb0.z + xbv * wb2.z;
                acc[i][7] += xa * wb0.w + xbv * wb2.w;
            }
        }
        {
            float4 wa1 = ws4[1024 + ci * 16 + cg * 2];
            float4 wb1 = ws4[1024 + ci * 16 + cg * 2 + 1];
            float4 wa3 = ws4[3 * 1024 + ci * 16 + cg * 2];
            float4 wb3 = ws4[3 * 1024 + ci * 16 + cg * 2 + 1];
            #pragma unroll
            for (int ii = 0; ii < 4; ii++) {
                const int i = 2 * ii + 1;
                float xa = xv[ii + 1], xbv = xv[ii + 2];
                acc[i][0] += xa * wa1.x + xbv * wa3.x;
                acc[i][1] += xa * wa1.y + xbv * wa3.y;
                acc[i][2] += xa * wa1.z + xbv * wa3.z;
                acc[i][3] += xa * wa1.w + xbv * wa3.w;
                acc[i][4] += xa * wb1.x + xbv * wb3.x;
                acc[i][5] += xa * wb1.y + xbv * wb3.y;
                acc[i][6] += xa * wb1.z + xbv * wb3.z;
                acc[i][7] += xa * wb1.w + xbv * wb3.w;
            }
        }
    }

    const int co0 = cg * 8;
    float4 bv0 = *(const float4*)(bias + co0);
    float4 bv1 = *(const float4*)(bias + co0 + 4);
    #pragma unroll
    for (int i = 0; i < 8; i++) {
        int gt = t0 + tg * 8 + i;
        float* op = y + ((size_t)b * Tout + gt) * 64 + co0;
        float4 o0, o1;
        o0.x = fmaxf(acc[i][0] + bv0.x, 0.f);
        o0.y = fmaxf(acc[i][1] + bv0.y, 0.f);
        o0.z = fmaxf(acc[i][2] + bv0.z, 0.f);
        o0.w = fmaxf(acc[i][3] + bv0.w, 0.f);
        o1.x = fmaxf(acc[i][4] + bv1.x, 0.f);
        o1.y = fmaxf(acc[i][5] + bv1.y, 0.f);
        o1.z = fmaxf(acc[i][6] + bv1.z, 0.f);
        o1.w = fmaxf(acc[i][7] + bv1.w, 0.f);
        *(float4*)op = o0;
        *(float4*)(op + 4) = o1;
    }
}

// ---------------- VQ ----------------
__global__ void __launch_bounds__(256) vq_kernel(
    const float* __restrict__ ze, const float* __restrict__ cb,
    float* __restrict__ zq, float* __restrict__ dout)
{
    __shared__ float zs[32 * 65];
    __shared__ float cbs[128 * 65];
    __shared__ float nzs[32], rsnzs[32];
    __shared__ float occ_pad[992];   // occupancy cap: total smem > 45.6KB -> 4 CTAs/SM

    const int tid = threadIdx.x;
    const int rg = tid >> 5;
    const int eg = tid & 31;
    const int row0 = blockIdx.x * 32;

    // opaque never-true write keeps the pad allocated (dout is 4-byte aligned)
    if ((((uintptr_t)dout) & 1) != 0) occ_pad[0] = 1.f;

    for (int idx = tid; idx < 32 * 16; idx += 256) {
        int r = idx >> 4, c4 = idx & 15;
        float4 v = *(const float4*)(ze + (size_t)(row0 + r) * 64 + c4 * 4);
        float* d = &zs[r * 65 + c4 * 4];
        d[0] = v.x; d[1] = v.y; d[2] = v.z; d[3] = v.w;
    }
    __syncthreads();
    if (tid < 32) {
        float s = 0.f;
        #pragma unroll 8
        for (int ci = 0; ci < 64; ci++) { float v = zs[tid * 65 + ci]; s += v * v; }
        nzs[tid] = s;
        rsnzs[tid] = rsqrtf(s);
    }

    float bv[4] = {3.4e38f, 3.4e38f, 3.4e38f, 3.4e38f};
    int bi[4] = {0, 0, 0, 0};

    for (int c = 0; c < 4; c++) {
        __syncthreads();
        for (int idx = tid; idx < 128 * 16; idx += 256) {
            int e = idx >> 4, c4 = idx & 15;
            float4 v = *(const float4*)(cb + (size_t)(c * 128 + e) * 64 + c4 * 4);
            float* d = &cbs[e * 65 + c4 * 4];
            d[0] = v.x; d[1] = v.y; d[2] = v.z; d[3] = v.w;
        }
        __syncthreads();

        float acc[4][4];
        #pragma unroll
        for (int i = 0; i < 4; i++)
            #pragma unroll
            for (int j = 0; j < 4; j++) acc[i][j] = 0.f;

        #pragma unroll 4
        for (int ci = 0; ci < 64; ci++) {
            float zv[4], cv[4];
            #pragma unroll
            for (int i = 0; i < 4; i++) zv[i] = zs[(rg * 4 + i) * 65 + ci];
            #pragma unroll
            for (int j = 0; j < 4; j++) cv[j] = cbs[(j * 32 + eg) * 65 + ci];
            #pragma unroll
            for (int i = 0; i < 4; i++)
                #pragma unroll
                for (int j = 0; j < 4; j++) acc[i][j] += zv[i] * cv[j];
        }

        #pragma unroll
        for (int j = 0; j < 4; j++) {
            int e = c * 128 + j * 32 + eg;
            float nev = __ldg(&g_ne[e]);
            float rse = __ldg(&g_rsne[e]);
            #pragma unroll
            for (int i = 0; i < 4; i++) {
                int r = rg * 4 + i;
                float dot = acc[i][j];
                float dist = -2.0f * dot + nzs[r] + nev;
                float sim = dot * rsnzs[r] * rse;
                dout[OFF_SIM + (size_t)(row0 + r) * NEMB + e] = sim;
                if (dist < bv[i]) { bv[i] = dist; bi[i] = e; }
            }
        }
    }

    #pragma unroll
    for (int i = 0; i < 4; i++) {
        float v = bv[i];
        int idx = bi[i];
        #pragma unroll
        for (int off = 16; off > 0; off >>= 1) {
            float ov = __shfl_down_sync(0xffffffffu, v, off);
            int oi = __shfl_down_sync(0xffffffffu, idx, off);
            if (ov < v || (ov == v && oi < idx)) { v = ov; idx = oi; }
        }
        if (eg == 0) {
            int r = rg * 4 + i;
            int gr = row0 + r;
            dout[OFF_IDS + gr] = (float)idx;
            float s = 0.f;
            const float* cp = cb + (size_t)idx * 64;
            float* qp = zq + (size_t)gr * 64;
            #pragma unroll 8
            for (int ci = 0; ci < 64; ci++) {
                float cvv = __ldg(cp + ci);
                qp[ci] = cvv;
                float d = zs[r * 65 + ci] - cvv;
                s += d * d;
            }
            atomicAdd(&g_loss, sqrtf(s));
        }
    }
}

// ---------------- host orchestration ----------------
#define SMEM_RES128 (64 * XS128 * 4)
#define SMEM_RES64  (64 * XS64 * 4)
#define SMEM_TRPJ   ((64 * XT_S + 130 * HS_S + 192) * 4)
#define SMEM_S2     (258 * 65 * 4)
#define SMEM_TR     ((ALIGN4(130 * 65) + 16384) * 4)

static inline void launch_res_pair(bool enc, int T,
    const float* w1, const float* b1, const float* w2, const float* b2,
    float* h, float* t)
{
    if (T >= 32768) {
        const int grid = NBATCH * (T >> 7);
        if (enc) {
            conv_res128_kernel<3, false><<<grid, 256, SMEM_RES128>>>(h, w1, b1, nullptr, t, T);
            conv_res128_kernel<1, true ><<<grid, 256, SMEM_RES128>>>(t, w2, b2, h, h, T);
        } else {
            conv_res128_kernel<1, false><<<grid, 256, SMEM_RES128>>>(h, w1, b1, nullptr, t, T);
            conv_res128_kernel<3, true ><<<grid, 256, SMEM_RES128>>>(t, w2, b2, h, h, T);
        }
    } else {
        const int grid = NBATCH * (T >> 6);
        if (enc) {
            conv_res64_kernel<3, false><<<grid, 256, SMEM_RES64>>>(h, w1, b1, nullptr, t, T);
            conv_res64_kernel<1, true ><<<grid, 256, SMEM_RES64>>>(t, w2, b2, h, h, T);
        } else {
            conv_res64_kernel<1, false><<<grid, 256, SMEM_RES64>>>(h, w1, b1, nullptr, t, T);
            conv_res64_kernel<3, true ><<<grid, 256, SMEM_RES64>>>(t, w2, b2, h, h, T);
        }
    }
}

extern "C" void kernel_launch(void* const* d_in, const int* in_sizes, int n_in,
                              void* d_out, int out_size)
{
    const float* x        = (const float*)d_in[0];
    const float* w_down0  = (const float*)d_in[1];
    const float* b_down0  = (const float*)d_in[2];
    const float* w_down   = (const float*)d_in[3];
    const float* b_down   = (const float*)d_in[4];
    const float* w_res_e  = (const float*)d_in[5];
    const float* b_res_e  = (const float*)d_in[6];
    const float* codebook = (const float*)d_in[7];
    const float* w_res_d  = (const float*)d_in[8];
    const float* b_res_d  = (const float*)d_in[9];
    const float* w_up     = (const float*)d_in[10];
    const float* b_up     = (const float*)d_in[11];
    const float* w_proj   = (const float*)d_in[12];
    const float* b_proj   = (const float*)d_in[13];
    float* out = (float*)d_out;

    float *A, *Bb;
    cudaGetSymbolAddress((void**)&A, g_A);
    cudaGetSymbolAddress((void**)&Bb, g_B);

    cudaFuncSetAttribute(conv_res128_kernel<3, false>, cudaFuncAttributeMaxDynamicSharedMemorySize, SMEM_RES128);
    cudaFuncSetAttribute(conv_res128_kernel<3, true >, cudaFuncAttributeMaxDynamicSharedMemorySize, SMEM_RES128);
    cudaFuncSetAttribute(conv_res128_kernel<1, false>, cudaFuncAttributeMaxDynamicSharedMemorySize, SMEM_RES128);
    cudaFuncSetAttribute(conv_res128_kernel<1, true >, cudaFuncAttributeMaxDynamicSharedMemorySize, SMEM_RES128);
    cudaFuncSetAttribute(conv_res64_kernel<3, false>, cudaFuncAttributeMaxDynamicSharedMemorySize, SMEM_RES64);
    cudaFuncSetAttribute(conv_res64_kernel<3, true >, cudaFuncAttributeMaxDynamicSharedMemorySize, SMEM_RES64);
    cudaFuncSetAttribute(conv_res64_kernel<1, false>, cudaFuncAttributeMaxDynamicSharedMemorySize, SMEM_RES64);
    cudaFuncSetAttribute(conv_res64_kernel<1, true >, cudaFuncAttributeMaxDynamicSharedMemorySize, SMEM_RES64);
    cudaFuncSetAttribute(conv_tr_proj_kernel, cudaFuncAttributeMaxDynamicSharedMemorySize, SMEM_TRPJ);
    cudaFuncSetAttribute(conv_s2_kernel, cudaFuncAttributeMaxDynamicSharedMemorySize, SMEM_S2);
    cudaFuncSetAttribute(conv_tr_kernel, cudaFuncAttributeMaxDynamicSharedMemorySize, SMEM_TR);

    ne_kernel<<<2, 256>>>(codebook);

    float* h = A;
    float* t = Bb;

    // ---------- encoder ----------
    down0_kernel<<<2048, 256>>>(x, w_down0, b_down0, h);
    int T = 32768;
    for (int blk = 0; blk < 3; blk++) {
        if (blk > 0) {
            int Tout = T >> 1;
            conv_s2_kernel<<<NBATCH * (Tout >> 7), 256, SMEM_S2>>>(
                h, w_down + (size_t)(blk - 1) * 16384, b_down + (blk - 1) * 64, t, Tout);
            T = Tout;
            float* tmp = h; h = t; t = tmp;
        }
        for (int r = 0; r < 4; r++) {
            const float* w1 = w_res_e + (size_t)((blk * 4 + r) * 2 + 0) * 12288;
            const float* w2 = w_res_e + (size_t)((blk * 4 + r) * 2 + 1) * 12288;
            const float* bb1 = b_res_e + ((blk * 4 + r) * 2 + 0) * 64;
            const float* bb2 = b_res_e + ((blk * 4 + r) * 2 + 1) * 64;
            launch_res_pair(true, T, w1, bb1, w2, bb2, h, t);
        }
    }

    // ---------- VQ (T = 8192) ----------
    vq_kernel<<<1024, 256>>>(h, codebook, t, out);
    loss_fin_kernel<<<1, 1>>>(out);
    { float* tmp = h; h = t; t = tmp; }   // h = z_q

    // ---------- decoder ----------
    for (int blk = 0; blk < 3; blk++) {
        for (int r = 0; r < 4; r++) {
            const float* w1 = w_res_d + (size_t)((blk * 4 + r) * 2 + 0) * 12288;
            const float* w2 = w_res_d + (size_t)((blk * 4 + r) * 2 + 1) * 12288;
            const float* bb1 = b_res_d + ((blk * 4 + r) * 2 + 0) * 64;
            const float* bb2 = b_res_d + ((blk * 4 + r) * 2 + 1) * 64;
            launch_res_pair(false, T, w1, bb1, w2, bb2, h, t);
        }
        int Tout = T << 1;
        if (Tout >= 65536) {
            conv_tr_proj_kernel<<<NBATCH * (Tout >> 7), 256, SMEM_TRPJ>>>(
                h, w_up + (size_t)blk * 16384, b_up + blk * 64,
                w_proj, b_proj, out, Tout);
        } else {
            conv_tr_kernel<<<NBATCH * (Tout >> 8), 256, SMEM_TR>>>(
                h, w_up + (size_t)blk * 16384, b_up + blk * 64, t, Tout);
            float* tmp = h; h = t; t = tmp;
        }
        T = Tout;
    }
}

// round 17
// speedup vs baseline: 1.6120x; 1.0085x over previous
#include <cuda_runtime.h>
#include <math.h>
#include <stdint.h>

// ---------------- constants ----------------
#define NBATCH 4
#define TTOP   65536
#define OFF_XHAT 0
#define OFF_LOSS 262144
#define OFF_IDS  262145
#define OFF_SIM  294913
#define NEMB 512

#define ALIGN4(n) (((n) + 3) & ~3)

// ---------------- scratch ----------------
__device__ float g_A[16777216];
__device__ float g_B[16777216];
__device__ float g_ne[NEMB];
__device__ float g_rsne[NEMB];
__device__ float g_loss;

__global__ void ne_kernel(const float* __restrict__ cb) {
    if (blockIdx.x == 0 && threadIdx.x == 0) g_loss = 0.f;
    int e = blockIdx.x * blockDim.x + threadIdx.x;
    if (e < NEMB) {
        float s = 0.f;
        #pragma unroll 8
        for (int ci = 0; ci < 64; ci++) { float v = cb[e * 64 + ci]; s += v * v; }
        g_ne[e] = s;
        g_rsne[e] = rsqrtf(s);
    }
}

__global__ void loss_fin_kernel(float* __restrict__ out) {
    out[OFF_LOSS] = 1.25f * g_loss / 32768.0f;
}

// ---------------- first conv: Cin=1 -> 64, K=4, stride 2, ReLU ----------------
__global__ void __launch_bounds__(256) down0_kernel(
    const float* __restrict__ x, const float* __restrict__ w,
    const float* __restrict__ bias, float* __restrict__ y)
{
    __shared__ float ws[256];
    __shared__ float bs[64];
    int tid = threadIdx.x;
    ws[tid] = w[tid];
    if (tid < 64) bs[tid] = bias[tid];
    __syncthreads();

    int g = blockIdx.x * 256 + tid;
    int q = g & 3;
    int rest = g >> 2;
    int ot = rest & 32767;
    int b = rest >> 15;

    float acc[16];
    #pragma unroll
    for (int c = 0; c < 16; c++) acc[c] = bs[q * 16 + c];
    #pragma unroll
    for (int k = 0; k < 4; k++) {
        int t = 2 * ot - 1 + k;
        float xv = (t >= 0 && t < TTOP) ? x[(size_t)b * TTOP + t] : 0.f;
        #pragma unroll
        for (int c = 0; c < 16; c++) acc[c] += xv * ws[k * 64 + q * 16 + c];
    }
    float* op = y + ((size_t)(b * 32768 + ot)) * 64 + q * 16;
    #pragma unroll
    for (int c4 = 0; c4 < 4; c4++) {
        float4 o;
        o.x = fmaxf(acc[c4 * 4 + 0], 0.f);
        o.y = fmaxf(acc[c4 * 4 + 1], 0.f);
        o.z = fmaxf(acc[c4 * 4 + 2], 0.f);
        o.w = fmaxf(acc[c4 * 4 + 3], 0.f);
        *(float4*)(op + c4 * 4) = o;
    }
}

// ---------------- FUSED residual pair, 128-t tile (T = 32768) ----------------
// y = x + relu(conv_D2(relu(conv_D1(x)+b1))+b2). Two-phase: phase 1 computes
// the intermediate y1 (with 2*D2 halo rows via edge groups) into transposed
// smem; phase 2 is the proven window/FFMA loop over y1 + residual from global.
#define XF_S 140

template<int D1, int D2>
__global__ void __launch_bounds__(256, 3) conv_pair128_kernel(
    const float* __restrict__ x,
    const float* __restrict__ w1, const float* __restrict__ b1,
    const float* __restrict__ w2, const float* __restrict__ b2,
    float* __restrict__ y, int T)
{
    constexpr int HALO = D1 + D2;          // 4
    constexpr int XROWS = 128 + 2 * HALO;  // 136
    constexpr int NQ = XROWS >> 2;         // 34
    constexpr int EXTRA = 2 * D2;          // halo rows of y1 beyond 128
    constexpr int W1 = 8 + 2 * D1;
    constexpr int NV1 = (W1 + 3) >> 2;
    constexpr int W2 = 8 + 2 * D2;
    constexpr int NV2 = (W2 + 3) >> 2;

    extern __shared__ float smem[];
    float* xsT = smem;              // [64][XF_S], col r <-> t = t0 - HALO + r
    float* ysT = smem + 64 * XF_S;  // [64][XF_S], col r <-> t = t0 - D2 + r

    const int tid = threadIdx.x;
    const int tilesPerB = T >> 7;
    const int b = blockIdx.x / tilesPerB;
    const int t0 = (blockIdx.x - b * tilesPerB) << 7;
    const float* xb = x + (size_t)b * T * 64;

    for (int idx = tid; idx < 64 * NQ; idx += 256) {
        int ci = idx & 63;
        int rb = (idx >> 6) << 2;
        int gt = t0 - HALO + rb;
        float4 v;
        v.x = (gt + 0 >= 0 && gt + 0 < T) ? xb[(size_t)(gt + 0) * 64 + ci] : 0.f;
        v.y = (gt + 1 >= 0 && gt + 1 < T) ? xb[(size_t)(gt + 1) * 64 + ci] : 0.f;
        v.z = (gt + 2 >= 0 && gt + 2 < T) ? xb[(size_t)(gt + 2) * 64 + ci] : 0.f;
        v.w = (gt + 3 >= 0 && gt + 3 < T) ? xb[(size_t)(gt + 3) * 64 + ci] : 0.f;
        *(float4*)&xsT[ci * XF_S + rb] = v;
    }
    __syncthreads();

    const int tg = tid >> 4;
    const int cg = tid & 15;
    const int tb = tg << 3;
    const int co0 = cg << 2;

    // ---- phase 1: y1 row r uses x cols r, r+D1, r+2*D1 ----
    float acc[8][4];
    #pragma unroll
    for (int i = 0; i < 8; i++)
        #pragma unroll
        for (int j = 0; j < 4; j++) acc[i][j] = 0.f;
    float accE[4] = {0.f, 0.f, 0.f, 0.f};   // edge groups: row 128+tg

    {
        const float4* wp = (const float4*)(w1 + co0);
        const float* xrp = &xsT[tb];
        const int eoff = 128 + tg - tb;      // extra row col offset rel. to xrp

        #pragma unroll 2
        for (int ci = 0; ci < 64; ci++) {
            const float4* xr = (const float4*)xrp;
            float xw[NV1 * 4];
            #pragma unroll
            for (int v = 0; v < NV1; v++) {
                float4 c = xr[v];
                xw[v * 4 + 0] = c.x; xw[v * 4 + 1] = c.y;
                xw[v * 4 + 2] = c.z; xw[v * 4 + 3] = c.w;
            }
            float4 wa0 = __ldg(wp);
            float4 wa1 = __ldg(wp + 1024);
            float4 wa2 = __ldg(wp + 2048);
            #pragma unroll
            for (int i = 0; i < 8; i++) {
                float x0 = xw[i];
                acc[i][0] += x0 * wa0.x; acc[i][1] += x0 * wa0.y;
                acc[i][2] += x0 * wa0.z; acc[i][3] += x0 * wa0.w;
                float x1 = xw[i + D1];
                acc[i][0] += x1 * wa1.x; acc[i][1] += x1 * wa1.y;
                acc[i][2] += x1 * wa1.z; acc[i][3] += x1 * wa1.w;
                float x2 = xw[i + 2 * D1];
                acc[i][0] += x2 * wa2.x; acc[i][1] += x2 * wa2.y;
                acc[i][2] += x2 * wa2.z; acc[i][3] += x2 * wa2.w;
            }
            if (tg < EXTRA) {
                float e0 = xrp[eoff];
                float e1 = xrp[eoff + D1];
                float e2 = xrp[eoff + 2 * D1];
                accE[0] += e0 * wa0.x + e1 * wa1.x + e2 * wa2.x;
                accE[1] += e0 * wa0.y + e1 * wa1.y + e2 * wa2.y;
                accE[2] += e0 * wa0.z + e1 * wa1.z + e2 * wa2.z;
                accE[3] += e0 * wa0.w + e1 * wa1.w + e2 * wa2.w;
            }
            wp += 16;
            xrp += XF_S;
        }
    }

    // write y1 (ReLU, zero outside [0,T)) transposed
    {
        float4 bv = *(const float4*)(b1 + co0);
        float bb[4] = {bv.x, bv.y, bv.z, bv.w};
        bool val[8];
        #pragma unroll
        for (int i = 0; i < 8; i++)
            val[i] = ((unsigned)(t0 - D2 + tb + i) < (unsigned)T);
        #pragma unroll
        for (int j = 0; j < 4; j++) {
            float4 lo, hi;
            lo.x = val[0] ? fmaxf(acc[0][j] + bb[j], 0.f) : 0.f;
            lo.y = val[1] ? fmaxf(acc[1][j] + bb[j], 0.f) : 0.f;
            lo.z = val[2] ? fmaxf(acc[2][j] + bb[j], 0.f) : 0.f;
            lo.w = val[3] ? fmaxf(acc[3][j] + bb[j], 0.f) : 0.f;
            hi.x = val[4] ? fmaxf(acc[4][j] + bb[j], 0.f) : 0.f;
            hi.y = val[5] ? fmaxf(acc[5][j] + bb[j], 0.f) : 0.f;
            hi.z = val[6] ? fmaxf(acc[6][j] + bb[j], 0.f) : 0.f;
            hi.w = val[7] ? fmaxf(acc[7][j] + bb[j], 0.f) : 0.f;
            *(float4*)&ysT[(co0 + j) * XF_S + tb] = lo;
            *(float4*)&ysT[(co0 + j) * XF_S + tb + 4] = hi;
        }
        if (tg < EXTRA) {
            int r = 128 + tg;
            bool ok = ((unsigned)(t0 - D2 + r) < (unsigned)T);
            #pragma unroll
            for (int j = 0; j < 4; j++)
                ysT[(co0 + j) * XF_S + r] = ok ? fmaxf(accE[j] + bb[j], 0.f) : 0.f;
        }
    }
    __syncthreads();

    // ---- phase 2: out t = t0+tb+i uses y1 cols (tb+i) + {0, D2, 2*D2} ----
    #pragma unroll
    for (int i = 0; i < 8; i++)
        #pragma unroll
        for (int j = 0; j < 4; j++) acc[i][j] = 0.f;

    {
        const float4* wp = (const float4*)(w2 + co0);
        const float* yrp = &ysT[tb];

        #pragma unroll 2
        for (int ci = 0; ci < 64; ci++) {
            const float4* yr = (const float4*)yrp;
            float yw[NV2 * 4];
            #pragma unroll
            for (int v = 0; v < NV2; v++) {
                float4 c = yr[v];
                yw[v * 4 + 0] = c.x; yw[v * 4 + 1] = c.y;
                yw[v * 4 + 2] = c.z; yw[v * 4 + 3] = c.w;
            }
            float4 wa0 = __ldg(wp);
            float4 wa1 = __ldg(wp + 1024);
            float4 wa2 = __ldg(wp + 2048);
            #pragma unroll
            for (int i = 0; i < 8; i++) {
                float x0 = yw[i];
                acc[i][0] += x0 * wa0.x; acc[i][1] += x0 * wa0.y;
                acc[i][2] += x0 * wa0.z; acc[i][3] += x0 * wa0.w;
                float x1 = yw[i + D2];
                acc[i][0] += x1 * wa1.x; acc[i][1] += x1 * wa1.y;
                acc[i][2] += x1 * wa1.z; acc[i][3] += x1 * wa1.w;
                float x2 = yw[i + 2 * D2];
                acc[i][0] += x2 * wa2.x; acc[i][1] += x2 * wa2.y;
                acc[i][2] += x2 * wa2.z; acc[i][3] += x2 * wa2.w;
            }
            wp += 16;
            yrp += XF_S;
        }
    }

    float4 bv = *(const float4*)(b2 + co0);
    #pragma unroll
    for (int i = 0; i < 8; i++) {
        int gt = t0 + tb + i;
        const float* rp = xb + (size_t)gt * 64 + co0;
        float4 r0 = *(const float4*)rp;
        float* op = y + ((size_t)b * T + gt) * 64 + co0;
        float4 o;
        o.x = r0.x + fmaxf(acc[i][0] + bv.x, 0.f);
        o.y = r0.y + fmaxf(acc[i][1] + bv.y, 0.f);
        o.z = r0.z + fmaxf(acc[i][2] + bv.z, 0.f);
        o.w = r0.w + fmaxf(acc[i][3] + bv.w, 0.f);
        *(float4*)op = o;
    }
}

// ---------------- residual conv, 64-t tile (proven, T<=16384) ----------------
#define XS64 76

template<int DIL, bool RES>
__global__ void __launch_bounds__(256, 4) conv_res64_kernel(
    const float* __restrict__ x, const float* __restrict__ w,
    const float* __restrict__ bias, const float* __restrict__ res,
    float* __restrict__ y, int T)
{
    constexpr int ROWS = 64 + 2 * DIL;
    constexpr int NQ = (ROWS + 3) >> 2;
    constexpr int W = 4 + 2 * DIL;
    constexpr int NV = (W + 3) >> 2;

    extern __shared__ float smem[];
    float* xsT = smem;   // [64][XS64]

    const int tid = threadIdx.x;
    const int tilesPerB = T >> 6;
    const int b = blockIdx.x / tilesPerB;
    const int t0 = (blockIdx.x - b * tilesPerB) << 6;
    const float* xb = x + (size_t)b * T * 64;

    for (int idx = tid; idx < 64 * NQ; idx += 256) {
        int ci = idx & 63;
        int rb = (idx >> 6) << 2;
        int gt = t0 - DIL + rb;
        float4 v;
        v.x = (gt + 0 >= 0 && gt + 0 < T) ? xb[(size_t)(gt + 0) * 64 + ci] : 0.f;
        v.y = (gt + 1 >= 0 && gt + 1 < T) ? xb[(size_t)(gt + 1) * 64 + ci] : 0.f;
        v.z = (gt + 2 >= 0 && gt + 2 < T) ? xb[(size_t)(gt + 2) * 64 + ci] : 0.f;
        v.w = (gt + 3 >= 0 && gt + 3 < T) ? xb[(size_t)(gt + 3) * 64 + ci] : 0.f;
        *(float4*)&xsT[ci * XS64 + rb] = v;
    }
    __syncthreads();

    const int tg = tid >> 4;
    const int cg = tid & 15;
    const int tb = tg << 2;
    const int co0 = cg << 2;

    float acc[4][4];
    #pragma unroll
    for (int i = 0; i < 4; i++)
        #pragma unroll
        for (int j = 0; j < 4; j++) acc[i][j] = 0.f;

    const float4* wp = (const float4*)(w + co0);
    const float* xrp = &xsT[tb];

    #pragma unroll 2
    for (int ci = 0; ci < 64; ci++) {
        const float4* xr = (const float4*)xrp;
        float xw[NV * 4];
        #pragma unroll
        for (int v = 0; v < NV; v++) {
            float4 c = xr[v];
            xw[v * 4 + 0] = c.x; xw[v * 4 + 1] = c.y;
            xw[v * 4 + 2] = c.z; xw[v * 4 + 3] = c.w;
        }

        float4 wa0 = __ldg(wp);
        float4 wa1 = __ldg(wp + 1024);
        float4 wa2 = __ldg(wp + 2048);
        #pragma unroll
        for (int i = 0; i < 4; i++) {
            float x0 = xw[i];
            acc[i][0] += x0 * wa0.x; acc[i][1] += x0 * wa0.y;
            acc[i][2] += x0 * wa0.z; acc[i][3] += x0 * wa0.w;
            float x1 = xw[i + DIL];
            acc[i][0] += x1 * wa1.x; acc[i][1] += x1 * wa1.y;
            acc[i][2] += x1 * wa1.z; acc[i][3] += x1 * wa1.w;
            float x2 = xw[i + 2 * DIL];
            acc[i][0] += x2 * wa2.x; acc[i][1] += x2 * wa2.y;
            acc[i][2] += x2 * wa2.z; acc[i][3] += x2 * wa2.w;
        }
        wp += 16;
        xrp += XS64;
    }

    float4 bv = *(const float4*)(bias + co0);
    #pragma unroll
    for (int i = 0; i < 4; i++) {
        int gt = t0 + tb + i;
        float* op = y + ((size_t)b * T + gt) * 64 + co0;
        float4 o;
        o.x = fmaxf(acc[i][0] + bv.x, 0.f);
        o.y = fmaxf(acc[i][1] + bv.y, 0.f);
        o.z = fmaxf(acc[i][2] + bv.z, 0.f);
        o.w = fmaxf(acc[i][3] + bv.w, 0.f);
        if (RES) {
            float4 r0 = *(const float4*)(res + ((size_t)b * T + gt) * 64 + co0);
            o.x += r0.x; o.y += r0.y; o.z += r0.z; o.w += r0.w;
        }
        *(float4*)op = o;
    }
}

// ---------------- strided down conv: K=4, stride 2, 64->64, ReLU -------------
__global__ void __launch_bounds__(256, 3) conv_s2_kernel(
    const float* __restrict__ x, const float* __restrict__ w,
    const float* __restrict__ bias, float* __restrict__ y, int Tout)
{
    extern __shared__ float smem[];
    float* xs = smem;                           // [258][65]
    const int Tin = Tout << 1;
    const int tid = threadIdx.x;
    const int tilesPerB = Tout >> 7;
    const int b = blockIdx.x / tilesPerB;
    const int t0 = (blockIdx.x - b * tilesPerB) << 7;
    const float* xb = x + (size_t)b * Tin * 64;

    for (int idx = tid; idx < 258 * 16; idx += 256) {
        int r = idx >> 4, c4 = idx & 15;
        int gt = 2 * t0 - 1 + r;
        float4 v = make_float4(0.f, 0.f, 0.f, 0.f);
        if (gt >= 0 && gt < Tin) v = *(const float4*)(xb + (size_t)gt * 64 + c4 * 4);
        float* d = &xs[r * 65 + c4 * 4];
        d[0] = v.x; d[1] = v.y; d[2] = v.z; d[3] = v.w;
    }
    __syncthreads();

    const int tg = tid >> 4;
    const int cg = tid & 15;
    const int tb = tg << 3;
    const int co0 = cg << 2;

    float acc[8][4];
    #pragma unroll
    for (int i = 0; i < 8; i++)
        #pragma unroll
        for (int j = 0; j < 4; j++) acc[i][j] = 0.f;

    const float4* wp = (const float4*)(w + co0);
    const float* xrow = &xs[(16 * tg) * 65];

    #pragma unroll 2
    for (int ci = 0; ci < 64; ci++) {
        float xw[18];
        #pragma unroll
        for (int m = 0; m < 18; m++) xw[m] = xrow[m * 65 + ci];

        float4 w0 = __ldg(wp);
        float4 w1 = __ldg(wp + 1024);
        float4 w2 = __ldg(wp + 2048);
        float4 w3 = __ldg(wp + 3072);
        #pragma unroll
        for (int i = 0; i < 8; i++) {
            float x0 = xw[2 * i + 0];
            acc[i][0] += x0 * w0.x; acc[i][1] += x0 * w0.y;
            acc[i][2] += x0 * w0.z; acc[i][3] += x0 * w0.w;
            float x1 = xw[2 * i + 1];
            acc[i][0] += x1 * w1.x; acc[i][1] += x1 * w1.y;
            acc[i][2] += x1 * w1.z; acc[i][3] += x1 * w1.w;
            float x2 = xw[2 * i + 2];
            acc[i][0] += x2 * w2.x; acc[i][1] += x2 * w2.y;
            acc[i][2] += x2 * w2.z; acc[i][3] += x2 * w2.w;
            float x3 = xw[2 * i + 3];
            acc[i][0] += x3 * w3.x; acc[i][1] += x3 * w3.y;
            acc[i][2] += x3 * w3.z; acc[i][3] += x3 * w3.w;
        }
        wp += 16;
    }

    float4 bv = *(const float4*)(bias + co0);
    #pragma unroll
    for (int i = 0; i < 8; i++) {
        int gt = t0 + tb + i;
        float* op = y + ((size_t)b * Tout + gt) * 64 + co0;
        float4 o;
        o.x = fmaxf(acc[i][0] + bv.x, 0.f);
        o.y = fmaxf(acc[i][1] + bv.y, 0.f);
        o.z = fmaxf(acc[i][2] + bv.z, 0.f);
        o.w = fmaxf(acc[i][3] + bv.w, 0.f);
        *(float4*)op = o;
    }
}

// ---------------- fused transposed conv + projection (Tout=65536) -----------
#define XT_S 68
#define HS_S 68

__global__ void __launch_bounds__(256, 3) conv_tr_proj_kernel(
    const float* __restrict__ x, const float* __restrict__ w,
    const float* __restrict__ bias,
    const float* __restrict__ wproj, const float* __restrict__ bproj,
    float* __restrict__ out, int Tout)
{
    extern __shared__ float smem[];
    float* xsT = smem;                          // [64][XT_S]
    float* hs  = smem + 64 * XT_S;              // [130][HS_S]
    float* wps = smem + 64 * XT_S + 130 * HS_S; // [192]

    const int Tin = Tout >> 1;
    const int tid = threadIdx.x;
    const int tilesPerB = Tout >> 7;
    const int b = blockIdx.x / tilesPerB;
    const int t0 = (blockIdx.x - b * tilesPerB) << 7;
    const float* xb = x + (size_t)b * Tin * 64;
    const int in0 = (t0 >> 1) - 1;

    for (int idx = tid; idx < 64 * 17; idx += 256) {
        int ci = idx & 63;
        int rb = (idx >> 6) << 2;
        int gt = in0 + rb;
        float4 v;
        v.x = (gt + 0 >= 0 && gt + 0 < Tin) ? xb[(size_t)(gt + 0) * 64 + ci] : 0.f;
        v.y = (gt + 1 >= 0 && gt + 1 < Tin) ? xb[(size_t)(gt + 1) * 64 + ci] : 0.f;
        v.z = (gt + 2 >= 0 && gt + 2 < Tin) ? xb[(size_t)(gt + 2) * 64 + ci] : 0.f;
        v.w = (gt + 3 >= 0 && gt + 3 < Tin) ? xb[(size_t)(gt + 3) * 64 + ci] : 0.f;
        *(float4*)&xsT[ci * XT_S + rb] = v;
    }
    if (tid < 192) wps[tid] = wproj[tid];
    __syncthreads();

    const int tg = tid >> 4;
    const int cg = tid & 15;
    const int tb = tg << 3;
    const int ib = tg << 2;
    const int co0 = cg << 2;

    float acc[8][4];
    #pragma unroll
    for (int i = 0; i < 8; i++)
        #pragma unroll
        for (int j = 0; j < 4; j++) acc[i][j] = 0.f;
    float accE[4] = {0.f, 0.f, 0.f, 0.f};

    const float4* wp = (const float4*)(w + co0);
    const float* xrp = &xsT[ib];

    #pragma unroll 2
    for (int ci = 0; ci < 64; ci++) {
        const float4* xr = (const float4*)xrp;
        float4 c0 = xr[0];
        float4 c1 = xr[1];
        float xw[8];
        xw[0] = c0.x; xw[1] = c0.y; xw[2] = c0.z; xw[3] = c0.w;
        xw[4] = c1.x; xw[5] = c1.y; xw[6] = c1.z; xw[7] = c1.w;

        float4 w0 = __ldg(wp);
        float4 w1 = __ldg(wp + 1024);
        float4 w2 = __ldg(wp + 2048);
        float4 w3 = __ldg(wp + 3072);
        #pragma unroll
        for (int ii = 0; ii < 4; ii++) {
            const int e = 2 * ii, o = 2 * ii + 1;
            float xe0 = xw[ii], xe1 = xw[ii + 1];
            acc[e][0] += xe0 * w0.x + xe1 * w2.x;
            acc[e][1] += xe0 * w0.y + xe1 * w2.y;
            acc[e][2] += xe0 * w0.z + xe1 * w2.z;
            acc[e][3] += xe0 * w0.w + xe1 * w2.w;
            float xo0 = xw[ii + 1], xo1 = xw[ii + 2];
            acc[o][0] += xo0 * w1.x + xo1 * w3.x;
            acc[o][1] += xo0 * w1.y + xo1 * w3.y;
            acc[o][2] += xo0 * w1.z + xo1 * w3.z;
            acc[o][3] += xo0 * w1.w + xo1 * w3.w;
        }
        if (tg == 0) {
            accE[0] += xw[0] * w1.x + xw[1] * w3.x;
            accE[1] += xw[0] * w1.y + xw[1] * w3.y;
            accE[2] += xw[0] * w1.z + xw[1] * w3.z;
            accE[3] += xw[0] * w1.w + xw[1] * w3.w;
        } else if (tg == 15) {
            accE[0] += xw[4] * w0.x + xw[5] * w2.x;
            accE[1] += xw[4] * w0.y + xw[5] * w2.y;
            accE[2] += xw[4] * w0.z + xw[5] * w2.z;
            accE[3] += xw[4] * w0.w + xw[5] * w2.w;
        }
        wp += 16;
        xrp += XT_S;
    }

    float4 bv = *(const float4*)(bias + co0);
    #pragma unroll
    for (int i = 0; i < 8; i++) {
        float4 o;
        o.x = fmaxf(acc[i][0] + bv.x, 0.f);
        o.y = fmaxf(acc[i][1] + bv.y, 0.f);
        o.z = fmaxf(acc[i][2] + bv.z, 0.f);
        o.w = fmaxf(acc[i][3] + bv.w, 0.f);
        *(float4*)&hs[(tb + 1 + i) * HS_S + co0] = o;
    }
    if (tg == 0) {
        float4 o = make_float4(0.f, 0.f, 0.f, 0.f);
        if (t0 > 0) {
            o.x = fmaxf(accE[0] + bv.x, 0.f);
            o.y = fmaxf(accE[1] + bv.y, 0.f);
            o.z = fmaxf(accE[2] + bv.z, 0.f);
            o.w = fmaxf(accE[3] + bv.w, 0.f);
        }
        *(float4*)&hs[0 * HS_S + co0] = o;
    } else if (tg == 15) {
        float4 o = make_float4(0.f, 0.f, 0.f, 0.f);
        if (t0 + 128 < Tout) {
            o.x = fmaxf(accE[0] + bv.x, 0.f);
            o.y = fmaxf(accE[1] + bv.y, 0.f);
            o.z = fmaxf(accE[2] + bv.z, 0.f);
            o.w = fmaxf(accE[3] + bv.w, 0.f);
        }
        *(float4*)&hs[129 * HS_S + co0] = o;
    }
    __syncthreads();

    if (tid < 128) {
        float a = __ldg(bproj);
        #pragma unroll
        for (int k = 0; k < 3; k++) {
            const float* hrow = &hs[(tid + k) * HS_S];
            const float* wrow = &wps[k * 64];
            #pragma unroll 8
            for (int ci = 0; ci < 64; ci++)
                a += hrow[ci] * wrow[ci];
        }
        out[OFF_XHAT + (size_t)b * Tout + t0 + tid] = a;
    }
}

// ---------------- transposed conv (Tout<=32768) ------------------------------
__global__ void __launch_bounds__(256, 2) conv_tr_kernel(
    const float* __restrict__ x, const float* __restrict__ w,
    const float* __restrict__ bias, float* __restrict__ y, int Tout)
{
    extern __shared__ float smem[];
    float* xs = smem;                           // [130][65]
    float* wsm = smem + ALIGN4(130 * 65);       // [4][64][64]
    const int Tin = Tout >> 1;
    const int tid = threadIdx.x;
    const int tilesPerB = Tout >> 8;
    const int b = blockIdx.x / tilesPerB;
    const int t0 = (blockIdx.x - b * tilesPerB) << 8;
    const float* xb = x + (size_t)b * Tin * 64;
    const int in0 = (t0 >> 1) - 1;

    for (int idx = tid; idx < 130 * 16; idx += 256) {
        int r = idx >> 4, c4 = idx & 15;
        int gt = in0 + r;
        float4 v = make_float4(0.f, 0.f, 0.f, 0.f);
        if (gt >= 0 && gt < Tin) v = *(const float4*)(xb + (size_t)gt * 64 + c4 * 4);
        float* d = &xs[r * 65 + c4 * 4];
        d[0] = v.x; d[1] = v.y; d[2] = v.z; d[3] = v.w;
    }
    {
        const float4* wg = (const float4*)w;
        float4* wd = (float4*)wsm;
        for (int idx = tid; idx < 4096; idx += 256) wd[idx] = wg[idx];
    }
    __syncthreads();

    const int tg = tid >> 3;
    const int cg = tid & 7;
    float acc[8][8];
    #pragma unroll
    for (int i = 0; i < 8; i++)
        #pragma unroll
        for (int j = 0; j < 8; j++) acc[i][j] = 0.f;

    const float4* ws4 = (const float4*)wsm;
    #pragma unroll 2
    for (int ci = 0; ci < 64; ci++) {
        float xv[6];
        #pragma unroll
        for (int m = 0; m < 6; m++) xv[m] = xs[(tg * 4 + m) * 65 + ci];
        {
            float4 wa0 = ws4[ci * 16 + cg * 2];
            float4 wb0 = ws4[ci * 16 + cg * 2 + 1];
            float4 wa2 = ws4[2 * 1024 + ci * 16 + cg * 2];
            float4 wb2 = ws4[2 * 1024 + ci * 16 + cg * 2 + 1];
            #pragma unroll
            for (int ii = 0; ii < 4; ii++) {
                const int i = 2 * ii;
                float xa = xv[ii], xbv = xv[ii + 1];
                acc[i][0] += xa * wa0.x + xbv * wa2.x;
                acc[i][1] += xa * wa0.y + xbv * wa2.y;
                acc[i][2] += xa * wa0.z + xbv * wa2.z;
                acc[i][3] += xa * wa0.w + xbv * wa2.w;
                acc[i][4] += xa * wb0.x + xbv * wb2.x;
                acc[i][5] += xa * wb0.y + xbv * wb2.y;
                acc[i][6] += xa * wb0.z + xbv * wb2.z;
                acc[i][7] += xa * wb0.w + xbv * wb2.w;
            }
        }
        {
            float4 wa1 = ws4[1024 + ci * 16 + cg * 2];
            float4 wb1 = ws4[1024 + ci * 16 + cg * 2 + 1];
            float4 wa3 = ws4[3 * 1024 + ci * 16 + cg * 2];
            float4 wb3 = ws4[3 * 1024 + ci * 16 + cg * 2 + 1];
            #pragma unroll
            for (int ii = 0; ii < 4; ii++) {
                const int i = 2 * ii + 1;
                float xa = xv[ii + 1], xbv = xv[ii + 2];
                acc[i][0] += xa * wa1.x + xbv * wa3.x;
                acc[i][1] += xa * wa1.y + xbv * wa3.y;
                acc[i][2] += xa * wa1.z + xbv * wa3.z;
                acc[i][3] += xa * wa1.w + xbv * wa3.w;
                acc[i][4] += xa * wb1.x + xbv * wb3.x;
                acc[i][5] += xa * wb1.y + xbv * wb3.y;
                acc[i][6] += xa * wb1.z + xbv * wb3.z;
                acc[i][7] += xa * wb1.w + xbv * wb3.w;
            }
        }
    }

    const int co0 = cg * 8;
    float4 bv0 = *(const float4*)(bias + co0);
    float4 bv1 = *(const float4*)(bias + co0 + 4);
    #pragma unroll
    for (int i = 0; i < 8; i++) {
        int gt = t0 + tg * 8 + i;
        float* op = y + ((size_t)b * Tout + gt) * 64 + co0;
        float4 o0, o1;
        o0.x = fmaxf(acc[i][0] + bv0.x, 0.f);
        o0.y = fmaxf(acc[i][1] + bv0.y, 0.f);
        o0.z = fmaxf(acc[i][2] + bv0.z, 0.f);
        o0.w = fmaxf(acc[i][3] + bv0.w, 0.f);
        o1.x = fmaxf(acc[i][4] + bv1.x, 0.f);
        o1.y = fmaxf(acc[i][5] + bv1.y, 0.f);
        o1.z = fmaxf(acc[i][6] + bv1.z, 0.f);
        o1.w = fmaxf(acc[i][7] + bv1.w, 0.f);
        *(float4*)op = o0;
        *(float4*)(op + 4) = o1;
    }
}

// ---------------- VQ ----------------
__global__ void __launch_bounds__(256) vq_kernel(
    const float* __restrict__ ze, const float* __restrict__ cb,
    float* __restrict__ zq, float* __restrict__ dout)
{
    __shared__ float zs[32 * 65];
    __shared__ float cbs[128 * 65];
    __shared__ float nzs[32], rsnzs[32];
    __shared__ float occ_pad[992];   // occupancy cap -> 4 CTAs/SM

    const int tid = threadIdx.x;
    const int rg = tid >> 5;
    const int eg = tid & 31;
    const int row0 = blockIdx.x * 32;

    if ((((uintptr_t)dout) & 1) != 0) occ_pad[0] = 1.f;

    for (int idx = tid; idx < 32 * 16; idx += 256) {
        int r = idx >> 4, c4 = idx & 15;
        float4 v = *(const float4*)(ze + (size_t)(row0 + r) * 64 + c4 * 4);
        float* d = &zs[r * 65 + c4 * 4];
        d[0] = v.x; d[1] = v.y; d[2] = v.z; d[3] = v.w;
    }
    __syncthreads();
    if (tid < 32) {
        float s = 0.f;
        #pragma unroll 8
        for (int ci = 0; ci < 64; ci++) { float v = zs[tid * 65 + ci]; s += v * v; }
        nzs[tid] = s;
        rsnzs[tid] = rsqrtf(s);
    }

    float bv[4] = {3.4e38f, 3.4e38f, 3.4e38f, 3.4e38f};
    int bi[4] = {0, 0, 0, 0};

    for (int c = 0; c < 4; c++) {
        __syncthreads();
        for (int idx = tid; idx < 128 * 16; idx += 256) {
            int e = idx >> 4, c4 = idx & 15;
            float4 v = *(const float4*)(cb + (size_t)(c * 128 + e) * 64 + c4 * 4);
            float* d = &cbs[e * 65 + c4 * 4];
            d[0] = v.x; d[1] = v.y; d[2] = v.z; d[3] = v.w;
        }
        __syncthreads();

        float acc[4][4];
        #pragma unroll
        for (int i = 0; i < 4; i++)
            #pragma unroll
            for (int j = 0; j < 4; j++) acc[i][j] = 0.f;

        #pragma unroll 4
        for (int ci = 0; ci < 64; ci++) {
            float zv[4], cv[4];
            #pragma unroll
            for (int i = 0; i < 4; i++) zv[i] = zs[(rg * 4 + i) * 65 + ci];
            #pragma unroll
            for (int j = 0; j < 4; j++) cv[j] = cbs[(j * 32 + eg) * 65 + ci];
            #pragma unroll
            for (int i = 0; i < 4; i++)
                #pragma unroll
                for (int j = 0; j < 4; j++) acc[i][j] += zv[i] * cv[j];
        }

        #pragma unroll
        for (int j = 0; j < 4; j++) {
            int e = c * 128 + j * 32 + eg;
            float nev = __ldg(&g_ne[e]);
            float rse = __ldg(&g_rsne[e]);
            #pragma unroll
            for (int i = 0; i < 4; i++) {
                int r = rg * 4 + i;
                float dot = acc[i][j];
                float dist = -2.0f * dot + nzs[r] + nev;
                float sim = dot * rsnzs[r] * rse;
                dout[OFF_SIM + (size_t)(row0 + r) * NEMB + e] = sim;
                if (dist < bv[i]) { bv[i] = dist; bi[i] = e; }
            }
        }
    }

    #pragma unroll
    for (int i = 0; i < 4; i++) {
        float v = bv[i];
        int idx = bi[i];
        #pragma unroll
        for (int off = 16; off > 0; off >>= 1) {
            float ov = __shfl_down_sync(0xffffffffu, v, off);
            int oi = __shfl_down_sync(0xffffffffu, idx, off);
            if (ov < v || (ov == v && oi < idx)) { v = ov; idx = oi; }
        }
        if (eg == 0) {
            int r = rg * 4 + i;
            int gr = row0 + r;
            dout[OFF_IDS + gr] = (float)idx;
            float s = 0.f;
            const float* cp = cb + (size_t)idx * 64;
            float* qp = zq + (size_t)gr * 64;
            #pragma unroll 8
            for (int ci = 0; ci < 64; ci++) {
                float cvv = __ldg(cp + ci);
                qp[ci] = cvv;
                float d = zs[r * 65 + ci] - cvv;
                s += d * d;
            }
            atomicAdd(&g_loss, sqrtf(s));
        }
    }
}

// ---------------- host orchestration ----------------
#define SMEM_PAIR   (2 * 64 * XF_S * 4)
#define SMEM_RES64  (64 * XS64 * 4)
#define SMEM_TRPJ   ((64 * XT_S + 130 * HS_S + 192) * 4)
#define SMEM_S2     (258 * 65 * 4)
#define SMEM_TR     ((ALIGN4(130 * 65) + 16384) * 4)

extern "C" void kernel_launch(void* const* d_in, const int* in_sizes, int n_in,
                              void* d_out, int out_size)
{
    const float* x        = (const float*)d_in[0];
    const float* w_down0  = (const float*)d_in[1];
    const float* b_down0  = (const float*)d_in[2];
    const float* w_down   = (const float*)d_in[3];
    const float* b_down   = (const float*)d_in[4];
    const float* w_res_e  = (const float*)d_in[5];
    const float* b_res_e  = (const float*)d_in[6];
    const float* codebook = (const float*)d_in[7];
    const float* w_res_d  = (const float*)d_in[8];
    const float* b_res_d  = (const float*)d_in[9];
    const float* w_up     = (const float*)d_in[10];
    const float* b_up     = (const float*)d_in[11];
    const float* w_proj   = (const float*)d_in[12];
    const float* b_proj   = (const float*)d_in[13];
    float* out = (float*)d_out;

    float *A, *Bb;
    cudaGetSymbolAddress((void**)&A, g_A);
    cudaGetSymbolAddress((void**)&Bb, g_B);

    cudaFuncSetAttribute(conv_pair128_kernel<3, 1>, cudaFuncAttributeMaxDynamicSharedMemorySize, SMEM_PAIR);
    cudaFuncSetAttribute(conv_pair128_kernel<1, 3>, cudaFuncAttributeMaxDynamicSharedMemorySize, SMEM_PAIR);
    cudaFuncSetAttribute(conv_res64_kernel<3, false>, cudaFuncAttributeMaxDynamicSharedMemorySize, SMEM_RES64);
    cudaFuncSetAttribute(conv_res64_kernel<3, true >, cudaFuncAttributeMaxDynamicSharedMemorySize, SMEM_RES64);
    cudaFuncSetAttribute(conv_res64_kernel<1, false>, cudaFuncAttributeMaxDynamicSharedMemorySize, SMEM_RES64);
    cudaFuncSetAttribute(conv_res64_kernel<1, true >, cudaFuncAttributeMaxDynamicSharedMemorySize, SMEM_RES64);
    cudaFuncSetAttribute(conv_tr_proj_kernel, cudaFuncAttributeMaxDynamicSharedMemorySize, SMEM_TRPJ);
    cudaFuncSetAttribute(conv_s2_kernel, cudaFuncAttributeMaxDynamicSharedMemorySize, SMEM_S2);
    cudaFuncSetAttribute(conv_tr_kernel, cudaFuncAttributeMaxDynamicSharedMemorySize, SMEM_TR);

    ne_kernel<<<2, 256>>>(codebook);

    float* h = A;
    float* t = Bb;

    // ---------- encoder ----------
    down0_kernel<<<2048, 256>>>(x, w_down0, b_down0, h);
    int T = 32768;
    for (int blk = 0; blk < 3; blk++) {
        if (blk > 0) {
            int Tout = T >> 1;
            conv_s2_kernel<<<NBATCH * (Tout >> 7), 256, SMEM_S2>>>(
                h, w_down + (size_t)(blk - 1) * 16384, b_down + (blk - 1) * 64, t, Tout);
            T = Tout;
            float* tmp = h; h = t; t = tmp;
        }
        for (int r = 0; r < 4; r++) {
            const float* w1 = w_res_e + (size_t)((blk * 4 + r) * 2 + 0) * 12288;
            const float* w2 = w_res_e + (size_t)((blk * 4 + r) * 2 + 1) * 12288;
            const float* bb1 = b_res_e + ((blk * 4 + r) * 2 + 0) * 64;
            const float* bb2 = b_res_e + ((blk * 4 + r) * 2 + 1) * 64;
            if (T >= 32768) {
                conv_pair128_kernel<3, 1><<<NBATCH * (T >> 7), 256, SMEM_PAIR>>>(
                    h, w1, bb1, w2, bb2, t, T);
                float* tmp = h; h = t; t = tmp;
            } else {
                const int grid = NBATCH * (T >> 6);
                conv_res64_kernel<3, false><<<grid, 256, SMEM_RES64>>>(h, w1, bb1, nullptr, t, T);
                conv_res64_kernel<1, true ><<<grid, 256, SMEM_RES64>>>(t, w2, bb2, h, h, T);
            }
        }
    }

    // ---------- VQ (T = 8192) ----------
    vq_kernel<<<1024, 256>>>(h, codebook, t, out);
    loss_fin_kernel<<<1, 1>>>(out);
    { float* tmp = h; h = t; t = tmp; }   // h = z_q

    // ---------- decoder ----------
    for (int blk = 0; blk < 3; blk++) {
        for (int r = 0; r < 4; r++) {
            const float* w1 = w_res_d + (size_t)((blk * 4 + r) * 2 + 0) * 12288;
            const float* w2 = w_res_d + (size_t)((blk * 4 + r) * 2 + 1) * 12288;
            const float* bb1 = b_res_d + ((blk * 4 + r) * 2 + 0) * 64;
            const float* bb2 = b_res_d + ((blk * 4 + r) * 2 + 1) * 64;
            if (T >= 32768) {
                conv_pair128_kernel<1, 3><<<NBATCH * (T >> 7), 256, SMEM_PAIR>>>(
                    h, w1, bb1, w2, bb2, t, T);
                float* tmp = h; h = t; t = tmp;
            } else {
                const int grid = NBATCH * (T >> 6);
                conv_res64_kernel<1, false><<<grid, 256, SMEM_RES64>>>(h, w1, bb1, nullptr, t, T);
                conv_res64_kernel<3, true ><<<grid, 256, SMEM_RES64>>>(t, w2, bb2, h, h, T);
            }
        }
        int Tout = T << 1;
        if (Tout >= 65536) {
            conv_tr_proj_kernel<<<NBATCH * (Tout >> 7), 256, SMEM_TRPJ>>>(
                h, w_up + (size_t)blk * 16384, b_up + blk * 64,
                w_proj, b_proj, out, Tout);
        } else {
            conv_tr_kernel<<<NBATCH * (Tout >> 8), 256, SMEM_TR>>>(
                h, w_up + (size_t)blk * 16384, b_up + blk * 64, t, Tout);
            float* tmp = h; h = t; t = tmp;
        }
        T = Tout;
    }
}